// round 1
// baseline (speedup 1.0000x reference)
#include <cuda_runtime.h>
#include <math.h>

// ---------------------------------------------------------------------------
// CrossAttention: B=8, S1=S2=2048, D=512, single head, fp32.
//   q = h1@Wq^T+bq ; k = h2@Wk^T+bk ; v = h2@Wv^T+bv
//   RoPE(q), RoPE(k)
//   E = q k^T / sqrt(D) ; P = softmax(E) ; O = P v
//   out = O@Wo^T + bo
// ---------------------------------------------------------------------------

#define BATCH 8
#define SEQ   2048
#define DIM   512
#define MS    (BATCH * SEQ)   // 16384

// Scratch (device globals — allocation-free per harness rules)
__device__ float g_Q[(size_t)MS * DIM];
__device__ float g_K[(size_t)MS * DIM];
__device__ float g_V[(size_t)MS * DIM];
__device__ float g_O[(size_t)MS * DIM];
__device__ float g_E[(size_t)BATCH * SEQ * SEQ];

// ---------------------------------------------------------------------------
// Tiled SGEMM, 128x128x16 block tile, 256 threads, 8x8 per-thread micro-tile.
// NT variant: C[m,n] = alpha * sum_k A[m,k]*B[n,k]  (+ bias[n])
//   A: [M,K] row-major, B: [N,K] row-major (both K-contiguous).
// NN variant: C[m,n] = alpha * sum_k A[m,k]*B[k,n]  (+ bias[n])
// All dims assumed divisible by tile sizes (true for this problem).
// ---------------------------------------------------------------------------

#define BM 128
#define BN 128
#define BK 16
#define TM 8
#define TN 8

__global__ __launch_bounds__(256) void gemm_nt(
    const float* __restrict__ A, const float* __restrict__ Bm,
    const float* __restrict__ bias, float* __restrict__ C,
    int M, int N, int K,
    long long sA, long long sB, long long sC, float alpha)
{
    A  += (long long)blockIdx.z * sA;
    Bm += (long long)blockIdx.z * sB;
    C  += (long long)blockIdx.z * sC;

    __shared__ __align__(16) float As[BK][BM];
    __shared__ __align__(16) float Bs[BK][BN];

    const int t  = threadIdx.x;
    const int tx = t & 15;
    const int ty = t >> 4;
    const int m0 = blockIdx.y * BM;
    const int n0 = blockIdx.x * BN;
    const int lr = t >> 2;          // 0..63
    const int lc = (t & 3) << 2;    // 0,4,8,12

    float acc[TM][TN] = {};

    for (int k0 = 0; k0 < K; k0 += BK) {
        #pragma unroll
        for (int h = 0; h < 2; h++) {
            const int r = lr + h * 64;
            float4 a = *reinterpret_cast<const float4*>(A + (long long)(m0 + r) * K + k0 + lc);
            As[lc + 0][r] = a.x; As[lc + 1][r] = a.y;
            As[lc + 2][r] = a.z; As[lc + 3][r] = a.w;
            float4 b = *reinterpret_cast<const float4*>(Bm + (long long)(n0 + r) * K + k0 + lc);
            Bs[lc + 0][r] = b.x; Bs[lc + 1][r] = b.y;
            Bs[lc + 2][r] = b.z; Bs[lc + 3][r] = b.w;
        }
        __syncthreads();

        #pragma unroll
        for (int kk = 0; kk < BK; kk++) {
            float4 a0 = *reinterpret_cast<const float4*>(&As[kk][ty * TM]);
            float4 a1 = *reinterpret_cast<const float4*>(&As[kk][ty * TM + 4]);
            float4 b0 = *reinterpret_cast<const float4*>(&Bs[kk][tx * TN]);
            float4 b1 = *reinterpret_cast<const float4*>(&Bs[kk][tx * TN + 4]);
            float ra[8] = {a0.x, a0.y, a0.z, a0.w, a1.x, a1.y, a1.z, a1.w};
            float rb[8] = {b0.x, b0.y, b0.z, b0.w, b1.x, b1.y, b1.z, b1.w};
            #pragma unroll
            for (int i = 0; i < TM; i++)
                #pragma unroll
                for (int j = 0; j < TN; j++)
                    acc[i][j] = fmaf(ra[i], rb[j], acc[i][j]);
        }
        __syncthreads();
    }

    float bb[TN];
    #pragma unroll
    for (int j = 0; j < TN; j++) bb[j] = bias ? bias[n0 + tx * TN + j] : 0.0f;

    #pragma unroll
    for (int i = 0; i < TM; i++) {
        float* crow = C + (long long)(m0 + ty * TM + i) * N + n0 + tx * TN;
        float4 v0, v1;
        v0.x = acc[i][0] * alpha + bb[0];
        v0.y = acc[i][1] * alpha + bb[1];
        v0.z = acc[i][2] * alpha + bb[2];
        v0.w = acc[i][3] * alpha + bb[3];
        v1.x = acc[i][4] * alpha + bb[4];
        v1.y = acc[i][5] * alpha + bb[5];
        v1.z = acc[i][6] * alpha + bb[6];
        v1.w = acc[i][7] * alpha + bb[7];
        *reinterpret_cast<float4*>(crow)     = v0;
        *reinterpret_cast<float4*>(crow + 4) = v1;
    }
}

__global__ __launch_bounds__(256) void gemm_nn(
    const float* __restrict__ A, const float* __restrict__ Bm,
    float* __restrict__ C,
    int M, int N, int K,
    long long sA, long long sB, long long sC, float alpha)
{
    A  += (long long)blockIdx.z * sA;
    Bm += (long long)blockIdx.z * sB;
    C  += (long long)blockIdx.z * sC;

    __shared__ __align__(16) float As[BK][BM];
    __shared__ __align__(16) float Bs[BK][BN];

    const int t  = threadIdx.x;
    const int tx = t & 15;
    const int ty = t >> 4;
    const int m0 = blockIdx.y * BM;
    const int n0 = blockIdx.x * BN;
    const int lr = t >> 2;           // A-load: 0..63
    const int lc = (t & 3) << 2;
    const int br = t >> 5;           // B-load row: 0..7
    const int bc = (t & 31) << 2;    // B-load col: 0..124

    float acc[TM][TN] = {};

    for (int k0 = 0; k0 < K; k0 += BK) {
        #pragma unroll
        for (int h = 0; h < 2; h++) {
            const int r = lr + h * 64;
            float4 a = *reinterpret_cast<const float4*>(A + (long long)(m0 + r) * K + k0 + lc);
            As[lc + 0][r] = a.x; As[lc + 1][r] = a.y;
            As[lc + 2][r] = a.z; As[lc + 3][r] = a.w;
            const int kr = br + h * 8;
            float4 b = *reinterpret_cast<const float4*>(Bm + (long long)(k0 + kr) * N + n0 + bc);
            *reinterpret_cast<float4*>(&Bs[kr][bc]) = b;
        }
        __syncthreads();

        #pragma unroll
        for (int kk = 0; kk < BK; kk++) {
            float4 a0 = *reinterpret_cast<const float4*>(&As[kk][ty * TM]);
            float4 a1 = *reinterpret_cast<const float4*>(&As[kk][ty * TM + 4]);
            float4 b0 = *reinterpret_cast<const float4*>(&Bs[kk][tx * TN]);
            float4 b1 = *reinterpret_cast<const float4*>(&Bs[kk][tx * TN + 4]);
            float ra[8] = {a0.x, a0.y, a0.z, a0.w, a1.x, a1.y, a1.z, a1.w};
            float rb[8] = {b0.x, b0.y, b0.z, b0.w, b1.x, b1.y, b1.z, b1.w};
            #pragma unroll
            for (int i = 0; i < TM; i++)
                #pragma unroll
                for (int j = 0; j < TN; j++)
                    acc[i][j] = fmaf(ra[i], rb[j], acc[i][j]);
        }
        __syncthreads();
    }

    #pragma unroll
    for (int i = 0; i < TM; i++) {
        float* crow = C + (long long)(m0 + ty * TM + i) * N + n0 + tx * TN;
        float4 v0, v1;
        v0.x = acc[i][0] * alpha; v0.y = acc[i][1] * alpha;
        v0.z = acc[i][2] * alpha; v0.w = acc[i][3] * alpha;
        v1.x = acc[i][4] * alpha; v1.y = acc[i][5] * alpha;
        v1.z = acc[i][6] * alpha; v1.w = acc[i][7] * alpha;
        *reinterpret_cast<float4*>(crow)     = v0;
        *reinterpret_cast<float4*>(crow + 4) = v1;
    }
}

// ---------------------------------------------------------------------------
// RoPE (full hidden dim, single head). Pairs (j, j+256), angle = s * invfreq[j],
// invfreq[j] = 10000^(-j/256), all in fp32 to match the JAX reference.
// ---------------------------------------------------------------------------
__global__ void rope_kernel(float* __restrict__ x, int S)
{
    const int half = DIM / 2;
    long long idx = (long long)blockIdx.x * blockDim.x + threadIdx.x;
    long long total = (long long)BATCH * S * half;
    if (idx >= total) return;
    int j = (int)(idx % half);
    long long bs = idx / half;
    int s = (int)(bs % S);

    float invf = powf(10000.0f, -(float)j / (float)half);
    float ang = (float)s * invf;
    float c = cosf(ang), sn = sinf(ang);

    float* p = x + bs * DIM;
    float x1 = p[j];
    float x2 = p[j + half];
    p[j]        = x1 * c - x2 * sn;
    p[j + half] = x2 * c + x1 * sn;
}

// ---------------------------------------------------------------------------
// Row softmax, L = 2048, one block (256 threads) per row, in-place.
// ---------------------------------------------------------------------------
__global__ __launch_bounds__(256) void softmax2048(float* __restrict__ E)
{
    const int L = SEQ, T = 256, PER = L / T;  // 8
    float* p = E + (size_t)blockIdx.x * L;
    const int t = threadIdx.x;

    float v[PER];
    float m = -3.4e38f;
    #pragma unroll
    for (int i = 0; i < PER; i++) { v[i] = p[t + i * T]; m = fmaxf(m, v[i]); }

    #pragma unroll
    for (int o = 16; o; o >>= 1) m = fmaxf(m, __shfl_xor_sync(0xffffffffu, m, o));

    __shared__ float redm[8], reds[8];
    if ((t & 31) == 0) redm[t >> 5] = m;
    __syncthreads();
    float bm = redm[0];
    #pragma unroll
    for (int w = 1; w < 8; w++) bm = fmaxf(bm, redm[w]);

    float s = 0.0f;
    #pragma unroll
    for (int i = 0; i < PER; i++) { v[i] = expf(v[i] - bm); s += v[i]; }

    #pragma unroll
    for (int o = 16; o; o >>= 1) s += __shfl_xor_sync(0xffffffffu, s, o);
    if ((t & 31) == 0) reds[t >> 5] = s;
    __syncthreads();
    float bs = 0.0f;
    #pragma unroll
    for (int w = 0; w < 8; w++) bs += reds[w];

    float inv = 1.0f / bs;
    #pragma unroll
    for (int i = 0; i < PER; i++) p[t + i * T] = v[i] * inv;
}

// ---------------------------------------------------------------------------
// Launch
// ---------------------------------------------------------------------------
extern "C" void kernel_launch(void* const* d_in, const int* in_sizes, int n_in,
                              void* d_out, int out_size)
{
    const float* h1 = (const float*)d_in[0];
    const float* h2 = (const float*)d_in[1];
    const float* Wq = (const float*)d_in[2];
    const float* bq = (const float*)d_in[3];
    const float* Wk = (const float*)d_in[4];
    const float* bk = (const float*)d_in[5];
    const float* Wv = (const float*)d_in[6];
    const float* bv = (const float*)d_in[7];
    const float* Wo = (const float*)d_in[8];
    const float* bo = (const float*)d_in[9];
    float* out = (float*)d_out;

    float *Q, *K, *V, *E, *O;
    cudaGetSymbolAddress((void**)&Q, g_Q);
    cudaGetSymbolAddress((void**)&K, g_K);
    cudaGetSymbolAddress((void**)&V, g_V);
    cudaGetSymbolAddress((void**)&E, g_E);
    cudaGetSymbolAddress((void**)&O, g_O);

    const float scale = 0.044194173824159216f;  // 1/sqrt(512)

    // Projections (fold batch into M: [16384, 512] @ [512, 512]^T)
    dim3 gp(DIM / BN, MS / BM, 1);
    gemm_nt<<<gp, 256>>>(h1, Wq, bq, Q, MS, DIM, DIM, 0, 0, 0, 1.0f);
    gemm_nt<<<gp, 256>>>(h2, Wk, bk, K, MS, DIM, DIM, 0, 0, 0, 1.0f);
    gemm_nt<<<gp, 256>>>(h2, Wv, bv, V, MS, DIM, DIM, 0, 0, 0, 1.0f);

    // RoPE on Q and K
    {
        long long total = (long long)MS * (DIM / 2);
        int blocks = (int)((total + 255) / 256);
        rope_kernel<<<blocks, 256>>>(Q, SEQ);
        rope_kernel<<<blocks, 256>>>(K, SEQ);
    }

    // Scores: E[b] = scale * Q[b] K[b]^T   (batched NT)
    dim3 ge(SEQ / BN, SEQ / BM, BATCH);
    gemm_nt<<<ge, 256>>>(Q, K, nullptr, E, SEQ, SEQ, DIM,
                         (long long)SEQ * DIM, (long long)SEQ * DIM,
                         (long long)SEQ * SEQ, scale);

    // Softmax per row
    softmax2048<<<BATCH * SEQ, 256>>>(E);

    // O[b] = P[b] V[b]   (batched NN)
    dim3 gpv(DIM / BN, SEQ / BM, BATCH);
    gemm_nn<<<gpv, 256>>>(E, V, O, SEQ, DIM, SEQ,
                          (long long)SEQ * SEQ, (long long)SEQ * DIM,
                          (long long)SEQ * DIM, 1.0f);

    // Output projection
    gemm_nt<<<gp, 256>>>(O, Wo, bo, out, MS, DIM, DIM, 0, 0, 0, 1.0f);
}

// round 3
// speedup vs baseline: 1.5516x; 1.5516x over previous
#include <cuda_runtime.h>
#include <cuda_bf16.h>
#include <stdint.h>
#include <math.h>

// ===========================================================================
// CrossAttention B=8, S=2048, D=512 (single head, fp32 I/O).
// GEMMs on mma.sync (HMMA bf16, fp32 accum) with 3-pass error-compensated
// splitting: C = Ahi*Bhi + Ahi*Blo + Alo*Bhi.
// (tcgen05 rejected by ptxas: harness PTX target is plain sm_103.)
// ===========================================================================

#define BATCH 8
#define SEQ   2048
#define DIM   512
#define MS    (BATCH * SEQ)     // 16384
#define HALFD (DIM / 2)

#define BM 128
#define BN 128
#define BKE 64                         // bf16 elems per k-tile (128 bytes)
#define BKB 128                        // bytes per smem row
#define STAGES 3
#define TILE_BYTES (BM * BKB)          // 16384
#define STAGE_BYTES (2 * TILE_BYTES)   // 32768
#define SMEM_DYN (STAGES * STAGE_BYTES)// 98304

// --------------------------- device scratch -------------------------------
__device__ __align__(1024) __nv_bfloat16 g_h1s[(size_t)MS * 2 * DIM];
__device__ __align__(1024) __nv_bfloat16 g_h2s[(size_t)MS * 2 * DIM];
__device__ __align__(1024) __nv_bfloat16 g_Wqs[(size_t)DIM * 2 * DIM];
__device__ __align__(1024) __nv_bfloat16 g_Wks[(size_t)DIM * 2 * DIM];
__device__ __align__(1024) __nv_bfloat16 g_Wvs[(size_t)DIM * 2 * DIM];
__device__ __align__(1024) __nv_bfloat16 g_Wos[(size_t)DIM * 2 * DIM];
__device__ __align__(1024) __nv_bfloat16 g_Qs[(size_t)MS * 2 * DIM];
__device__ __align__(1024) __nv_bfloat16 g_Ks[(size_t)MS * 2 * DIM];
__device__ __align__(1024) __nv_bfloat16 g_Vts[(size_t)BATCH * DIM * 2 * SEQ];
__device__ __align__(1024) __nv_bfloat16 g_Es[(size_t)BATCH * SEQ * 2 * SEQ];
__device__ __align__(1024) __nv_bfloat16 g_Os[(size_t)MS * 2 * DIM];
__device__ __align__(1024) float g_E[(size_t)BATCH * SEQ * SEQ];
__device__ __align__(1024) float g_Fq[(size_t)MS * DIM];
__device__ __align__(1024) float g_Fk[(size_t)MS * DIM];
__device__ __align__(1024) float g_Fv[(size_t)MS * DIM];

// --------------------------- PTX helpers -----------------------------------
__device__ __forceinline__ uint32_t smem_u32(const void* p) {
    uint32_t a;
    asm("{ .reg .u64 t; cvta.to.shared.u64 t, %1; cvt.u32.u64 %0, t; }"
        : "=r"(a) : "l"(p));
    return a;
}
__device__ __forceinline__ void cp_async16(uint32_t dst, const void* src) {
    asm volatile("cp.async.cg.shared.global [%0], [%1], 16;" :: "r"(dst), "l"(src));
}
__device__ __forceinline__ void cp_commit() {
    asm volatile("cp.async.commit_group;" ::: "memory");
}
template <int N> __device__ __forceinline__ void cp_wait() {
    asm volatile("cp.async.wait_group %0;" :: "n"(N) : "memory");
}
__device__ __forceinline__ void ldsm4(uint32_t& r0, uint32_t& r1, uint32_t& r2,
                                      uint32_t& r3, uint32_t a) {
    asm volatile("ldmatrix.sync.aligned.m8n8.x4.shared.b16 {%0,%1,%2,%3}, [%4];"
                 : "=r"(r0), "=r"(r1), "=r"(r2), "=r"(r3) : "r"(a));
}
__device__ __forceinline__ void mma16816(float* d, const uint32_t* a,
                                         uint32_t b0, uint32_t b1) {
    asm volatile(
        "mma.sync.aligned.m16n8k16.row.col.f32.bf16.bf16.f32 "
        "{%0,%1,%2,%3}, {%4,%5,%6,%7}, {%8,%9}, {%0,%1,%2,%3};"
        : "+f"(d[0]), "+f"(d[1]), "+f"(d[2]), "+f"(d[3])
        : "r"(a[0]), "r"(a[1]), "r"(a[2]), "r"(a[3]), "r"(b0), "r"(b1));
}
__device__ __forceinline__ uint32_t sw128(uint32_t off) {
    return off ^ ((off >> 3) & 0x70);
}

// --------------------------- GEMM kernel -----------------------------------
// NT: C[m,n] = alpha * sum_passes A_part[m,k] * B_part[n,k]  (+ bias[n])
// A: [rowsA, 2*Kp] bf16 (cols [0,Kp)=hi, [Kp,2Kp)=lo), K-contiguous.
// B: [rowsB, 2*Kp] bf16 likewise.
__global__ __launch_bounds__(256) void gemm3(
    const __nv_bfloat16* __restrict__ A, const __nv_bfloat16* __restrict__ B,
    float* __restrict__ C, const float* __restrict__ bias,
    int Kp, int ldC, int aRowsPerB, int bRowsPerB, long long cPerB, float alpha)
{
    extern __shared__ __align__(1024) char smem[];
    const int tid  = threadIdx.x;
    const int wid  = tid >> 5;
    const int lane = tid & 31;
    const int wm   = wid & 3;     // 4 warps along M
    const int wn   = wid >> 2;    // 2 warps along N

    const long long lda = 2LL * Kp;
    A += (long long)blockIdx.z * aRowsPerB * lda + (long long)blockIdx.y * BM * lda;
    B += (long long)blockIdx.z * bRowsPerB * lda + (long long)blockIdx.x * BN * lda;

    const uint32_t smb = smem_u32(smem);
    const int cpp   = Kp / BKE;
    const int total = 3 * cpp;

    auto issue = [&](int it) {
        const int pass = it / cpp, kc = it % cpp;
        const long long ka = (long long)((pass == 2 ? Kp : 0) + kc * BKE);
        const long long kb = (long long)((pass == 1 ? Kp : 0) + kc * BKE);
        const uint32_t sb = smb + (it % STAGES) * STAGE_BYTES;
        #pragma unroll
        for (int i = 0; i < 4; i++) {
            const int id = tid * 4 + i;       // 0..1023
            const int r = id >> 3, c = id & 7;
            const uint32_t off = sw128((uint32_t)(r * BKB + c * 16));
            cp_async16(sb + off, A + (long long)r * lda + ka + c * 8);
            cp_async16(sb + TILE_BYTES + off, B + (long long)r * lda + kb + c * 8);
        }
        cp_commit();
    };

    float acc[2][8][4] = {};
    const int aRowBase = wm * 32;
    const int bRowBase = wn * 64;
    const int lrow = lane & 15;
    const int lkc  = lane >> 4;

    const int prol = (total < STAGES - 1) ? total : (STAGES - 1);
    for (int it = 0; it < prol; it++) issue(it);

    for (int it = 0; it < total; it++) {
        cp_wait<STAGES - 2>();
        __syncthreads();
        const uint32_t sa  = smb + (it % STAGES) * STAGE_BYTES;
        const uint32_t sbB = sa + TILE_BYTES;

        #pragma unroll
        for (int ks = 0; ks < 4; ks++) {
            uint32_t a[2][4], b[4][4];
            #pragma unroll
            for (int mi = 0; mi < 2; mi++) {
                const int row = aRowBase + mi * 16 + lrow;
                const uint32_t off = sw128((uint32_t)(row * BKB + ks * 32 + lkc * 16));
                ldsm4(a[mi][0], a[mi][1], a[mi][2], a[mi][3], sa + off);
            }
            #pragma unroll
            for (int nt = 0; nt < 4; nt++) {
                const int row = bRowBase + nt * 16 + lrow;
                const uint32_t off = sw128((uint32_t)(row * BKB + ks * 32 + lkc * 16));
                ldsm4(b[nt][0], b[nt][1], b[nt][2], b[nt][3], sbB + off);
            }
            #pragma unroll
            for (int mi = 0; mi < 2; mi++)
                #pragma unroll
                for (int nt = 0; nt < 4; nt++) {
                    mma16816(acc[mi][nt * 2],     a[mi], b[nt][0], b[nt][2]);
                    mma16816(acc[mi][nt * 2 + 1], a[mi], b[nt][1], b[nt][3]);
                }
        }
        __syncthreads();
        if (it + STAGES - 1 < total) issue(it + STAGES - 1);
    }

    // Epilogue
    C += (long long)blockIdx.z * cPerB;
    const int m0 = blockIdx.y * BM + wm * 32;
    const int n0 = blockIdx.x * BN + wn * 64;
    #pragma unroll
    for (int mi = 0; mi < 2; mi++) {
        const int r = m0 + mi * 16 + (lane >> 2);
        #pragma unroll
        for (int nj = 0; nj < 8; nj++) {
            const int cidx = n0 + nj * 8 + (lane & 3) * 2;
            float b0 = 0.f, b1 = 0.f;
            if (bias) { b0 = bias[cidx]; b1 = bias[cidx + 1]; }
            float2 v0, v1;
            v0.x = acc[mi][nj][0] * alpha + b0;
            v0.y = acc[mi][nj][1] * alpha + b1;
            v1.x = acc[mi][nj][2] * alpha + b0;
            v1.y = acc[mi][nj][3] * alpha + b1;
            *reinterpret_cast<float2*>(C + (long long)r * ldC + cidx) = v0;
            *reinterpret_cast<float2*>(C + (long long)(r + 8) * ldC + cidx) = v1;
        }
    }
}

// --------------------------- elementwise kernels ---------------------------
__global__ void split_kernel(const float* __restrict__ x, __nv_bfloat16* __restrict__ y,
                             int K, long long n)
{
    long long i = (long long)blockIdx.x * blockDim.x + threadIdx.x;
    if (i >= n) return;
    long long r = i / K; int c = (int)(i % K);
    float f = x[i];
    __nv_bfloat16 hi = __float2bfloat16(f);
    float lo = f - __bfloat162float(hi);
    y[r * (2LL * K) + c]     = hi;
    y[r * (2LL * K) + K + c] = __float2bfloat16(lo);
}

__global__ void rope_split_kernel(const float* __restrict__ x, __nv_bfloat16* __restrict__ y)
{
    long long idx = (long long)blockIdx.x * blockDim.x + threadIdx.x;
    long long tot = (long long)MS * HALFD;
    if (idx >= tot) return;
    int j = (int)(idx % HALFD);
    long long bs = idx / HALFD;
    int s = (int)(bs % SEQ);

    float invf = powf(10000.0f, -(float)j / (float)HALFD);
    float ang = (float)s * invf;
    float c = cosf(ang), sn = sinf(ang);

    const float* p = x + bs * DIM;
    float x1 = p[j], x2 = p[j + HALFD];
    float o1 = x1 * c - x2 * sn;
    float o2 = x2 * c + x1 * sn;

    __nv_bfloat16* q = y + bs * (2 * DIM);
    __nv_bfloat16 h1b = __float2bfloat16(o1);
    __nv_bfloat16 h2b = __float2bfloat16(o2);
    q[j]               = h1b;
    q[DIM + j]         = __float2bfloat16(o1 - __bfloat162float(h1b));
    q[j + HALFD]       = h2b;
    q[DIM + j + HALFD] = __float2bfloat16(o2 - __bfloat162float(h2b));
}

// V [B, S(k), D(n)] fp32 -> Vt [B*D rows, 2*S cols] split bf16 (transposed)
__global__ void transpose_split_kernel(const float* __restrict__ V, __nv_bfloat16* __restrict__ Vt)
{
    __shared__ float tile[32][33];
    const int b  = blockIdx.z;
    const int n0 = blockIdx.x * 32;
    const int k0 = blockIdx.y * 32;
    const int tx = threadIdx.x, ty = threadIdx.y;   // block (32, 8)
    const float* src = V + (size_t)b * SEQ * DIM;
    #pragma unroll
    for (int i = 0; i < 4; i++)
        tile[ty + 8 * i][tx] = src[(size_t)(k0 + ty + 8 * i) * DIM + n0 + tx];
    __syncthreads();
    __nv_bfloat16* dst = Vt + (size_t)b * DIM * (2 * SEQ);
    #pragma unroll
    for (int i = 0; i < 4; i++) {
        float f = tile[tx][ty + 8 * i];
        __nv_bfloat16 hi = __float2bfloat16(f);
        float lo = f - __bfloat162float(hi);
        size_t row = (size_t)(n0 + ty + 8 * i) * (2 * SEQ) + (k0 + tx);
        dst[row]       = hi;
        dst[row + SEQ] = __float2bfloat16(lo);
    }
}

__global__ __launch_bounds__(256) void softmax_split_kernel(const float* __restrict__ E,
                                                            __nv_bfloat16* __restrict__ Es)
{
    const int T = 256, PER = SEQ / T;    // 8
    const float* p = E + (size_t)blockIdx.x * SEQ;
    __nv_bfloat16* o = Es + (size_t)blockIdx.x * (2 * SEQ);
    const int t = threadIdx.x;

    float v[PER];
    float m = -3.4e38f;
    #pragma unroll
    for (int i = 0; i < PER; i++) { v[i] = p[t + i * T]; m = fmaxf(m, v[i]); }
    #pragma unroll
    for (int off = 16; off; off >>= 1) m = fmaxf(m, __shfl_xor_sync(0xffffffffu, m, off));

    __shared__ float redm[8], reds[8];
    if ((t & 31) == 0) redm[t >> 5] = m;
    __syncthreads();
    float bm = redm[0];
    #pragma unroll
    for (int w = 1; w < 8; w++) bm = fmaxf(bm, redm[w]);

    float s = 0.0f;
    #pragma unroll
    for (int i = 0; i < PER; i++) { v[i] = expf(v[i] - bm); s += v[i]; }
    #pragma unroll
    for (int off = 16; off; off >>= 1) s += __shfl_xor_sync(0xffffffffu, s, off);
    if ((t & 31) == 0) reds[t >> 5] = s;
    __syncthreads();
    float bs = 0.0f;
    #pragma unroll
    for (int w = 0; w < 8; w++) bs += reds[w];

    float inv = 1.0f / bs;
    #pragma unroll
    for (int i = 0; i < PER; i++) {
        float f = v[i] * inv;
        __nv_bfloat16 hi = __float2bfloat16(f);
        o[t + i * T]       = hi;
        o[SEQ + t + i * T] = __float2bfloat16(f - __bfloat162float(hi));
    }
}

// --------------------------- host side -------------------------------------
extern "C" void kernel_launch(void* const* d_in, const int* in_sizes, int n_in,
                              void* d_out, int out_size)
{
    const float* h1 = (const float*)d_in[0];
    const float* h2 = (const float*)d_in[1];
    const float* Wq = (const float*)d_in[2];
    const float* bq = (const float*)d_in[3];
    const float* Wk = (const float*)d_in[4];
    const float* bk = (const float*)d_in[5];
    const float* Wv = (const float*)d_in[6];
    const float* bv = (const float*)d_in[7];
    const float* Wo = (const float*)d_in[8];
    const float* bo = (const float*)d_in[9];
    float* out = (float*)d_out;

    void *h1s, *h2s, *Wqs, *Wks, *Wvs, *Wos, *Qs, *Ks, *Vts, *Es, *Os;
    float *E, *Fq, *Fk, *Fv;
    cudaGetSymbolAddress(&h1s, g_h1s);  cudaGetSymbolAddress(&h2s, g_h2s);
    cudaGetSymbolAddress(&Wqs, g_Wqs);  cudaGetSymbolAddress(&Wks, g_Wks);
    cudaGetSymbolAddress(&Wvs, g_Wvs);  cudaGetSymbolAddress(&Wos, g_Wos);
    cudaGetSymbolAddress(&Qs, g_Qs);    cudaGetSymbolAddress(&Ks, g_Ks);
    cudaGetSymbolAddress(&Vts, g_Vts);  cudaGetSymbolAddress(&Es, g_Es);
    cudaGetSymbolAddress(&Os, g_Os);
    cudaGetSymbolAddress((void**)&E, g_E);
    cudaGetSymbolAddress((void**)&Fq, g_Fq);
    cudaGetSymbolAddress((void**)&Fk, g_Fk);
    cudaGetSymbolAddress((void**)&Fv, g_Fv);

    cudaFuncSetAttribute(gemm3, cudaFuncAttributeMaxDynamicSharedMemorySize, SMEM_DYN);

    const float scale = 0.044194173824159216f;  // 1/sqrt(512)

    // 1. split inputs and weights to bf16 hi|lo
    {
        long long n = (long long)MS * DIM;
        int blk = (int)((n + 255) / 256);
        split_kernel<<<blk, 256>>>(h1, (__nv_bfloat16*)h1s, DIM, n);
        split_kernel<<<blk, 256>>>(h2, (__nv_bfloat16*)h2s, DIM, n);
        long long nw = (long long)DIM * DIM;
        int blkw = (int)((nw + 255) / 256);
        split_kernel<<<blkw, 256>>>(Wq, (__nv_bfloat16*)Wqs, DIM, nw);
        split_kernel<<<blkw, 256>>>(Wk, (__nv_bfloat16*)Wks, DIM, nw);
        split_kernel<<<blkw, 256>>>(Wv, (__nv_bfloat16*)Wvs, DIM, nw);
        split_kernel<<<blkw, 256>>>(Wo, (__nv_bfloat16*)Wos, DIM, nw);
    }

    // 2. projections
    dim3 gp(DIM / BN, MS / BM, 1);
    gemm3<<<gp, 256, SMEM_DYN>>>((const __nv_bfloat16*)h1s, (const __nv_bfloat16*)Wqs,
                                 Fq, bq, DIM, DIM, 0, 0, 0, 1.0f);
    gemm3<<<gp, 256, SMEM_DYN>>>((const __nv_bfloat16*)h2s, (const __nv_bfloat16*)Wks,
                                 Fk, bk, DIM, DIM, 0, 0, 0, 1.0f);
    gemm3<<<gp, 256, SMEM_DYN>>>((const __nv_bfloat16*)h2s, (const __nv_bfloat16*)Wvs,
                                 Fv, bv, DIM, DIM, 0, 0, 0, 1.0f);

    // 3. RoPE + split Q, K ; transpose + split V
    {
        long long tot = (long long)MS * HALFD;
        int blk = (int)((tot + 255) / 256);
        rope_split_kernel<<<blk, 256>>>(Fq, (__nv_bfloat16*)Qs);
        rope_split_kernel<<<blk, 256>>>(Fk, (__nv_bfloat16*)Ks);
        dim3 gt(DIM / 32, SEQ / 32, BATCH);
        transpose_split_kernel<<<gt, dim3(32, 8)>>>(Fv, (__nv_bfloat16*)Vts);
    }

    // 4. scores: E[b] = scale * Q[b] K[b]^T
    dim3 ge(SEQ / BN, SEQ / BM, BATCH);
    gemm3<<<ge, 256, SMEM_DYN>>>((const __nv_bfloat16*)Qs, (const __nv_bfloat16*)Ks,
                                 E, nullptr, DIM, SEQ, SEQ, SEQ,
                                 (long long)SEQ * SEQ, scale);

    // 5. softmax + split to bf16
    softmax_split_kernel<<<BATCH * SEQ, 256>>>(E, (__nv_bfloat16*)Es);

    // 6. O[b] = P[b] V[b]  (NT against transposed V)
    dim3 gpv(DIM / BN, SEQ / BM, BATCH);
    gemm3<<<gpv, 256, SMEM_DYN>>>((const __nv_bfloat16*)Es, (const __nv_bfloat16*)Vts,
                                  Fq, nullptr, SEQ, DIM, SEQ, DIM,
                                  (long long)SEQ * DIM, 1.0f);

    // 7. split O, output projection
    {
        long long n = (long long)MS * DIM;
        int blk = (int)((n + 255) / 256);
        split_kernel<<<blk, 256>>>(Fq, (__nv_bfloat16*)Os, DIM, n);
    }
    gemm3<<<gp, 256, SMEM_DYN>>>((const __nv_bfloat16*)Os, (const __nv_bfloat16*)Wos,
                                 out, bo, DIM, DIM, 0, 0, 0, 1.0f);
}

// round 4
// speedup vs baseline: 1.8475x; 1.1907x over previous
#include <cuda_runtime.h>
#include <cuda_bf16.h>
#include <stdint.h>
#include <math.h>

// ===========================================================================
// CrossAttention B=8, S=2048, D=512 (single head, fp32 I/O).
// GEMMs on mma.sync (HMMA bf16, fp32 accum), 3-term error-compensated split
// computed FUSED in a single k-loop:
//   C = Ahi*Bhi + Ahi*Blo + Alo*Bhi    (fragments loaded once, reused 2x)
// ===========================================================================

#define BATCH 8
#define SEQ   2048
#define DIM   512
#define MS    (BATCH * SEQ)     // 16384
#define HALFD (DIM / 2)

#define BM 128
#define BN 128
#define BKE 64                          // bf16 elems per k-chunk (128 bytes)
#define BKB 128                         // bytes per smem row
#define STAGES 3
#define TILE_BYTES (BM * BKB)           // 16384 (one 128x64 bf16 tile)
#define STAGE_BYTES (4 * TILE_BYTES)    // Ahi|Alo|Bhi|Blo = 65536
#define SMEM_DYN (STAGES * STAGE_BYTES) // 196608

// --------------------------- device scratch -------------------------------
__device__ __align__(1024) __nv_bfloat16 g_h1s[(size_t)MS * 2 * DIM];
__device__ __align__(1024) __nv_bfloat16 g_h2s[(size_t)MS * 2 * DIM];
__device__ __align__(1024) __nv_bfloat16 g_Wqs[(size_t)DIM * 2 * DIM];
__device__ __align__(1024) __nv_bfloat16 g_Wks[(size_t)DIM * 2 * DIM];
__device__ __align__(1024) __nv_bfloat16 g_Wvs[(size_t)DIM * 2 * DIM];
__device__ __align__(1024) __nv_bfloat16 g_Wos[(size_t)DIM * 2 * DIM];
__device__ __align__(1024) __nv_bfloat16 g_Qs[(size_t)MS * 2 * DIM];
__device__ __align__(1024) __nv_bfloat16 g_Ks[(size_t)MS * 2 * DIM];
__device__ __align__(1024) __nv_bfloat16 g_Vts[(size_t)BATCH * DIM * 2 * SEQ];
__device__ __align__(1024) __nv_bfloat16 g_Es[(size_t)BATCH * SEQ * 2 * SEQ];
__device__ __align__(1024) __nv_bfloat16 g_Os[(size_t)MS * 2 * DIM];
__device__ __align__(1024) float g_E[(size_t)BATCH * SEQ * SEQ];
__device__ __align__(1024) float g_Fq[(size_t)MS * DIM];
__device__ __align__(1024) float g_Fk[(size_t)MS * DIM];
__device__ __align__(1024) float g_Fv[(size_t)MS * DIM];

// --------------------------- PTX helpers -----------------------------------
__device__ __forceinline__ uint32_t smem_u32(const void* p) {
    uint32_t a;
    asm("{ .reg .u64 t; cvta.to.shared.u64 t, %1; cvt.u32.u64 %0, t; }"
        : "=r"(a) : "l"(p));
    return a;
}
__device__ __forceinline__ void cp_async16(uint32_t dst, const void* src) {
    asm volatile("cp.async.cg.shared.global [%0], [%1], 16;" :: "r"(dst), "l"(src));
}
__device__ __forceinline__ void cp_commit() {
    asm volatile("cp.async.commit_group;" ::: "memory");
}
template <int N> __device__ __forceinline__ void cp_wait() {
    asm volatile("cp.async.wait_group %0;" :: "n"(N) : "memory");
}
__device__ __forceinline__ void ldsm4(uint32_t& r0, uint32_t& r1, uint32_t& r2,
                                      uint32_t& r3, uint32_t a) {
    asm volatile("ldmatrix.sync.aligned.m8n8.x4.shared.b16 {%0,%1,%2,%3}, [%4];"
                 : "=r"(r0), "=r"(r1), "=r"(r2), "=r"(r3) : "r"(a));
}
__device__ __forceinline__ void mma16816(float* d, const uint32_t* a,
                                         uint32_t b0, uint32_t b1) {
    asm volatile(
        "mma.sync.aligned.m16n8k16.row.col.f32.bf16.bf16.f32 "
        "{%0,%1,%2,%3}, {%4,%5,%6,%7}, {%8,%9}, {%0,%1,%2,%3};"
        : "+f"(d[0]), "+f"(d[1]), "+f"(d[2]), "+f"(d[3])
        : "r"(a[0]), "r"(a[1]), "r"(a[2]), "r"(a[3]), "r"(b0), "r"(b1));
}
__device__ __forceinline__ uint32_t sw128(uint32_t off) {
    return off ^ ((off >> 3) & 0x70);
}

// --------------------------- GEMM kernel -----------------------------------
// NT: C[m,n] = alpha * (Ahi.Bhi + Ahi.Blo + Alo.Bhi)[m,n] + bias[n]
// A: [rowsA, 2*Kp] bf16 (cols [0,Kp)=hi, [Kp,2Kp)=lo), K-contiguous.
// B: [rowsB, 2*Kp] bf16 likewise.
__global__ __launch_bounds__(256) void gemm3(
    const __nv_bfloat16* __restrict__ A, const __nv_bfloat16* __restrict__ B,
    float* __restrict__ C, const float* __restrict__ bias,
    int Kp, int ldC, int aRowsPerB, int bRowsPerB, long long cPerB, float alpha)
{
    extern __shared__ __align__(1024) char smem[];
    const int tid  = threadIdx.x;
    const int wid  = tid >> 5;
    const int lane = tid & 31;
    const int wm   = wid & 3;     // 4 warps along M
    const int wn   = wid >> 2;    // 2 warps along N

    const long long lda = 2LL * Kp;
    A += (long long)blockIdx.z * aRowsPerB * lda + (long long)blockIdx.y * BM * lda;
    B += (long long)blockIdx.z * bRowsPerB * lda + (long long)blockIdx.x * BN * lda;

    const uint32_t smb = smem_u32(smem);
    const int chunks = Kp / BKE;

    // per-thread load geometry: 4 float4 per tile
    const int lr0 = (tid * 4) >> 3;       // row of first elem (2 rows per thread)
    const int lc0 = (tid * 4) & 7;        // col group 0..7 (16B units)

    auto issue = [&](int it) {
        const long long khi = (long long)it * BKE;
        const long long klo = (long long)Kp + it * BKE;
        const uint32_t sb = smb + (it % STAGES) * STAGE_BYTES;
        #pragma unroll
        for (int i = 0; i < 4; i++) {
            const int id = tid * 4 + i;
            const int r = id >> 3, c = id & 7;
            const uint32_t off = sw128((uint32_t)(r * BKB + c * 16));
            const long long arow = (long long)r * lda;
            cp_async16(sb + off,                  A + arow + khi + c * 8);
            cp_async16(sb + TILE_BYTES + off,     A + arow + klo + c * 8);
            cp_async16(sb + 2 * TILE_BYTES + off, B + arow + khi + c * 8);
            cp_async16(sb + 3 * TILE_BYTES + off, B + arow + klo + c * 8);
        }
        cp_commit();
    };

    float acc[2][8][4] = {};
    const int aRowBase = wm * 32;
    const int bRowBase = wn * 64;
    const int lrow = lane & 15;
    const int lkc  = lane >> 4;

    const int prol = (chunks < STAGES - 1) ? chunks : (STAGES - 1);
    for (int it = 0; it < prol; it++) issue(it);

    for (int it = 0; it < chunks; it++) {
        cp_wait<STAGES - 2>();
        __syncthreads();
        const uint32_t sAhi = smb + (it % STAGES) * STAGE_BYTES;
        const uint32_t sAlo = sAhi + TILE_BYTES;
        const uint32_t sBhi = sAhi + 2 * TILE_BYTES;
        const uint32_t sBlo = sAhi + 3 * TILE_BYTES;

        #pragma unroll
        for (int ks = 0; ks < 4; ks++) {
            uint32_t ahi[2][4], alo[2][4], bhi[4][4], blo[4][4];
            #pragma unroll
            for (int mi = 0; mi < 2; mi++) {
                const int row = aRowBase + mi * 16 + lrow;
                const uint32_t off = sw128((uint32_t)(row * BKB + ks * 32 + lkc * 16));
                ldsm4(ahi[mi][0], ahi[mi][1], ahi[mi][2], ahi[mi][3], sAhi + off);
                ldsm4(alo[mi][0], alo[mi][1], alo[mi][2], alo[mi][3], sAlo + off);
            }
            #pragma unroll
            for (int nt = 0; nt < 4; nt++) {
                const int row = bRowBase + nt * 16 + lrow;
                const uint32_t off = sw128((uint32_t)(row * BKB + ks * 32 + lkc * 16));
                ldsm4(bhi[nt][0], bhi[nt][1], bhi[nt][2], bhi[nt][3], sBhi + off);
                ldsm4(blo[nt][0], blo[nt][1], blo[nt][2], blo[nt][3], sBlo + off);
            }
            #pragma unroll
            for (int mi = 0; mi < 2; mi++)
                #pragma unroll
                for (int nt = 0; nt < 4; nt++) {
                    // hi*hi
                    mma16816(acc[mi][nt * 2],     ahi[mi], bhi[nt][0], bhi[nt][2]);
                    mma16816(acc[mi][nt * 2 + 1], ahi[mi], bhi[nt][1], bhi[nt][3]);
                    // hi*lo
                    mma16816(acc[mi][nt * 2],     ahi[mi], blo[nt][0], blo[nt][2]);
                    mma16816(acc[mi][nt * 2 + 1], ahi[mi], blo[nt][1], blo[nt][3]);
                    // lo*hi
                    mma16816(acc[mi][nt * 2],     alo[mi], bhi[nt][0], bhi[nt][2]);
                    mma16816(acc[mi][nt * 2 + 1], alo[mi], bhi[nt][1], bhi[nt][3]);
                }
        }
        __syncthreads();
        if (it + STAGES - 1 < chunks) issue(it + STAGES - 1);
    }

    // Epilogue
    C += (long long)blockIdx.z * cPerB;
    const int m0 = blockIdx.y * BM + wm * 32;
    const int n0 = blockIdx.x * BN + wn * 64;
    #pragma unroll
    for (int mi = 0; mi < 2; mi++) {
        const int r = m0 + mi * 16 + (lane >> 2);
        #pragma unroll
        for (int nj = 0; nj < 8; nj++) {
            const int cidx = n0 + nj * 8 + (lane & 3) * 2;
            float b0 = 0.f, b1 = 0.f;
            if (bias) { b0 = bias[cidx]; b1 = bias[cidx + 1]; }
            float2 v0, v1;
            v0.x = acc[mi][nj][0] * alpha + b0;
            v0.y = acc[mi][nj][1] * alpha + b1;
            v1.x = acc[mi][nj][2] * alpha + b0;
            v1.y = acc[mi][nj][3] * alpha + b1;
            *reinterpret_cast<float2*>(C + (long long)r * ldC + cidx) = v0;
            *reinterpret_cast<float2*>(C + (long long)(r + 8) * ldC + cidx) = v1;
        }
    }
}

// --------------------------- elementwise kernels ---------------------------
__global__ void split_kernel(const float* __restrict__ x, __nv_bfloat16* __restrict__ y,
                             int K, long long n)
{
    long long i = (long long)blockIdx.x * blockDim.x + threadIdx.x;
    if (i >= n) return;
    long long r = i / K; int c = (int)(i % K);
    float f = x[i];
    __nv_bfloat16 hi = __float2bfloat16(f);
    float lo = f - __bfloat162float(hi);
    y[r * (2LL * K) + c]     = hi;
    y[r * (2LL * K) + K + c] = __float2bfloat16(lo);
}

__global__ void rope_split_kernel(const float* __restrict__ x, __nv_bfloat16* __restrict__ y)
{
    long long idx = (long long)blockIdx.x * blockDim.x + threadIdx.x;
    long long tot = (long long)MS * HALFD;
    if (idx >= tot) return;
    int j = (int)(idx % HALFD);
    long long bs = idx / HALFD;
    int s = (int)(bs % SEQ);

    float invf = powf(10000.0f, -(float)j / (float)HALFD);
    float ang = (float)s * invf;
    float c = cosf(ang), sn = sinf(ang);

    const float* p = x + bs * DIM;
    float x1 = p[j], x2 = p[j + HALFD];
    float o1 = x1 * c - x2 * sn;
    float o2 = x2 * c + x1 * sn;

    __nv_bfloat16* q = y + bs * (2 * DIM);
    __nv_bfloat16 h1b = __float2bfloat16(o1);
    __nv_bfloat16 h2b = __float2bfloat16(o2);
    q[j]               = h1b;
    q[DIM + j]         = __float2bfloat16(o1 - __bfloat162float(h1b));
    q[j + HALFD]       = h2b;
    q[DIM + j + HALFD] = __float2bfloat16(o2 - __bfloat162float(h2b));
}

// V [B, S(k), D(n)] fp32 -> Vt [B*D rows, 2*S cols] split bf16 (transposed)
__global__ void transpose_split_kernel(const float* __restrict__ V, __nv_bfloat16* __restrict__ Vt)
{
    __shared__ float tile[32][33];
    const int b  = blockIdx.z;
    const int n0 = blockIdx.x * 32;
    const int k0 = blockIdx.y * 32;
    const int tx = threadIdx.x, ty = threadIdx.y;   // block (32, 8)
    const float* src = V + (size_t)b * SEQ * DIM;
    #pragma unroll
    for (int i = 0; i < 4; i++)
        tile[ty + 8 * i][tx] = src[(size_t)(k0 + ty + 8 * i) * DIM + n0 + tx];
    __syncthreads();
    __nv_bfloat16* dst = Vt + (size_t)b * DIM * (2 * SEQ);
    #pragma unroll
    for (int i = 0; i < 4; i++) {
        float f = tile[tx][ty + 8 * i];
        __nv_bfloat16 hi = __float2bfloat16(f);
        float lo = f - __bfloat162float(hi);
        size_t row = (size_t)(n0 + ty + 8 * i) * (2 * SEQ) + (k0 + tx);
        dst[row]       = hi;
        dst[row + SEQ] = __float2bfloat16(lo);
    }
}

__global__ __launch_bounds__(256) void softmax_split_kernel(const float* __restrict__ E,
                                                            __nv_bfloat16* __restrict__ Es)
{
    const int T = 256, PER = SEQ / T;    // 8
    const float* p = E + (size_t)blockIdx.x * SEQ;
    __nv_bfloat16* o = Es + (size_t)blockIdx.x * (2 * SEQ);
    const int t = threadIdx.x;

    float v[PER];
    float m = -3.4e38f;
    #pragma unroll
    for (int i = 0; i < PER; i++) { v[i] = p[t + i * T]; m = fmaxf(m, v[i]); }
    #pragma unroll
    for (int off = 16; off; off >>= 1) m = fmaxf(m, __shfl_xor_sync(0xffffffffu, m, off));

    __shared__ float redm[8], reds[8];
    if ((t & 31) == 0) redm[t >> 5] = m;
    __syncthreads();
    float bm = redm[0];
    #pragma unroll
    for (int w = 1; w < 8; w++) bm = fmaxf(bm, redm[w]);

    float s = 0.0f;
    #pragma unroll
    for (int i = 0; i < PER; i++) { v[i] = expf(v[i] - bm); s += v[i]; }
    #pragma unroll
    for (int off = 16; off; off >>= 1) s += __shfl_xor_sync(0xffffffffu, s, off);
    if ((t & 31) == 0) reds[t >> 5] = s;
    __syncthreads();
    float bs = 0.0f;
    #pragma unroll
    for (int w = 0; w < 8; w++) bs += reds[w];

    float inv = 1.0f / bs;
    #pragma unroll
    for (int i = 0; i < PER; i++) {
        float f = v[i] * inv;
        __nv_bfloat16 hi = __float2bfloat16(f);
        o[t + i * T]       = hi;
        o[SEQ + t + i * T] = __float2bfloat16(f - __bfloat162float(hi));
    }
}

// --------------------------- host side -------------------------------------
extern "C" void kernel_launch(void* const* d_in, const int* in_sizes, int n_in,
                              void* d_out, int out_size)
{
    const float* h1 = (const float*)d_in[0];
    const float* h2 = (const float*)d_in[1];
    const float* Wq = (const float*)d_in[2];
    const float* bq = (const float*)d_in[3];
    const float* Wk = (const float*)d_in[4];
    const float* bk = (const float*)d_in[5];
    const float* Wv = (const float*)d_in[6];
    const float* bv = (const float*)d_in[7];
    const float* Wo = (const float*)d_in[8];
    const float* bo = (const float*)d_in[9];
    float* out = (float*)d_out;

    void *h1s, *h2s, *Wqs, *Wks, *Wvs, *Wos, *Qs, *Ks, *Vts, *Es, *Os;
    float *E, *Fq, *Fk, *Fv;
    cudaGetSymbolAddress(&h1s, g_h1s);  cudaGetSymbolAddress(&h2s, g_h2s);
    cudaGetSymbolAddress(&Wqs, g_Wqs);  cudaGetSymbolAddress(&Wks, g_Wks);
    cudaGetSymbolAddress(&Wvs, g_Wvs);  cudaGetSymbolAddress(&Wos, g_Wos);
    cudaGetSymbolAddress(&Qs, g_Qs);    cudaGetSymbolAddress(&Ks, g_Ks);
    cudaGetSymbolAddress(&Vts, g_Vts);  cudaGetSymbolAddress(&Es, g_Es);
    cudaGetSymbolAddress(&Os, g_Os);
    cudaGetSymbolAddress((void**)&E, g_E);
    cudaGetSymbolAddress((void**)&Fq, g_Fq);
    cudaGetSymbolAddress((void**)&Fk, g_Fk);
    cudaGetSymbolAddress((void**)&Fv, g_Fv);

    cudaFuncSetAttribute(gemm3, cudaFuncAttributeMaxDynamicSharedMemorySize, SMEM_DYN);

    const float scale = 0.044194173824159216f;  // 1/sqrt(512)

    // 1. split inputs and weights to bf16 hi|lo
    {
        long long n = (long long)MS * DIM;
        int blk = (int)((n + 255) / 256);
        split_kernel<<<blk, 256>>>(h1, (__nv_bfloat16*)h1s, DIM, n);
        split_kernel<<<blk, 256>>>(h2, (__nv_bfloat16*)h2s, DIM, n);
        long long nw = (long long)DIM * DIM;
        int blkw = (int)((nw + 255) / 256);
        split_kernel<<<blkw, 256>>>(Wq, (__nv_bfloat16*)Wqs, DIM, nw);
        split_kernel<<<blkw, 256>>>(Wk, (__nv_bfloat16*)Wks, DIM, nw);
        split_kernel<<<blkw, 256>>>(Wv, (__nv_bfloat16*)Wvs, DIM, nw);
        split_kernel<<<blkw, 256>>>(Wo, (__nv_bfloat16*)Wos, DIM, nw);
    }

    // 2. projections
    dim3 gp(DIM / BN, MS / BM, 1);
    gemm3<<<gp, 256, SMEM_DYN>>>((const __nv_bfloat16*)h1s, (const __nv_bfloat16*)Wqs,
                                 Fq, bq, DIM, DIM, 0, 0, 0, 1.0f);
    gemm3<<<gp, 256, SMEM_DYN>>>((const __nv_bfloat16*)h2s, (const __nv_bfloat16*)Wks,
                                 Fk, bk, DIM, DIM, 0, 0, 0, 1.0f);
    gemm3<<<gp, 256, SMEM_DYN>>>((const __nv_bfloat16*)h2s, (const __nv_bfloat16*)Wvs,
                                 Fv, bv, DIM, DIM, 0, 0, 0, 1.0f);

    // 3. RoPE + split Q, K ; transpose + split V
    {
        long long tot = (long long)MS * HALFD;
        int blk = (int)((tot + 255) / 256);
        rope_split_kernel<<<blk, 256>>>(Fq, (__nv_bfloat16*)Qs);
        rope_split_kernel<<<blk, 256>>>(Fk, (__nv_bfloat16*)Ks);
        dim3 gt(DIM / 32, SEQ / 32, BATCH);
        transpose_split_kernel<<<gt, dim3(32, 8)>>>(Fv, (__nv_bfloat16*)Vts);
    }

    // 4. scores: E[b] = scale * Q[b] K[b]^T
    dim3 ge(SEQ / BN, SEQ / BM, BATCH);
    gemm3<<<ge, 256, SMEM_DYN>>>((const __nv_bfloat16*)Qs, (const __nv_bfloat16*)Ks,
                                 E, nullptr, DIM, SEQ, SEQ, SEQ,
                                 (long long)SEQ * SEQ, scale);

    // 5. softmax + split to bf16
    softmax_split_kernel<<<BATCH * SEQ, 256>>>(E, (__nv_bfloat16*)Es);

    // 6. O[b] = P[b] V[b]  (NT against transposed V)
    dim3 gpv(DIM / BN, SEQ / BM, BATCH);
    gemm3<<<gpv, 256, SMEM_DYN>>>((const __nv_bfloat16*)Es, (const __nv_bfloat16*)Vts,
                                  Fq, nullptr, SEQ, DIM, SEQ, DIM,
                                  (long long)SEQ * DIM, 1.0f);

    // 7. split O, output projection
    {
        long long n = (long long)MS * DIM;
        int blk = (int)((n + 255) / 256);
        split_kernel<<<blk, 256>>>(Fq, (__nv_bfloat16*)Os, DIM, n);
    }
    gemm3<<<gp, 256, SMEM_DYN>>>((const __nv_bfloat16*)Os, (const __nv_bfloat16*)Wos,
                                 out, bo, DIM, DIM, 0, 0, 0, 1.0f);
}

// round 5
// speedup vs baseline: 1.8722x; 1.0134x over previous
#include <cuda_runtime.h>
#include <cuda_bf16.h>
#include <stdint.h>
#include <math.h>

// ===========================================================================
// CrossAttention B=8, S=2048, D=512 (single head, fp32 I/O).
// GEMMs on mma.sync (HMMA bf16, fp32 accum), 3-term error-compensated split
// fused in a single k-loop, TERM-MAJOR mma ordering for tensor-pipe ILP:
//   C = Ahi*Bhi + Ahi*Blo + Alo*Bhi
// ===========================================================================

#define BATCH 8
#define SEQ   2048
#define DIM   512
#define MS    (BATCH * SEQ)     // 16384
#define HALFD (DIM / 2)

#define BM 128
#define BN 128
#define BKE 64                          // bf16 elems per k-chunk (128 bytes)
#define BKB 128                         // bytes per smem row
#define STAGES 3
#define TILE_BYTES (BM * BKB)           // 16384 (one 128x64 bf16 tile)
#define STAGE_BYTES (4 * TILE_BYTES)    // Ahi|Alo|Bhi|Blo = 65536
#define SMEM_DYN (STAGES * STAGE_BYTES) // 196608

// --------------------------- device scratch -------------------------------
__device__ __align__(1024) __nv_bfloat16 g_h1s[(size_t)MS * 2 * DIM];
__device__ __align__(1024) __nv_bfloat16 g_h2s[(size_t)MS * 2 * DIM];
__device__ __align__(1024) __nv_bfloat16 g_Wqs[(size_t)DIM * 2 * DIM];
__device__ __align__(1024) __nv_bfloat16 g_Wks[(size_t)DIM * 2 * DIM];
__device__ __align__(1024) __nv_bfloat16 g_Wvs[(size_t)DIM * 2 * DIM];
__device__ __align__(1024) __nv_bfloat16 g_Wos[(size_t)DIM * 2 * DIM];
__device__ __align__(1024) __nv_bfloat16 g_Qs[(size_t)MS * 2 * DIM];
__device__ __align__(1024) __nv_bfloat16 g_Ks[(size_t)MS * 2 * DIM];
__device__ __align__(1024) __nv_bfloat16 g_Vts[(size_t)BATCH * DIM * 2 * SEQ];
__device__ __align__(1024) __nv_bfloat16 g_Es[(size_t)BATCH * SEQ * 2 * SEQ];
__device__ __align__(1024) __nv_bfloat16 g_Os[(size_t)MS * 2 * DIM];
__device__ __align__(1024) float g_E[(size_t)BATCH * SEQ * SEQ];
__device__ __align__(1024) float g_Fq[(size_t)MS * DIM];
__device__ __align__(1024) float g_Fk[(size_t)MS * DIM];
__device__ __align__(1024) float g_Fv[(size_t)MS * DIM];

// --------------------------- PTX helpers -----------------------------------
__device__ __forceinline__ uint32_t smem_u32(const void* p) {
    uint32_t a;
    asm("{ .reg .u64 t; cvta.to.shared.u64 t, %1; cvt.u32.u64 %0, t; }"
        : "=r"(a) : "l"(p));
    return a;
}
__device__ __forceinline__ void cp_async16(uint32_t dst, const void* src) {
    asm volatile("cp.async.cg.shared.global [%0], [%1], 16;" :: "r"(dst), "l"(src));
}
__device__ __forceinline__ void cp_commit() {
    asm volatile("cp.async.commit_group;" ::: "memory");
}
template <int N> __device__ __forceinline__ void cp_wait() {
    asm volatile("cp.async.wait_group %0;" :: "n"(N) : "memory");
}
__device__ __forceinline__ void ldsm4(uint32_t& r0, uint32_t& r1, uint32_t& r2,
                                      uint32_t& r3, uint32_t a) {
    asm volatile("ldmatrix.sync.aligned.m8n8.x4.shared.b16 {%0,%1,%2,%3}, [%4];"
                 : "=r"(r0), "=r"(r1), "=r"(r2), "=r"(r3) : "r"(a));
}
__device__ __forceinline__ void mma16816(float* d, const uint32_t* a,
                                         uint32_t b0, uint32_t b1) {
    asm volatile(
        "mma.sync.aligned.m16n8k16.row.col.f32.bf16.bf16.f32 "
        "{%0,%1,%2,%3}, {%4,%5,%6,%7}, {%8,%9}, {%0,%1,%2,%3};"
        : "+f"(d[0]), "+f"(d[1]), "+f"(d[2]), "+f"(d[3])
        : "r"(a[0]), "r"(a[1]), "r"(a[2]), "r"(a[3]), "r"(b0), "r"(b1));
}
__device__ __forceinline__ uint32_t sw128(uint32_t off) {
    return off ^ ((off >> 3) & 0x70);
}

// --------------------------- GEMM kernel -----------------------------------
// NT: C[m,n] = alpha * (Ahi.Bhi + Ahi.Blo + Alo.Bhi)[m,n] + bias[n]
// A: [rowsA, 2*Kp] bf16 (cols [0,Kp)=hi, [Kp,2Kp)=lo), K-contiguous.
// B: [rowsB, 2*Kp] bf16 likewise.
__global__ __launch_bounds__(256) void gemm3(
    const __nv_bfloat16* __restrict__ A, const __nv_bfloat16* __restrict__ B,
    float* __restrict__ C, const float* __restrict__ bias,
    int Kp, int ldC, int aRowsPerB, int bRowsPerB, long long cPerB, float alpha)
{
    extern __shared__ __align__(1024) char smem[];
    const int tid  = threadIdx.x;
    const int wid  = tid >> 5;
    const int lane = tid & 31;
    const int wm   = wid & 3;     // 4 warps along M
    const int wn   = wid >> 2;    // 2 warps along N

    const long long lda = 2LL * Kp;
    A += (long long)blockIdx.z * aRowsPerB * lda + (long long)blockIdx.y * BM * lda;
    B += (long long)blockIdx.z * bRowsPerB * lda + (long long)blockIdx.x * BN * lda;

    const uint32_t smb = smem_u32(smem);
    const int chunks = Kp / BKE;

    auto issue = [&](int it) {
        const long long khi = (long long)it * BKE;
        const long long klo = (long long)Kp + it * BKE;
        const uint32_t sb = smb + (it % STAGES) * STAGE_BYTES;
        #pragma unroll
        for (int i = 0; i < 4; i++) {
            const int id = tid * 4 + i;
            const int r = id >> 3, c = id & 7;
            const uint32_t off = sw128((uint32_t)(r * BKB + c * 16));
            const long long arow = (long long)r * lda;
            cp_async16(sb + off,                  A + arow + khi + c * 8);
            cp_async16(sb + TILE_BYTES + off,     A + arow + klo + c * 8);
            cp_async16(sb + 2 * TILE_BYTES + off, B + arow + khi + c * 8);
            cp_async16(sb + 3 * TILE_BYTES + off, B + arow + klo + c * 8);
        }
        cp_commit();
    };

    float acc[2][8][4] = {};
    const int aRowBase = wm * 32;
    const int bRowBase = wn * 64;
    const int lrow = lane & 15;
    const int lkc  = lane >> 4;

    const int prol = (chunks < STAGES - 1) ? chunks : (STAGES - 1);
    for (int it = 0; it < prol; it++) issue(it);

    for (int it = 0; it < chunks; it++) {
        cp_wait<STAGES - 2>();
        __syncthreads();
        // stage (it-1) has been fully consumed by every warp before this sync,
        // so refill it now and overlap the cp.async with this iter's compute.
        if (it + STAGES - 1 < chunks) issue(it + STAGES - 1);

        const uint32_t sAhi = smb + (it % STAGES) * STAGE_BYTES;
        const uint32_t sAlo = sAhi + TILE_BYTES;
        const uint32_t sBhi = sAhi + 2 * TILE_BYTES;
        const uint32_t sBlo = sAhi + 3 * TILE_BYTES;

        #pragma unroll
        for (int ks = 0; ks < 4; ks++) {
            uint32_t ahi[2][4], alo[2][4], bhi[4][4], blo[4][4];
            #pragma unroll
            for (int mi = 0; mi < 2; mi++) {
                const int row = aRowBase + mi * 16 + lrow;
                const uint32_t off = sw128((uint32_t)(row * BKB + ks * 32 + lkc * 16));
                ldsm4(ahi[mi][0], ahi[mi][1], ahi[mi][2], ahi[mi][3], sAhi + off);
                ldsm4(alo[mi][0], alo[mi][1], alo[mi][2], alo[mi][3], sAlo + off);
            }
            #pragma unroll
            for (int nt = 0; nt < 4; nt++) {
                const int row = bRowBase + nt * 16 + lrow;
                const uint32_t off = sw128((uint32_t)(row * BKB + ks * 32 + lkc * 16));
                ldsm4(bhi[nt][0], bhi[nt][1], bhi[nt][2], bhi[nt][3], sBhi + off);
                ldsm4(blo[nt][0], blo[nt][1], blo[nt][2], blo[nt][3], sBlo + off);
            }
            // Term-major: 16 independent MMAs per term; accumulator reuse
            // distance = 16 issues >> HMMA latency -> no RAW stalls.
            #pragma unroll
            for (int mi = 0; mi < 2; mi++)
                #pragma unroll
                for (int nt = 0; nt < 4; nt++) {
                    mma16816(acc[mi][nt * 2],     ahi[mi], bhi[nt][0], bhi[nt][2]);
                    mma16816(acc[mi][nt * 2 + 1], ahi[mi], bhi[nt][1], bhi[nt][3]);
                }
            #pragma unroll
            for (int mi = 0; mi < 2; mi++)
                #pragma unroll
                for (int nt = 0; nt < 4; nt++) {
                    mma16816(acc[mi][nt * 2],     ahi[mi], blo[nt][0], blo[nt][2]);
                    mma16816(acc[mi][nt * 2 + 1], ahi[mi], blo[nt][1], blo[nt][3]);
                }
            #pragma unroll
            for (int mi = 0; mi < 2; mi++)
                #pragma unroll
                for (int nt = 0; nt < 4; nt++) {
                    mma16816(acc[mi][nt * 2],     alo[mi], bhi[nt][0], bhi[nt][2]);
                    mma16816(acc[mi][nt * 2 + 1], alo[mi], bhi[nt][1], bhi[nt][3]);
                }
        }
    }

    // Epilogue
    C += (long long)blockIdx.z * cPerB;
    const int m0 = blockIdx.y * BM + wm * 32;
    const int n0 = blockIdx.x * BN + wn * 64;
    #pragma unroll
    for (int mi = 0; mi < 2; mi++) {
        const int r = m0 + mi * 16 + (lane >> 2);
        #pragma unroll
        for (int nj = 0; nj < 8; nj++) {
            const int cidx = n0 + nj * 8 + (lane & 3) * 2;
            float b0 = 0.f, b1 = 0.f;
            if (bias) { b0 = bias[cidx]; b1 = bias[cidx + 1]; }
            float2 v0, v1;
            v0.x = acc[mi][nj][0] * alpha + b0;
            v0.y = acc[mi][nj][1] * alpha + b1;
            v1.x = acc[mi][nj][2] * alpha + b0;
            v1.y = acc[mi][nj][3] * alpha + b1;
            *reinterpret_cast<float2*>(C + (long long)r * ldC + cidx) = v0;
            *reinterpret_cast<float2*>(C + (long long)(r + 8) * ldC + cidx) = v1;
        }
    }
}

// --------------------------- elementwise kernels ---------------------------
__global__ void split_kernel(const float* __restrict__ x, __nv_bfloat16* __restrict__ y,
                             int K, long long n)
{
    long long i = (long long)blockIdx.x * blockDim.x + threadIdx.x;
    if (i >= n) return;
    long long r = i / K; int c = (int)(i % K);
    float f = x[i];
    __nv_bfloat16 hi = __float2bfloat16(f);
    float lo = f - __bfloat162float(hi);
    y[r * (2LL * K) + c]     = hi;
    y[r * (2LL * K) + K + c] = __float2bfloat16(lo);
}

__global__ void rope_split_kernel(const float* __restrict__ x, __nv_bfloat16* __restrict__ y)
{
    long long idx = (long long)blockIdx.x * blockDim.x + threadIdx.x;
    long long tot = (long long)MS * HALFD;
    if (idx >= tot) return;
    int j = (int)(idx % HALFD);
    long long bs = idx / HALFD;
    int s = (int)(bs % SEQ);

    float invf = powf(10000.0f, -(float)j / (float)HALFD);
    float ang = (float)s * invf;
    float c = cosf(ang), sn = sinf(ang);

    const float* p = x + bs * DIM;
    float x1 = p[j], x2 = p[j + HALFD];
    float o1 = x1 * c - x2 * sn;
    float o2 = x2 * c + x1 * sn;

    __nv_bfloat16* q = y + bs * (2 * DIM);
    __nv_bfloat16 h1b = __float2bfloat16(o1);
    __nv_bfloat16 h2b = __float2bfloat16(o2);
    q[j]               = h1b;
    q[DIM + j]         = __float2bfloat16(o1 - __bfloat162float(h1b));
    q[j + HALFD]       = h2b;
    q[DIM + j + HALFD] = __float2bfloat16(o2 - __bfloat162float(h2b));
}

// V [B, S(k), D(n)] fp32 -> Vt [B*D rows, 2*S cols] split bf16 (transposed)
__global__ void transpose_split_kernel(const float* __restrict__ V, __nv_bfloat16* __restrict__ Vt)
{
    __shared__ float tile[32][33];
    const int b  = blockIdx.z;
    const int n0 = blockIdx.x * 32;
    const int k0 = blockIdx.y * 32;
    const int tx = threadIdx.x, ty = threadIdx.y;   // block (32, 8)
    const float* src = V + (size_t)b * SEQ * DIM;
    #pragma unroll
    for (int i = 0; i < 4; i++)
        tile[ty + 8 * i][tx] = src[(size_t)(k0 + ty + 8 * i) * DIM + n0 + tx];
    __syncthreads();
    __nv_bfloat16* dst = Vt + (size_t)b * DIM * (2 * SEQ);
    #pragma unroll
    for (int i = 0; i < 4; i++) {
        float f = tile[tx][ty + 8 * i];
        __nv_bfloat16 hi = __float2bfloat16(f);
        float lo = f - __bfloat162float(hi);
        size_t row = (size_t)(n0 + ty + 8 * i) * (2 * SEQ) + (k0 + tx);
        dst[row]       = hi;
        dst[row + SEQ] = __float2bfloat16(lo);
    }
}

__global__ __launch_bounds__(256) void softmax_split_kernel(const float* __restrict__ E,
                                                            __nv_bfloat16* __restrict__ Es)
{
    const int T = 256, PER = SEQ / T;    // 8
    const float* p = E + (size_t)blockIdx.x * SEQ;
    __nv_bfloat16* o = Es + (size_t)blockIdx.x * (2 * SEQ);
    const int t = threadIdx.x;

    float v[PER];
    float m = -3.4e38f;
    #pragma unroll
    for (int i = 0; i < PER; i++) { v[i] = p[t + i * T]; m = fmaxf(m, v[i]); }
    #pragma unroll
    for (int off = 16; off; off >>= 1) m = fmaxf(m, __shfl_xor_sync(0xffffffffu, m, off));

    __shared__ float redm[8], reds[8];
    if ((t & 31) == 0) redm[t >> 5] = m;
    __syncthreads();
    float bm = redm[0];
    #pragma unroll
    for (int w = 1; w < 8; w++) bm = fmaxf(bm, redm[w]);

    float s = 0.0f;
    #pragma unroll
    for (int i = 0; i < PER; i++) { v[i] = expf(v[i] - bm); s += v[i]; }
    #pragma unroll
    for (int off = 16; off; off >>= 1) s += __shfl_xor_sync(0xffffffffu, s, off);
    if ((t & 31) == 0) reds[t >> 5] = s;
    __syncthreads();
    float bs = 0.0f;
    #pragma unroll
    for (int w = 0; w < 8; w++) bs += reds[w];

    float inv = 1.0f / bs;
    #pragma unroll
    for (int i = 0; i < PER; i++) {
        float f = v[i] * inv;
        __nv_bfloat16 hi = __float2bfloat16(f);
        o[t + i * T]       = hi;
        o[SEQ + t + i * T] = __float2bfloat16(f - __bfloat162float(hi));
    }
}

// --------------------------- host side -------------------------------------
extern "C" void kernel_launch(void* const* d_in, const int* in_sizes, int n_in,
                              void* d_out, int out_size)
{
    const float* h1 = (const float*)d_in[0];
    const float* h2 = (const float*)d_in[1];
    const float* Wq = (const float*)d_in[2];
    const float* bq = (const float*)d_in[3];
    const float* Wk = (const float*)d_in[4];
    const float* bk = (const float*)d_in[5];
    const float* Wv = (const float*)d_in[6];
    const float* bv = (const float*)d_in[7];
    const float* Wo = (const float*)d_in[8];
    const float* bo = (const float*)d_in[9];
    float* out = (float*)d_out;

    void *h1s, *h2s, *Wqs, *Wks, *Wvs, *Wos, *Qs, *Ks, *Vts, *Es, *Os;
    float *E, *Fq, *Fk, *Fv;
    cudaGetSymbolAddress(&h1s, g_h1s);  cudaGetSymbolAddress(&h2s, g_h2s);
    cudaGetSymbolAddress(&Wqs, g_Wqs);  cudaGetSymbolAddress(&Wks, g_Wks);
    cudaGetSymbolAddress(&Wvs, g_Wvs);  cudaGetSymbolAddress(&Wos, g_Wos);
    cudaGetSymbolAddress(&Qs, g_Qs);    cudaGetSymbolAddress(&Ks, g_Ks);
    cudaGetSymbolAddress(&Vts, g_Vts);  cudaGetSymbolAddress(&Es, g_Es);
    cudaGetSymbolAddress(&Os, g_Os);
    cudaGetSymbolAddress((void**)&E, g_E);
    cudaGetSymbolAddress((void**)&Fq, g_Fq);
    cudaGetSymbolAddress((void**)&Fk, g_Fk);
    cudaGetSymbolAddress((void**)&Fv, g_Fv);

    cudaFuncSetAttribute(gemm3, cudaFuncAttributeMaxDynamicSharedMemorySize, SMEM_DYN);

    const float scale = 0.044194173824159216f;  // 1/sqrt(512)

    // 1. split inputs and weights to bf16 hi|lo
    {
        long long n = (long long)MS * DIM;
        int blk = (int)((n + 255) / 256);
        split_kernel<<<blk, 256>>>(h1, (__nv_bfloat16*)h1s, DIM, n);
        split_kernel<<<blk, 256>>>(h2, (__nv_bfloat16*)h2s, DIM, n);
        long long nw = (long long)DIM * DIM;
        int blkw = (int)((nw + 255) / 256);
        split_kernel<<<blkw, 256>>>(Wq, (__nv_bfloat16*)Wqs, DIM, nw);
        split_kernel<<<blkw, 256>>>(Wk, (__nv_bfloat16*)Wks, DIM, nw);
        split_kernel<<<blkw, 256>>>(Wv, (__nv_bfloat16*)Wvs, DIM, nw);
        split_kernel<<<blkw, 256>>>(Wo, (__nv_bfloat16*)Wos, DIM, nw);
    }

    // 2. projections
    dim3 gp(DIM / BN, MS / BM, 1);
    gemm3<<<gp, 256, SMEM_DYN>>>((const __nv_bfloat16*)h1s, (const __nv_bfloat16*)Wqs,
                                 Fq, bq, DIM, DIM, 0, 0, 0, 1.0f);
    gemm3<<<gp, 256, SMEM_DYN>>>((const __nv_bfloat16*)h2s, (const __nv_bfloat16*)Wks,
                                 Fk, bk, DIM, DIM, 0, 0, 0, 1.0f);
    gemm3<<<gp, 256, SMEM_DYN>>>((const __nv_bfloat16*)h2s, (const __nv_bfloat16*)Wvs,
                                 Fv, bv, DIM, DIM, 0, 0, 0, 1.0f);

    // 3. RoPE + split Q, K ; transpose + split V
    {
        long long tot = (long long)MS * HALFD;
        int blk = (int)((tot + 255) / 256);
        rope_split_kernel<<<blk, 256>>>(Fq, (__nv_bfloat16*)Qs);
        rope_split_kernel<<<blk, 256>>>(Fk, (__nv_bfloat16*)Ks);
        dim3 gt(DIM / 32, SEQ / 32, BATCH);
        transpose_split_kernel<<<gt, dim3(32, 8)>>>(Fv, (__nv_bfloat16*)Vts);
    }

    // 4. scores: E[b] = scale * Q[b] K[b]^T
    dim3 ge(SEQ / BN, SEQ / BM, BATCH);
    gemm3<<<ge, 256, SMEM_DYN>>>((const __nv_bfloat16*)Qs, (const __nv_bfloat16*)Ks,
                                 E, nullptr, DIM, SEQ, SEQ, SEQ,
                                 (long long)SEQ * SEQ, scale);

    // 5. softmax + split to bf16
    softmax_split_kernel<<<BATCH * SEQ, 256>>>(E, (__nv_bfloat16*)Es);

    // 6. O[b] = P[b] V[b]  (NT against transposed V)
    dim3 gpv(DIM / BN, SEQ / BM, BATCH);
    gemm3<<<gpv, 256, SMEM_DYN>>>((const __nv_bfloat16*)Es, (const __nv_bfloat16*)Vts,
                                  Fq, nullptr, SEQ, DIM, SEQ, DIM,
                                  (long long)SEQ * DIM, 1.0f);

    // 7. split O, output projection
    {
        long long n = (long long)MS * DIM;
        int blk = (int)((n + 255) / 256);
        split_kernel<<<blk, 256>>>(Fq, (__nv_bfloat16*)Os, DIM, n);
    }
    gemm3<<<gp, 256, SMEM_DYN>>>((const __nv_bfloat16*)Os, (const __nv_bfloat16*)Wos,
                                 out, bo, DIM, DIM, 0, 0, 0, 1.0f);
}

// round 6
// speedup vs baseline: 2.2657x; 1.2102x over previous
#include <cuda_runtime.h>
#include <cuda_fp16.h>
#include <stdint.h>
#include <math.h>

// ===========================================================================
// CrossAttention B=8, S=2048, D=512 (single head, fp32 I/O).
// GEMMs on mma.sync (HMMA fp16, fp32 accum) with error-compensated splitting:
//   projections: C = Ahi*Bhi + Alo*Bhi + Ahi*Blo   (3-term, err ~1e-7)
//   attention:   C = Ahi*Bhi + Alo*Bhi             (2-term, err ~3e-4)
// ===========================================================================

#define BATCH 8
#define SEQ   2048
#define DIM   512
#define MS    (BATCH * SEQ)     // 16384
#define HALFD (DIM / 2)

#define BM 128
#define BN 128
#define BKE 64                          // fp16 elems per k-chunk (128 bytes)
#define BKB 128                         // bytes per smem row
#define STAGES 3
#define TILE_BYTES (BM * BKB)           // 16384 (one 128x64 f16 tile)
#define STAGE_BYTES (4 * TILE_BYTES)    // Ahi|Alo|Bhi|Blo = 65536
#define SMEM_DYN (STAGES * STAGE_BYTES) // 196608

// --------------------------- device scratch -------------------------------
__device__ __align__(1024) __half g_h1s[(size_t)MS * 2 * DIM];
__device__ __align__(1024) __half g_h2s[(size_t)MS * 2 * DIM];
__device__ __align__(1024) __half g_Wqs[(size_t)DIM * 2 * DIM];
__device__ __align__(1024) __half g_Wks[(size_t)DIM * 2 * DIM];
__device__ __align__(1024) __half g_Wvs[(size_t)DIM * 2 * DIM];
__device__ __align__(1024) __half g_Wos[(size_t)DIM * 2 * DIM];
__device__ __align__(1024) __half g_Qs[(size_t)MS * 2 * DIM];
__device__ __align__(1024) __half g_Ks[(size_t)MS * 2 * DIM];
__device__ __align__(1024) __half g_Vts[(size_t)BATCH * DIM * 2 * SEQ];
__device__ __align__(1024) __half g_Es[(size_t)BATCH * SEQ * 2 * SEQ];
__device__ __align__(1024) __half g_Os[(size_t)MS * 2 * DIM];
__device__ __align__(1024) float g_E[(size_t)BATCH * SEQ * SEQ];
__device__ __align__(1024) float g_Fq[(size_t)MS * DIM];
__device__ __align__(1024) float g_Fk[(size_t)MS * DIM];
__device__ __align__(1024) float g_Fv[(size_t)MS * DIM];

// --------------------------- PTX helpers -----------------------------------
__device__ __forceinline__ uint32_t smem_u32(const void* p) {
    uint32_t a;
    asm("{ .reg .u64 t; cvta.to.shared.u64 t, %1; cvt.u32.u64 %0, t; }"
        : "=r"(a) : "l"(p));
    return a;
}
__device__ __forceinline__ void cp_async16(uint32_t dst, const void* src) {
    asm volatile("cp.async.cg.shared.global [%0], [%1], 16;" :: "r"(dst), "l"(src));
}
__device__ __forceinline__ void cp_commit() {
    asm volatile("cp.async.commit_group;" ::: "memory");
}
template <int N> __device__ __forceinline__ void cp_wait() {
    asm volatile("cp.async.wait_group %0;" :: "n"(N) : "memory");
}
__device__ __forceinline__ void ldsm4(uint32_t& r0, uint32_t& r1, uint32_t& r2,
                                      uint32_t& r3, uint32_t a) {
    asm volatile("ldmatrix.sync.aligned.m8n8.x4.shared.b16 {%0,%1,%2,%3}, [%4];"
                 : "=r"(r0), "=r"(r1), "=r"(r2), "=r"(r3) : "r"(a));
}
__device__ __forceinline__ void mma16816(float* d, const uint32_t* a,
                                         uint32_t b0, uint32_t b1) {
    asm volatile(
        "mma.sync.aligned.m16n8k16.row.col.f32.f16.f16.f32 "
        "{%0,%1,%2,%3}, {%4,%5,%6,%7}, {%8,%9}, {%0,%1,%2,%3};"
        : "+f"(d[0]), "+f"(d[1]), "+f"(d[2]), "+f"(d[3])
        : "r"(a[0]), "r"(a[1]), "r"(a[2]), "r"(a[3]), "r"(b0), "r"(b1));
}
__device__ __forceinline__ uint32_t sw128(uint32_t off) {
    return off ^ ((off >> 3) & 0x70);
}

// --------------------------- GEMM kernel -----------------------------------
// NT: C[m,n] = alpha * (Ahi.Bhi + Alo.Bhi [+ Ahi.Blo if TERMS==3]) + bias[n]
// A: [rowsA, 2*Kp] f16 (cols [0,Kp)=hi, [Kp,2Kp)=lo), K-contiguous.
// B: [rowsB, 2*Kp] f16 likewise (lo half unused when TERMS==2).
template <int TERMS>
__global__ __launch_bounds__(256) void gemm_ec(
    const __half* __restrict__ A, const __half* __restrict__ B,
    float* __restrict__ C, const float* __restrict__ bias,
    int Kp, int ldC, int aRowsPerB, int bRowsPerB, long long cPerB, float alpha)
{
    extern __shared__ __align__(1024) char smem[];
    const int tid  = threadIdx.x;
    const int wid  = tid >> 5;
    const int lane = tid & 31;
    const int wm   = wid & 3;     // 4 warps along M
    const int wn   = wid >> 2;    // 2 warps along N

    const long long lda = 2LL * Kp;
    A += (long long)blockIdx.z * aRowsPerB * lda + (long long)blockIdx.y * BM * lda;
    B += (long long)blockIdx.z * bRowsPerB * lda + (long long)blockIdx.x * BN * lda;

    const uint32_t smb = smem_u32(smem);
    const int chunks = Kp / BKE;

    auto issue = [&](int it) {
        const long long khi = (long long)it * BKE;
        const long long klo = (long long)Kp + it * BKE;
        const uint32_t sb = smb + (it % STAGES) * STAGE_BYTES;
        #pragma unroll
        for (int i = 0; i < 4; i++) {
            const int id = tid * 4 + i;
            const int r = id >> 3, c = id & 7;
            const uint32_t off = sw128((uint32_t)(r * BKB + c * 16));
            const long long arow = (long long)r * lda;
            cp_async16(sb + off,                  A + arow + khi + c * 8);
            cp_async16(sb + TILE_BYTES + off,     A + arow + klo + c * 8);
            cp_async16(sb + 2 * TILE_BYTES + off, B + arow + khi + c * 8);
            if (TERMS == 3)
                cp_async16(sb + 3 * TILE_BYTES + off, B + arow + klo + c * 8);
        }
        cp_commit();
    };

    float acc[2][8][4] = {};
    const int aRowBase = wm * 32;
    const int bRowBase = wn * 64;
    const int lrow = lane & 15;
    const int lkc  = lane >> 4;

    const int prol = (chunks < STAGES - 1) ? chunks : (STAGES - 1);
    for (int it = 0; it < prol; it++) issue(it);

    for (int it = 0; it < chunks; it++) {
        cp_wait<STAGES - 2>();
        __syncthreads();
        // stage (it-1) fully consumed before this sync -> refill now,
        // overlapping cp.async issue with this iter's compute.
        if (it + STAGES - 1 < chunks) issue(it + STAGES - 1);

        const uint32_t sAhi = smb + (it % STAGES) * STAGE_BYTES;
        const uint32_t sAlo = sAhi + TILE_BYTES;
        const uint32_t sBhi = sAhi + 2 * TILE_BYTES;
        const uint32_t sBlo = sAhi + 3 * TILE_BYTES;

        #pragma unroll
        for (int ks = 0; ks < 4; ks++) {
            uint32_t ahi[2][4], alo[2][4], bhi[4][4], blo[4][4];
            #pragma unroll
            for (int mi = 0; mi < 2; mi++) {
                const int row = aRowBase + mi * 16 + lrow;
                const uint32_t off = sw128((uint32_t)(row * BKB + ks * 32 + lkc * 16));
                ldsm4(ahi[mi][0], ahi[mi][1], ahi[mi][2], ahi[mi][3], sAhi + off);
                ldsm4(alo[mi][0], alo[mi][1], alo[mi][2], alo[mi][3], sAlo + off);
            }
            #pragma unroll
            for (int nt = 0; nt < 4; nt++) {
                const int row = bRowBase + nt * 16 + lrow;
                const uint32_t off = sw128((uint32_t)(row * BKB + ks * 32 + lkc * 16));
                ldsm4(bhi[nt][0], bhi[nt][1], bhi[nt][2], bhi[nt][3], sBhi + off);
                if (TERMS == 3)
                    ldsm4(blo[nt][0], blo[nt][1], blo[nt][2], blo[nt][3], sBlo + off);
            }
            #pragma unroll
            for (int mi = 0; mi < 2; mi++)
                #pragma unroll
                for (int nt = 0; nt < 4; nt++) {
                    mma16816(acc[mi][nt * 2],     ahi[mi], bhi[nt][0], bhi[nt][2]);
                    mma16816(acc[mi][nt * 2 + 1], ahi[mi], bhi[nt][1], bhi[nt][3]);
                }
            #pragma unroll
            for (int mi = 0; mi < 2; mi++)
                #pragma unroll
                for (int nt = 0; nt < 4; nt++) {
                    mma16816(acc[mi][nt * 2],     alo[mi], bhi[nt][0], bhi[nt][2]);
                    mma16816(acc[mi][nt * 2 + 1], alo[mi], bhi[nt][1], bhi[nt][3]);
                }
            if (TERMS == 3) {
                #pragma unroll
                for (int mi = 0; mi < 2; mi++)
                    #pragma unroll
                    for (int nt = 0; nt < 4; nt++) {
                        mma16816(acc[mi][nt * 2],     ahi[mi], blo[nt][0], blo[nt][2]);
                        mma16816(acc[mi][nt * 2 + 1], ahi[mi], blo[nt][1], blo[nt][3]);
                    }
            }
        }
    }

    // Epilogue
    C += (long long)blockIdx.z * cPerB;
    const int m0 = blockIdx.y * BM + wm * 32;
    const int n0 = blockIdx.x * BN + wn * 64;
    #pragma unroll
    for (int mi = 0; mi < 2; mi++) {
        const int r = m0 + mi * 16 + (lane >> 2);
        #pragma unroll
        for (int nj = 0; nj < 8; nj++) {
            const int cidx = n0 + nj * 8 + (lane & 3) * 2;
            float b0 = 0.f, b1 = 0.f;
            if (bias) { b0 = bias[cidx]; b1 = bias[cidx + 1]; }
            float2 v0, v1;
            v0.x = acc[mi][nj][0] * alpha + b0;
            v0.y = acc[mi][nj][1] * alpha + b1;
            v1.x = acc[mi][nj][2] * alpha + b0;
            v1.y = acc[mi][nj][3] * alpha + b1;
            *reinterpret_cast<float2*>(C + (long long)r * ldC + cidx) = v0;
            *reinterpret_cast<float2*>(C + (long long)(r + 8) * ldC + cidx) = v1;
        }
    }
}

// --------------------------- elementwise kernels ---------------------------
__global__ void split_kernel(const float* __restrict__ x, __half* __restrict__ y,
                             int K, long long n)
{
    long long i = (long long)blockIdx.x * blockDim.x + threadIdx.x;
    if (i >= n) return;
    long long r = i / K; int c = (int)(i % K);
    float f = x[i];
    __half hi = __float2half(f);
    float lo = f - __half2float(hi);
    y[r * (2LL * K) + c]     = hi;
    y[r * (2LL * K) + K + c] = __float2half(lo);
}

__global__ void rope_split_kernel(const float* __restrict__ x, __half* __restrict__ y)
{
    long long idx = (long long)blockIdx.x * blockDim.x + threadIdx.x;
    long long tot = (long long)MS * HALFD;
    if (idx >= tot) return;
    int j = (int)(idx % HALFD);
    long long bs = idx / HALFD;
    int s = (int)(bs % SEQ);

    float invf = powf(10000.0f, -(float)j / (float)HALFD);
    float ang = (float)s * invf;
    float c = cosf(ang), sn = sinf(ang);

    const float* p = x + bs * DIM;
    float x1 = p[j], x2 = p[j + HALFD];
    float o1 = x1 * c - x2 * sn;
    float o2 = x2 * c + x1 * sn;

    __half* q = y + bs * (2 * DIM);
    __half h1b = __float2half(o1);
    __half h2b = __float2half(o2);
    q[j]               = h1b;
    q[DIM + j]         = __float2half(o1 - __half2float(h1b));
    q[j + HALFD]       = h2b;
    q[DIM + j + HALFD] = __float2half(o2 - __half2float(h2b));
}

// V [B, S(k), D(n)] fp32 -> Vt [B*D rows, 2*S cols] split f16 (transposed)
__global__ void transpose_split_kernel(const float* __restrict__ V, __half* __restrict__ Vt)
{
    __shared__ float tile[32][33];
    const int b  = blockIdx.z;
    const int n0 = blockIdx.x * 32;
    const int k0 = blockIdx.y * 32;
    const int tx = threadIdx.x, ty = threadIdx.y;   // block (32, 8)
    const float* src = V + (size_t)b * SEQ * DIM;
    #pragma unroll
    for (int i = 0; i < 4; i++)
        tile[ty + 8 * i][tx] = src[(size_t)(k0 + ty + 8 * i) * DIM + n0 + tx];
    __syncthreads();
    __half* dst = Vt + (size_t)b * DIM * (2 * SEQ);
    #pragma unroll
    for (int i = 0; i < 4; i++) {
        float f = tile[tx][ty + 8 * i];
        __half hi = __float2half(f);
        float lo = f - __half2float(hi);
        size_t row = (size_t)(n0 + ty + 8 * i) * (2 * SEQ) + (k0 + tx);
        dst[row]       = hi;
        dst[row + SEQ] = __float2half(lo);
    }
}

__global__ __launch_bounds__(256) void softmax_split_kernel(const float* __restrict__ E,
                                                            __half* __restrict__ Es)
{
    const int T = 256, PER = SEQ / T;    // 8
    const float* p = E + (size_t)blockIdx.x * SEQ;
    __half* o = Es + (size_t)blockIdx.x * (2 * SEQ);
    const int t = threadIdx.x;

    float v[PER];
    float m = -3.4e38f;
    #pragma unroll
    for (int i = 0; i < PER; i++) { v[i] = p[t + i * T]; m = fmaxf(m, v[i]); }
    #pragma unroll
    for (int off = 16; off; off >>= 1) m = fmaxf(m, __shfl_xor_sync(0xffffffffu, m, off));

    __shared__ float redm[8], reds[8];
    if ((t & 31) == 0) redm[t >> 5] = m;
    __syncthreads();
    float bm = redm[0];
    #pragma unroll
    for (int w = 1; w < 8; w++) bm = fmaxf(bm, redm[w]);

    float s = 0.0f;
    #pragma unroll
    for (int i = 0; i < PER; i++) { v[i] = expf(v[i] - bm); s += v[i]; }
    #pragma unroll
    for (int off = 16; off; off >>= 1) s += __shfl_xor_sync(0xffffffffu, s, off);
    if ((t & 31) == 0) reds[t >> 5] = s;
    __syncthreads();
    float bs = 0.0f;
    #pragma unroll
    for (int w = 0; w < 8; w++) bs += reds[w];

    float inv = 1.0f / bs;
    #pragma unroll
    for (int i = 0; i < PER; i++) {
        float f = v[i] * inv;
        __half hi = __float2half(f);
        o[t + i * T]       = hi;
        o[SEQ + t + i * T] = __float2half(f - __half2float(hi));
    }
}

// --------------------------- host side -------------------------------------
extern "C" void kernel_launch(void* const* d_in, const int* in_sizes, int n_in,
                              void* d_out, int out_size)
{
    const float* h1 = (const float*)d_in[0];
    const float* h2 = (const float*)d_in[1];
    const float* Wq = (const float*)d_in[2];
    const float* bq = (const float*)d_in[3];
    const float* Wk = (const float*)d_in[4];
    const float* bk = (const float*)d_in[5];
    const float* Wv = (const float*)d_in[6];
    const float* bv = (const float*)d_in[7];
    const float* Wo = (const float*)d_in[8];
    const float* bo = (const float*)d_in[9];
    float* out = (float*)d_out;

    void *h1s, *h2s, *Wqs, *Wks, *Wvs, *Wos, *Qs, *Ks, *Vts, *Es, *Os;
    float *E, *Fq, *Fk, *Fv;
    cudaGetSymbolAddress(&h1s, g_h1s);  cudaGetSymbolAddress(&h2s, g_h2s);
    cudaGetSymbolAddress(&Wqs, g_Wqs);  cudaGetSymbolAddress(&Wks, g_Wks);
    cudaGetSymbolAddress(&Wvs, g_Wvs);  cudaGetSymbolAddress(&Wos, g_Wos);
    cudaGetSymbolAddress(&Qs, g_Qs);    cudaGetSymbolAddress(&Ks, g_Ks);
    cudaGetSymbolAddress(&Vts, g_Vts);  cudaGetSymbolAddress(&Es, g_Es);
    cudaGetSymbolAddress(&Os, g_Os);
    cudaGetSymbolAddress((void**)&E, g_E);
    cudaGetSymbolAddress((void**)&Fq, g_Fq);
    cudaGetSymbolAddress((void**)&Fk, g_Fk);
    cudaGetSymbolAddress((void**)&Fv, g_Fv);

    cudaFuncSetAttribute(gemm_ec<3>, cudaFuncAttributeMaxDynamicSharedMemorySize, SMEM_DYN);
    cudaFuncSetAttribute(gemm_ec<2>, cudaFuncAttributeMaxDynamicSharedMemorySize, SMEM_DYN);

    const float scale = 0.044194173824159216f;  // 1/sqrt(512)

    long long nIn = (long long)MS * DIM;
    int blkIn = (int)((nIn + 255) / 256);
    long long nW = (long long)DIM * DIM;
    int blkW = (int)((nW + 255) / 256);

    // Launches 0-4: splits needed for the first GEMM wave.
    split_kernel<<<blkIn, 256>>>(h1, (__half*)h1s, DIM, nIn);
    split_kernel<<<blkIn, 256>>>(h2, (__half*)h2s, DIM, nIn);
    split_kernel<<<blkW, 256>>>(Wq, (__half*)Wqs, DIM, nW);
    split_kernel<<<blkW, 256>>>(Wk, (__half*)Wks, DIM, nW);
    split_kernel<<<blkW, 256>>>(Wv, (__half*)Wvs, DIM, nW);

    // Launch 5 (ncu -s 5 -c 1 profiles this one): Q projection GEMM.
    dim3 gp(DIM / BN, MS / BM, 1);
    gemm_ec<3><<<gp, 256, SMEM_DYN>>>((const __half*)h1s, (const __half*)Wqs,
                                      Fq, bq, DIM, DIM, 0, 0, 0, 1.0f);
    gemm_ec<3><<<gp, 256, SMEM_DYN>>>((const __half*)h2s, (const __half*)Wks,
                                      Fk, bk, DIM, DIM, 0, 0, 0, 1.0f);
    gemm_ec<3><<<gp, 256, SMEM_DYN>>>((const __half*)h2s, (const __half*)Wvs,
                                      Fv, bv, DIM, DIM, 0, 0, 0, 1.0f);

    // RoPE + split Q, K ; transpose + split V ; split Wo (needed later)
    {
        long long tot = (long long)MS * HALFD;
        int blk = (int)((tot + 255) / 256);
        rope_split_kernel<<<blk, 256>>>(Fq, (__half*)Qs);
        rope_split_kernel<<<blk, 256>>>(Fk, (__half*)Ks);
        dim3 gt(DIM / 32, SEQ / 32, BATCH);
        transpose_split_kernel<<<gt, dim3(32, 8)>>>(Fv, (__half*)Vts);
        split_kernel<<<blkW, 256>>>(Wo, (__half*)Wos, DIM, nW);
    }

    // scores: E[b] = scale * Q[b] K[b]^T   (2-term)
    dim3 ge(SEQ / BN, SEQ / BM, BATCH);
    gemm_ec<2><<<ge, 256, SMEM_DYN>>>((const __half*)Qs, (const __half*)Ks,
                                      E, nullptr, DIM, SEQ, SEQ, SEQ,
                                      (long long)SEQ * SEQ, scale);

    // softmax + split to f16
    softmax_split_kernel<<<BATCH * SEQ, 256>>>(E, (__half*)Es);

    // O[b] = P[b] V[b]  (NT against transposed V, 2-term)
    dim3 gpv(DIM / BN, SEQ / BM, BATCH);
    gemm_ec<2><<<gpv, 256, SMEM_DYN>>>((const __half*)Es, (const __half*)Vts,
                                       Fq, nullptr, SEQ, DIM, SEQ, DIM,
                                       (long long)SEQ * DIM, 1.0f);

    // split O, output projection (3-term)
    split_kernel<<<blkIn, 256>>>(Fq, (__half*)Os, DIM, nIn);
    gemm_ec<3><<<gp, 256, SMEM_DYN>>>((const __half*)Os, (const __half*)Wos,
                                      out, bo, DIM, DIM, 0, 0, 0, 1.0f);
}

// round 7
// speedup vs baseline: 2.8608x; 1.2626x over previous
#include <cuda_runtime.h>
#include <cuda_fp16.h>
#include <stdint.h>
#include <math.h>

// ===========================================================================
// CrossAttention B=8, S=2048, D=512 (single head, fp32 I/O).
// GEMMs on mma.sync (HMMA fp16, fp32 accum), error-compensated splitting with
// per-GEMM term counts chosen against the 1e-3 rel_err budget:
//   QKV projections : 2-term  (Ahi*Bhi + Alo*Bhi)
//   QK^T            : 1-term  (Qhi*Khi)            [E errors are absolute]
//   PV              : 2-term  (Phi*Vhi + Plo*Vhi)  [P>0: lo limb mandatory]
//   out projection  : 2-term
// ===========================================================================

#define BATCH 8
#define SEQ   2048
#define DIM   512
#define MS    (BATCH * SEQ)     // 16384
#define HALFD (DIM / 2)

#define BM 128
#define BN 128
#define BKE 64                          // fp16 elems per k-chunk (128 bytes)
#define BKB 128                         // bytes per smem row
#define STAGES 3
#define TILE_BYTES (BM * BKB)           // 16384 (one 128x64 f16 tile)
#define SMEM_T2 (STAGES * 3 * TILE_BYTES)   // 147456 (Ahi|Alo|Bhi)
#define SMEM_T1 (STAGES * 2 * TILE_BYTES)   //  98304 (Ahi|Bhi)

// --------------------------- device scratch -------------------------------
__device__ __align__(1024) __half g_h1s[(size_t)MS * 2 * DIM];
__device__ __align__(1024) __half g_h2s[(size_t)MS * 2 * DIM];
__device__ __align__(1024) __half g_Wqs[(size_t)DIM * 2 * DIM];
__device__ __align__(1024) __half g_Wks[(size_t)DIM * 2 * DIM];
__device__ __align__(1024) __half g_Wvs[(size_t)DIM * 2 * DIM];
__device__ __align__(1024) __half g_Wos[(size_t)DIM * 2 * DIM];
__device__ __align__(1024) __half g_Qs[(size_t)MS * 2 * DIM];
__device__ __align__(1024) __half g_Ks[(size_t)MS * 2 * DIM];
__device__ __align__(1024) __half g_Vts[(size_t)BATCH * DIM * 2 * SEQ];
__device__ __align__(1024) __half g_Es[(size_t)BATCH * SEQ * 2 * SEQ];
__device__ __align__(1024) __half g_Os[(size_t)MS * 2 * DIM];
__device__ __align__(1024) float g_E[(size_t)BATCH * SEQ * SEQ];
__device__ __align__(1024) float g_Fq[(size_t)MS * DIM];
__device__ __align__(1024) float g_Fk[(size_t)MS * DIM];
__device__ __align__(1024) float g_Fv[(size_t)MS * DIM];

// --------------------------- PTX helpers -----------------------------------
__device__ __forceinline__ uint32_t smem_u32(const void* p) {
    uint32_t a;
    asm("{ .reg .u64 t; cvta.to.shared.u64 t, %1; cvt.u32.u64 %0, t; }"
        : "=r"(a) : "l"(p));
    return a;
}
__device__ __forceinline__ void cp_async16(uint32_t dst, const void* src) {
    asm volatile("cp.async.cg.shared.global [%0], [%1], 16;" :: "r"(dst), "l"(src));
}
__device__ __forceinline__ void cp_commit() {
    asm volatile("cp.async.commit_group;" ::: "memory");
}
template <int N> __device__ __forceinline__ void cp_wait() {
    asm volatile("cp.async.wait_group %0;" :: "n"(N) : "memory");
}
__device__ __forceinline__ void ldsm4(uint32_t& r0, uint32_t& r1, uint32_t& r2,
                                      uint32_t& r3, uint32_t a) {
    asm volatile("ldmatrix.sync.aligned.m8n8.x4.shared.b16 {%0,%1,%2,%3}, [%4];"
                 : "=r"(r0), "=r"(r1), "=r"(r2), "=r"(r3) : "r"(a));
}
__device__ __forceinline__ void mma16816(float* d, const uint32_t* a,
                                         uint32_t b0, uint32_t b1) {
    asm volatile(
        "mma.sync.aligned.m16n8k16.row.col.f32.f16.f16.f32 "
        "{%0,%1,%2,%3}, {%4,%5,%6,%7}, {%8,%9}, {%0,%1,%2,%3};"
        : "+f"(d[0]), "+f"(d[1]), "+f"(d[2]), "+f"(d[3])
        : "r"(a[0]), "r"(a[1]), "r"(a[2]), "r"(a[3]), "r"(b0), "r"(b1));
}
__device__ __forceinline__ uint32_t sw128(uint32_t off) {
    return off ^ ((off >> 3) & 0x70);
}

// --------------------------- GEMM core -------------------------------------
// NT: C[m,n] = alpha * (Ahi.Bhi [+ Alo.Bhi if TERMS>=2]) + bias[n]
// A,B: [rows, 2*Kp] f16, hi in cols [0,Kp), lo in [Kp,2Kp). B lo never read.
// A,B pre-offset to this CTA's tile rows; C pre-offset to this batch.
template <int TERMS>
__device__ __forceinline__ void gemm_core(
    const __half* __restrict__ A, const __half* __restrict__ B,
    float* __restrict__ C, const float* __restrict__ bias,
    int Kp, int ldC, float alpha, int m0, int n0, char* smem)
{
    constexpr int NTILES = (TERMS >= 2) ? 3 : 2;
    constexpr int STB = NTILES * TILE_BYTES;
    constexpr uint32_t BHI = (TERMS >= 2) ? 2 * TILE_BYTES : TILE_BYTES;

    const int tid  = threadIdx.x;
    const int wid  = tid >> 5;
    const int lane = tid & 31;
    const int wm   = wid & 3;     // 4 warps along M
    const int wn   = wid >> 2;    // 2 warps along N
    const long long lda = 2LL * Kp;
    const uint32_t smb = smem_u32(smem);
    const int chunks = Kp / BKE;

    auto issue = [&](int it) {
        const long long khi = (long long)it * BKE;
        const long long klo = (long long)Kp + it * BKE;
        const uint32_t sb = smb + (it % STAGES) * STB;
        #pragma unroll
        for (int i = 0; i < 4; i++) {
            const int id = tid * 4 + i;
            const int r = id >> 3, c = id & 7;
            const uint32_t off = sw128((uint32_t)(r * BKB + c * 16));
            const long long arow = (long long)r * lda;
            cp_async16(sb + off, A + arow + khi + c * 8);
            if (TERMS >= 2)
                cp_async16(sb + TILE_BYTES + off, A + arow + klo + c * 8);
            cp_async16(sb + BHI + off, B + arow + khi + c * 8);
        }
        cp_commit();
    };

    float acc[2][8][4] = {};
    const int aRowBase = wm * 32;
    const int bRowBase = wn * 64;
    const int lrow = lane & 15;
    const int lkc  = lane >> 4;

    const int prol = (chunks < STAGES - 1) ? chunks : (STAGES - 1);
    for (int it = 0; it < prol; it++) issue(it);

    for (int it = 0; it < chunks; it++) {
        cp_wait<STAGES - 2>();
        __syncthreads();
        if (it + STAGES - 1 < chunks) issue(it + STAGES - 1);

        const uint32_t sAhi = smb + (it % STAGES) * STB;
        const uint32_t sAlo = sAhi + TILE_BYTES;
        const uint32_t sBhi = sAhi + BHI;

        #pragma unroll
        for (int ks = 0; ks < 4; ks++) {
            uint32_t ahi[2][4], alo[2][4], bhi[4][4];
            #pragma unroll
            for (int mi = 0; mi < 2; mi++) {
                const int row = aRowBase + mi * 16 + lrow;
                const uint32_t off = sw128((uint32_t)(row * BKB + ks * 32 + lkc * 16));
                ldsm4(ahi[mi][0], ahi[mi][1], ahi[mi][2], ahi[mi][3], sAhi + off);
                if (TERMS >= 2)
                    ldsm4(alo[mi][0], alo[mi][1], alo[mi][2], alo[mi][3], sAlo + off);
            }
            #pragma unroll
            for (int nt = 0; nt < 4; nt++) {
                const int row = bRowBase + nt * 16 + lrow;
                const uint32_t off = sw128((uint32_t)(row * BKB + ks * 32 + lkc * 16));
                ldsm4(bhi[nt][0], bhi[nt][1], bhi[nt][2], bhi[nt][3], sBhi + off);
            }
            #pragma unroll
            for (int mi = 0; mi < 2; mi++)
                #pragma unroll
                for (int nt = 0; nt < 4; nt++) {
                    mma16816(acc[mi][nt * 2],     ahi[mi], bhi[nt][0], bhi[nt][2]);
                    mma16816(acc[mi][nt * 2 + 1], ahi[mi], bhi[nt][1], bhi[nt][3]);
                }
            if (TERMS >= 2) {
                #pragma unroll
                for (int mi = 0; mi < 2; mi++)
                    #pragma unroll
                    for (int nt = 0; nt < 4; nt++) {
                        mma16816(acc[mi][nt * 2],     alo[mi], bhi[nt][0], bhi[nt][2]);
                        mma16816(acc[mi][nt * 2 + 1], alo[mi], bhi[nt][1], bhi[nt][3]);
                    }
            }
        }
    }

    // Epilogue
    #pragma unroll
    for (int mi = 0; mi < 2; mi++) {
        const int r = m0 + wm * 32 + mi * 16 + (lane >> 2);
        #pragma unroll
        for (int nj = 0; nj < 8; nj++) {
            const int cidx = n0 + wn * 64 + nj * 8 + (lane & 3) * 2;
            float b0 = 0.f, b1 = 0.f;
            if (bias) { b0 = bias[cidx]; b1 = bias[cidx + 1]; }
            float2 v0, v1;
            v0.x = acc[mi][nj][0] * alpha + b0;
            v0.y = acc[mi][nj][1] * alpha + b1;
            v1.x = acc[mi][nj][2] * alpha + b0;
            v1.y = acc[mi][nj][3] * alpha + b1;
            *reinterpret_cast<float2*>(C + (long long)r * ldC + cidx) = v0;
            *reinterpret_cast<float2*>(C + (long long)(r + 8) * ldC + cidx) = v1;
        }
    }
}

// Generic (possibly batched) GEMM
template <int TERMS>
__global__ __launch_bounds__(256) void gemm_ec(
    const __half* __restrict__ A, const __half* __restrict__ B,
    float* __restrict__ C, const float* __restrict__ bias,
    int Kp, int ldC, int aRowsPerB, int bRowsPerB, long long cPerB, float alpha)
{
    extern __shared__ __align__(1024) char smem[];
    const long long lda = 2LL * Kp;
    const __half* Ab = A + ((long long)blockIdx.z * aRowsPerB + (long long)blockIdx.y * BM) * lda;
    const __half* Bb = B + ((long long)blockIdx.z * bRowsPerB + (long long)blockIdx.x * BN) * lda;
    float* Cb = C + (long long)blockIdx.z * cPerB;
    gemm_core<TERMS>(Ab, Bb, Cb, bias, Kp, ldC, alpha,
                     blockIdx.y * BM, blockIdx.x * BN, smem);
}

// Fused Q/K/V projections: one launch, z selects the GEMM (cuts wave tail).
__global__ __launch_bounds__(256) void gemm_qkv(
    const __half* __restrict__ h1s, const __half* __restrict__ h2s,
    const __half* __restrict__ Wq, const __half* __restrict__ Wk,
    const __half* __restrict__ Wv,
    float* __restrict__ Fq, float* __restrict__ Fk, float* __restrict__ Fv,
    const float* __restrict__ bq, const float* __restrict__ bk,
    const float* __restrict__ bv)
{
    extern __shared__ __align__(1024) char smem[];
    const __half* A; const __half* B; float* C; const float* bias;
    if (blockIdx.z == 0)      { A = h1s; B = Wq; C = Fq; bias = bq; }
    else if (blockIdx.z == 1) { A = h2s; B = Wk; C = Fk; bias = bk; }
    else                      { A = h2s; B = Wv; C = Fv; bias = bv; }
    const long long lda = 2LL * DIM;
    A += (long long)blockIdx.y * BM * lda;
    B += (long long)blockIdx.x * BN * lda;
    gemm_core<2>(A, B, C, bias, DIM, DIM, 1.0f,
                 blockIdx.y * BM, blockIdx.x * BN, smem);
}

// --------------------------- elementwise kernels ---------------------------
__global__ void split_kernel(const float* __restrict__ x, __half* __restrict__ y,
                             int K, long long n, int write_lo)
{
    long long i = (long long)blockIdx.x * blockDim.x + threadIdx.x;
    if (i >= n) return;
    long long r = i / K; int c = (int)(i % K);
    float f = x[i];
    __half hi = __float2half(f);
    y[r * (2LL * K) + c] = hi;
    if (write_lo)
        y[r * (2LL * K) + K + c] = __float2half(f - __half2float(hi));
}

// RoPE, hi limb only (Q and K are consumed hi-only downstream)
__global__ void rope_hi_kernel(const float* __restrict__ x, __half* __restrict__ y)
{
    long long idx = (long long)blockIdx.x * blockDim.x + threadIdx.x;
    long long tot = (long long)MS * HALFD;
    if (idx >= tot) return;
    int j = (int)(idx % HALFD);
    long long bs = idx / HALFD;
    int s = (int)(bs % SEQ);

    float invf = powf(10000.0f, -(float)j / (float)HALFD);
    float ang = (float)s * invf;
    float c = cosf(ang), sn = sinf(ang);

    const float* p = x + bs * DIM;
    float x1 = p[j], x2 = p[j + HALFD];
    __half* q = y + bs * (2 * DIM);
    q[j]         = __float2half(x1 * c - x2 * sn);
    q[j + HALFD] = __float2half(x2 * c + x1 * sn);
}

// V [B, S(k), D(n)] fp32 -> Vt [B*D rows, 2*S cols] f16 hi-only (transposed)
__global__ void transpose_hi_kernel(const float* __restrict__ V, __half* __restrict__ Vt)
{
    __shared__ float tile[32][33];
    const int b  = blockIdx.z;
    const int n0 = blockIdx.x * 32;
    const int k0 = blockIdx.y * 32;
    const int tx = threadIdx.x, ty = threadIdx.y;   // block (32, 8)
    const float* src = V + (size_t)b * SEQ * DIM;
    #pragma unroll
    for (int i = 0; i < 4; i++)
        tile[ty + 8 * i][tx] = src[(size_t)(k0 + ty + 8 * i) * DIM + n0 + tx];
    __syncthreads();
    __half* dst = Vt + (size_t)b * DIM * (2 * SEQ);
    #pragma unroll
    for (int i = 0; i < 4; i++) {
        float f = tile[tx][ty + 8 * i];
        dst[(size_t)(n0 + ty + 8 * i) * (2 * SEQ) + (k0 + tx)] = __float2half(f);
    }
}

__global__ __launch_bounds__(256) void softmax_split_kernel(const float* __restrict__ E,
                                                            __half* __restrict__ Es)
{
    const int T = 256, PER = SEQ / T;    // 8
    const float* p = E + (size_t)blockIdx.x * SEQ;
    __half* o = Es + (size_t)blockIdx.x * (2 * SEQ);
    const int t = threadIdx.x;

    float v[PER];
    float m = -3.4e38f;
    #pragma unroll
    for (int i = 0; i < PER; i++) { v[i] = p[t + i * T]; m = fmaxf(m, v[i]); }
    #pragma unroll
    for (int off = 16; off; off >>= 1) m = fmaxf(m, __shfl_xor_sync(0xffffffffu, m, off));

    __shared__ float redm[8], reds[8];
    if ((t & 31) == 0) redm[t >> 5] = m;
    __syncthreads();
    float bm = redm[0];
    #pragma unroll
    for (int w = 1; w < 8; w++) bm = fmaxf(bm, redm[w]);

    float s = 0.0f;
    #pragma unroll
    for (int i = 0; i < PER; i++) { v[i] = expf(v[i] - bm); s += v[i]; }
    #pragma unroll
    for (int off = 16; off; off >>= 1) s += __shfl_xor_sync(0xffffffffu, s, off);
    if ((t & 31) == 0) reds[t >> 5] = s;
    __syncthreads();
    float bs = 0.0f;
    #pragma unroll
    for (int w = 0; w < 8; w++) bs += reds[w];

    float inv = 1.0f / bs;
    #pragma unroll
    for (int i = 0; i < PER; i++) {
        float f = v[i] * inv;
        __half hi = __float2half(f);
        o[t + i * T]       = hi;
        o[SEQ + t + i * T] = __float2half(f - __half2float(hi));
    }
}

// --------------------------- host side -------------------------------------
extern "C" void kernel_launch(void* const* d_in, const int* in_sizes, int n_in,
                              void* d_out, int out_size)
{
    const float* h1 = (const float*)d_in[0];
    const float* h2 = (const float*)d_in[1];
    const float* Wq = (const float*)d_in[2];
    const float* bq = (const float*)d_in[3];
    const float* Wk = (const float*)d_in[4];
    const float* bk = (const float*)d_in[5];
    const float* Wv = (const float*)d_in[6];
    const float* bv = (const float*)d_in[7];
    const float* Wo = (const float*)d_in[8];
    const float* bo = (const float*)d_in[9];
    float* out = (float*)d_out;

    void *h1s, *h2s, *Wqs, *Wks, *Wvs, *Wos, *Qs, *Ks, *Vts, *Es, *Os;
    float *E, *Fq, *Fk, *Fv;
    cudaGetSymbolAddress(&h1s, g_h1s);  cudaGetSymbolAddress(&h2s, g_h2s);
    cudaGetSymbolAddress(&Wqs, g_Wqs);  cudaGetSymbolAddress(&Wks, g_Wks);
    cudaGetSymbolAddress(&Wvs, g_Wvs);  cudaGetSymbolAddress(&Wos, g_Wos);
    cudaGetSymbolAddress(&Qs, g_Qs);    cudaGetSymbolAddress(&Ks, g_Ks);
    cudaGetSymbolAddress(&Vts, g_Vts);  cudaGetSymbolAddress(&Es, g_Es);
    cudaGetSymbolAddress(&Os, g_Os);
    cudaGetSymbolAddress((void**)&E, g_E);
    cudaGetSymbolAddress((void**)&Fq, g_Fq);
    cudaGetSymbolAddress((void**)&Fk, g_Fk);
    cudaGetSymbolAddress((void**)&Fv, g_Fv);

    cudaFuncSetAttribute(gemm_qkv,   cudaFuncAttributeMaxDynamicSharedMemorySize, SMEM_T2);
    cudaFuncSetAttribute(gemm_ec<2>, cudaFuncAttributeMaxDynamicSharedMemorySize, SMEM_T2);
    cudaFuncSetAttribute(gemm_ec<1>, cudaFuncAttributeMaxDynamicSharedMemorySize, SMEM_T1);

    const float scale = 0.044194173824159216f;  // 1/sqrt(512)

    long long nIn = (long long)MS * DIM;
    int blkIn = (int)((nIn + 255) / 256);
    long long nW = (long long)DIM * DIM;
    int blkW = (int)((nW + 255) / 256);

    // Launches 0-4: splits (A-side inputs need lo; weights are B-side, hi only)
    split_kernel<<<blkIn, 256>>>(h1, (__half*)h1s, DIM, nIn, 1);
    split_kernel<<<blkIn, 256>>>(h2, (__half*)h2s, DIM, nIn, 1);
    split_kernel<<<blkW, 256>>>(Wq, (__half*)Wqs, DIM, nW, 0);
    split_kernel<<<blkW, 256>>>(Wk, (__half*)Wks, DIM, nW, 0);
    split_kernel<<<blkW, 256>>>(Wv, (__half*)Wvs, DIM, nW, 0);

    // Launch 5 (ncu -s 5 -c 1 profiles this): fused Q/K/V projections, 2-term
    dim3 gqkv(DIM / BN, MS / BM, 3);
    gemm_qkv<<<gqkv, 256, SMEM_T2>>>((const __half*)h1s, (const __half*)h2s,
                                     (const __half*)Wqs, (const __half*)Wks,
                                     (const __half*)Wvs, Fq, Fk, Fv, bq, bk, bv);

    // RoPE hi-only; transpose V hi-only; split Wo (hi only, B-side)
    {
        long long tot = (long long)MS * HALFD;
        int blk = (int)((tot + 255) / 256);
        rope_hi_kernel<<<blk, 256>>>(Fq, (__half*)Qs);
        rope_hi_kernel<<<blk, 256>>>(Fk, (__half*)Ks);
        dim3 gt(DIM / 32, SEQ / 32, BATCH);
        transpose_hi_kernel<<<gt, dim3(32, 8)>>>(Fv, (__half*)Vts);
        split_kernel<<<blkW, 256>>>(Wo, (__half*)Wos, DIM, nW, 0);
    }

    // scores: E[b] = scale * Qhi[b] Khi[b]^T   (1-term)
    dim3 ge(SEQ / BN, SEQ / BM, BATCH);
    gemm_ec<1><<<ge, 256, SMEM_T1>>>((const __half*)Qs, (const __half*)Ks,
                                     E, nullptr, DIM, SEQ, SEQ, SEQ,
                                     (long long)SEQ * SEQ, scale);

    // softmax + split P to f16 hi|lo
    softmax_split_kernel<<<BATCH * SEQ, 256>>>(E, (__half*)Es);

    // O[b] = P[b] V[b]  (NT vs transposed V, 2-term)
    dim3 gpv(DIM / BN, SEQ / BM, BATCH);
    gemm_ec<2><<<gpv, 256, SMEM_T2>>>((const __half*)Es, (const __half*)Vts,
                                      Fq, nullptr, SEQ, DIM, SEQ, DIM,
                                      (long long)SEQ * DIM, 1.0f);

    // split O (A-side: hi+lo), output projection (2-term)
    split_kernel<<<blkIn, 256>>>(Fq, (__half*)Os, DIM, nIn, 1);
    dim3 gp(DIM / BN, MS / BM, 1);
    gemm_ec<2><<<gp, 256, SMEM_T2>>>((const __half*)Os, (const __half*)Wos,
                                     out, bo, DIM, DIM, 0, 0, 0, 1.0f);
}

// round 8
// speedup vs baseline: 3.4416x; 1.2030x over previous
#include <cuda_runtime.h>
#include <cuda_fp16.h>
#include <stdint.h>
#include <math.h>

// ===========================================================================
// CrossAttention B=8, S=2048, D=512 (single head, fp32 I/O).
// GEMMs on mma.sync (HMMA fp16, fp32 accum), error-compensated splitting with
// per-GEMM term counts tuned against the 1e-3 rel_err budget:
//   QKV projections : 2-term  (Ahi*Bhi + Alo*Bhi)
//   QK^T            : 1-term  (Qhi*Khi)
//   PV              : 1-term  (Phi*Vhi)
//   out projection  : 2-term
// 1-term operands use compact hi-only layouts; 1-term GEMMs run 2 CTAs/SM.
// ===========================================================================

#define BATCH 8
#define SEQ   2048
#define DIM   512
#define MS    (BATCH * SEQ)     // 16384
#define HALFD (DIM / 2)

#define BM 128
#define BN 128
#define BKE 64                          // fp16 elems per k-chunk (128 bytes)
#define BKB 128                         // bytes per smem row
#define STAGES 3
#define TILE_BYTES (BM * BKB)           // 16384 (one 128x64 f16 tile)
#define SMEM_T2 (STAGES * 3 * TILE_BYTES)   // 147456 (Ahi|Alo|Bhi)
#define SMEM_T1 (STAGES * 2 * TILE_BYTES)   //  98304 (Ahi|Bhi) -> 2 CTAs/SM

// --------------------------- device scratch -------------------------------
// 2-term (hi|lo, stride 2*K):
__device__ __align__(1024) __half g_h1s[(size_t)MS * 2 * DIM];
__device__ __align__(1024) __half g_h2s[(size_t)MS * 2 * DIM];
__device__ __align__(1024) __half g_Wqs[(size_t)DIM * 2 * DIM];
__device__ __align__(1024) __half g_Wks[(size_t)DIM * 2 * DIM];
__device__ __align__(1024) __half g_Wvs[(size_t)DIM * 2 * DIM];
__device__ __align__(1024) __half g_Wos[(size_t)DIM * 2 * DIM];
__device__ __align__(1024) __half g_Os[(size_t)MS * 2 * DIM];
// 1-term compact (hi only, stride K):
__device__ __align__(1024) __half g_Qs[(size_t)MS * DIM];
__device__ __align__(1024) __half g_Ks[(size_t)MS * DIM];
__device__ __align__(1024) __half g_Vts[(size_t)BATCH * DIM * SEQ];
__device__ __align__(1024) __half g_Es[(size_t)BATCH * SEQ * SEQ];
// fp32 intermediates:
__device__ __align__(1024) float g_E[(size_t)BATCH * SEQ * SEQ];
__device__ __align__(1024) float g_Fq[(size_t)MS * DIM];
__device__ __align__(1024) float g_Fk[(size_t)MS * DIM];
__device__ __align__(1024) float g_Fv[(size_t)MS * DIM];

// --------------------------- PTX helpers -----------------------------------
__device__ __forceinline__ uint32_t smem_u32(const void* p) {
    uint32_t a;
    asm("{ .reg .u64 t; cvta.to.shared.u64 t, %1; cvt.u32.u64 %0, t; }"
        : "=r"(a) : "l"(p));
    return a;
}
__device__ __forceinline__ void cp_async16(uint32_t dst, const void* src) {
    asm volatile("cp.async.cg.shared.global [%0], [%1], 16;" :: "r"(dst), "l"(src));
}
__device__ __forceinline__ void cp_commit() {
    asm volatile("cp.async.commit_group;" ::: "memory");
}
template <int N> __device__ __forceinline__ void cp_wait() {
    asm volatile("cp.async.wait_group %0;" :: "n"(N) : "memory");
}
__device__ __forceinline__ void ldsm4(uint32_t& r0, uint32_t& r1, uint32_t& r2,
                                      uint32_t& r3, uint32_t a) {
    asm volatile("ldmatrix.sync.aligned.m8n8.x4.shared.b16 {%0,%1,%2,%3}, [%4];"
                 : "=r"(r0), "=r"(r1), "=r"(r2), "=r"(r3) : "r"(a));
}
__device__ __forceinline__ void mma16816(float* d, const uint32_t* a,
                                         uint32_t b0, uint32_t b1) {
    asm volatile(
        "mma.sync.aligned.m16n8k16.row.col.f32.f16.f16.f32 "
        "{%0,%1,%2,%3}, {%4,%5,%6,%7}, {%8,%9}, {%0,%1,%2,%3};"
        : "+f"(d[0]), "+f"(d[1]), "+f"(d[2]), "+f"(d[3])
        : "r"(a[0]), "r"(a[1]), "r"(a[2]), "r"(a[3]), "r"(b0), "r"(b1));
}
__device__ __forceinline__ uint32_t sw128(uint32_t off) {
    return off ^ ((off >> 3) & 0x70);
}

// --------------------------- GEMM core -------------------------------------
// NT: C[m,n] = alpha * (Ahi.Bhi [+ Alo.Bhi if TERMS>=2]) + bias[n]
// TERMS==2: A,B layout [rows, 2*Kp] (hi cols [0,Kp), lo [Kp,2Kp)); B lo unread.
// TERMS==1: A,B compact layout [rows, Kp].
// A,B pre-offset to this CTA's tile rows; C pre-offset to this batch.
template <int TERMS>
__device__ __forceinline__ void gemm_core(
    const __half* __restrict__ A, const __half* __restrict__ B,
    float* __restrict__ C, const float* __restrict__ bias,
    int Kp, int ldC, float alpha, int m0, int n0, char* smem)
{
    constexpr int NTILES = (TERMS >= 2) ? 3 : 2;
    constexpr int STB = NTILES * TILE_BYTES;
    constexpr uint32_t BHI = (TERMS >= 2) ? 2 * TILE_BYTES : TILE_BYTES;

    const int tid  = threadIdx.x;
    const int wid  = tid >> 5;
    const int lane = tid & 31;
    const int wm   = wid & 3;     // 4 warps along M
    const int wn   = wid >> 2;    // 2 warps along N
    const long long lda = (TERMS >= 2) ? 2LL * Kp : (long long)Kp;
    const uint32_t smb = smem_u32(smem);
    const int chunks = Kp / BKE;

    auto issue = [&](int it) {
        const long long khi = (long long)it * BKE;
        const long long klo = (long long)Kp + it * BKE;
        const uint32_t sb = smb + (it % STAGES) * STB;
        #pragma unroll
        for (int i = 0; i < 4; i++) {
            const int id = tid * 4 + i;
            const int r = id >> 3, c = id & 7;
            const uint32_t off = sw128((uint32_t)(r * BKB + c * 16));
            const long long arow = (long long)r * lda;
            cp_async16(sb + off, A + arow + khi + c * 8);
            if (TERMS >= 2)
                cp_async16(sb + TILE_BYTES + off, A + arow + klo + c * 8);
            cp_async16(sb + BHI + off, B + arow + khi + c * 8);
        }
        cp_commit();
    };

    float acc[2][8][4] = {};
    const int aRowBase = wm * 32;
    const int bRowBase = wn * 64;
    const int lrow = lane & 15;
    const int lkc  = lane >> 4;

    const int prol = (chunks < STAGES - 1) ? chunks : (STAGES - 1);
    for (int it = 0; it < prol; it++) issue(it);

    for (int it = 0; it < chunks; it++) {
        cp_wait<STAGES - 2>();
        __syncthreads();
        if (it + STAGES - 1 < chunks) issue(it + STAGES - 1);

        const uint32_t sAhi = smb + (it % STAGES) * STB;
        const uint32_t sAlo = sAhi + TILE_BYTES;
        const uint32_t sBhi = sAhi + BHI;

        #pragma unroll
        for (int ks = 0; ks < 4; ks++) {
            uint32_t ahi[2][4], alo[2][4], bhi[4][4];
            #pragma unroll
            for (int mi = 0; mi < 2; mi++) {
                const int row = aRowBase + mi * 16 + lrow;
                const uint32_t off = sw128((uint32_t)(row * BKB + ks * 32 + lkc * 16));
                ldsm4(ahi[mi][0], ahi[mi][1], ahi[mi][2], ahi[mi][3], sAhi + off);
                if (TERMS >= 2)
                    ldsm4(alo[mi][0], alo[mi][1], alo[mi][2], alo[mi][3], sAlo + off);
            }
            #pragma unroll
            for (int nt = 0; nt < 4; nt++) {
                const int row = bRowBase + nt * 16 + lrow;
                const uint32_t off = sw128((uint32_t)(row * BKB + ks * 32 + lkc * 16));
                ldsm4(bhi[nt][0], bhi[nt][1], bhi[nt][2], bhi[nt][3], sBhi + off);
            }
            #pragma unroll
            for (int mi = 0; mi < 2; mi++)
                #pragma unroll
                for (int nt = 0; nt < 4; nt++) {
                    mma16816(acc[mi][nt * 2],     ahi[mi], bhi[nt][0], bhi[nt][2]);
                    mma16816(acc[mi][nt * 2 + 1], ahi[mi], bhi[nt][1], bhi[nt][3]);
                }
            if (TERMS >= 2) {
                #pragma unroll
                for (int mi = 0; mi < 2; mi++)
                    #pragma unroll
                    for (int nt = 0; nt < 4; nt++) {
                        mma16816(acc[mi][nt * 2],     alo[mi], bhi[nt][0], bhi[nt][2]);
                        mma16816(acc[mi][nt * 2 + 1], alo[mi], bhi[nt][1], bhi[nt][3]);
                    }
            }
        }
    }

    // Epilogue
    #pragma unroll
    for (int mi = 0; mi < 2; mi++) {
        const int r = m0 + wm * 32 + mi * 16 + (lane >> 2);
        #pragma unroll
        for (int nj = 0; nj < 8; nj++) {
            const int cidx = n0 + wn * 64 + nj * 8 + (lane & 3) * 2;
            float b0 = 0.f, b1 = 0.f;
            if (bias) { b0 = bias[cidx]; b1 = bias[cidx + 1]; }
            float2 v0, v1;
            v0.x = acc[mi][nj][0] * alpha + b0;
            v0.y = acc[mi][nj][1] * alpha + b1;
            v1.x = acc[mi][nj][2] * alpha + b0;
            v1.y = acc[mi][nj][3] * alpha + b1;
            *reinterpret_cast<float2*>(C + (long long)r * ldC + cidx) = v0;
            *reinterpret_cast<float2*>(C + (long long)(r + 8) * ldC + cidx) = v1;
        }
    }
}

// Generic (possibly batched) GEMM. 1-term variant allows 2 CTAs/SM.
template <int TERMS>
__global__ __launch_bounds__(256, (TERMS == 1) ? 2 : 1) void gemm_ec(
    const __half* __restrict__ A, const __half* __restrict__ B,
    float* __restrict__ C, const float* __restrict__ bias,
    int Kp, int ldC, int aRowsPerB, int bRowsPerB, long long cPerB, float alpha)
{
    extern __shared__ __align__(1024) char smem[];
    const long long lda = (TERMS >= 2) ? 2LL * Kp : (long long)Kp;
    const __half* Ab = A + ((long long)blockIdx.z * aRowsPerB + (long long)blockIdx.y * BM) * lda;
    const __half* Bb = B + ((long long)blockIdx.z * bRowsPerB + (long long)blockIdx.x * BN) * lda;
    float* Cb = C + (long long)blockIdx.z * cPerB;
    gemm_core<TERMS>(Ab, Bb, Cb, bias, Kp, ldC, alpha,
                     blockIdx.y * BM, blockIdx.x * BN, smem);
}

// Fused Q/K/V projections: one launch, z selects the GEMM (cuts wave tail).
__global__ __launch_bounds__(256, 1) void gemm_qkv(
    const __half* __restrict__ h1s, const __half* __restrict__ h2s,
    const __half* __restrict__ Wq, const __half* __restrict__ Wk,
    const __half* __restrict__ Wv,
    float* __restrict__ Fq, float* __restrict__ Fk, float* __restrict__ Fv,
    const float* __restrict__ bq, const float* __restrict__ bk,
    const float* __restrict__ bv)
{
    extern __shared__ __align__(1024) char smem[];
    const __half* A; const __half* B; float* C; const float* bias;
    if (blockIdx.z == 0)      { A = h1s; B = Wq; C = Fq; bias = bq; }
    else if (blockIdx.z == 1) { A = h2s; B = Wk; C = Fk; bias = bk; }
    else                      { A = h2s; B = Wv; C = Fv; bias = bv; }
    const long long lda = 2LL * DIM;
    A += (long long)blockIdx.y * BM * lda;
    B += (long long)blockIdx.x * BN * lda;
    gemm_core<2>(A, B, C, bias, DIM, DIM, 1.0f,
                 blockIdx.y * BM, blockIdx.x * BN, smem);
}

// --------------------------- elementwise kernels ---------------------------
__global__ void split_kernel(const float* __restrict__ x, __half* __restrict__ y,
                             int K, long long n, int write_lo)
{
    long long i = (long long)blockIdx.x * blockDim.x + threadIdx.x;
    if (i >= n) return;
    long long r = i / K; int c = (int)(i % K);
    float f = x[i];
    __half hi = __float2half(f);
    y[r * (2LL * K) + c] = hi;
    if (write_lo)
        y[r * (2LL * K) + K + c] = __float2half(f - __half2float(hi));
}

// RoPE, hi limb only, compact [MS, DIM] layout.
__global__ void rope_hi_kernel(const float* __restrict__ x, __half* __restrict__ y)
{
    long long idx = (long long)blockIdx.x * blockDim.x + threadIdx.x;
    long long tot = (long long)MS * HALFD;
    if (idx >= tot) return;
    int j = (int)(idx % HALFD);
    long long bs = idx / HALFD;
    int s = (int)(bs % SEQ);

    float invf = powf(10000.0f, -(float)j / (float)HALFD);
    float ang = (float)s * invf;
    float c = cosf(ang), sn = sinf(ang);

    const float* p = x + bs * DIM;
    float x1 = p[j], x2 = p[j + HALFD];
    __half* q = y + bs * DIM;
    q[j]         = __float2half(x1 * c - x2 * sn);
    q[j + HALFD] = __float2half(x2 * c + x1 * sn);
}

// V [B, S(k), D(n)] fp32 -> Vt [B*D rows, SEQ cols] f16 hi-only (transposed)
__global__ void transpose_hi_kernel(const float* __restrict__ V, __half* __restrict__ Vt)
{
    __shared__ float tile[32][33];
    const int b  = blockIdx.z;
    const int n0 = blockIdx.x * 32;
    const int k0 = blockIdx.y * 32;
    const int tx = threadIdx.x, ty = threadIdx.y;   // block (32, 8)
    const float* src = V + (size_t)b * SEQ * DIM;
    #pragma unroll
    for (int i = 0; i < 4; i++)
        tile[ty + 8 * i][tx] = src[(size_t)(k0 + ty + 8 * i) * DIM + n0 + tx];
    __syncthreads();
    __half* dst = Vt + (size_t)b * DIM * SEQ;
    #pragma unroll
    for (int i = 0; i < 4; i++) {
        float f = tile[tx][ty + 8 * i];
        dst[(size_t)(n0 + ty + 8 * i) * SEQ + (k0 + tx)] = __float2half(f);
    }
}

// softmax over rows of E fp32 (len 2048) -> compact f16 hi-only [row, SEQ]
__global__ __launch_bounds__(256) void softmax_hi_kernel(const float* __restrict__ E,
                                                         __half* __restrict__ Es)
{
    const int T = 256, PER = SEQ / T;    // 8
    const float* p = E + (size_t)blockIdx.x * SEQ;
    __half* o = Es + (size_t)blockIdx.x * SEQ;
    const int t = threadIdx.x;

    float v[PER];
    float m = -3.4e38f;
    #pragma unroll
    for (int i = 0; i < PER; i++) { v[i] = p[t + i * T]; m = fmaxf(m, v[i]); }
    #pragma unroll
    for (int off = 16; off; off >>= 1) m = fmaxf(m, __shfl_xor_sync(0xffffffffu, m, off));

    __shared__ float redm[8], reds[8];
    if ((t & 31) == 0) redm[t >> 5] = m;
    __syncthreads();
    float bm = redm[0];
    #pragma unroll
    for (int w = 1; w < 8; w++) bm = fmaxf(bm, redm[w]);

    float s = 0.0f;
    #pragma unroll
    for (int i = 0; i < PER; i++) { v[i] = expf(v[i] - bm); s += v[i]; }
    #pragma unroll
    for (int off = 16; off; off >>= 1) s += __shfl_xor_sync(0xffffffffu, s, off);
    if ((t & 31) == 0) reds[t >> 5] = s;
    __syncthreads();
    float bs = 0.0f;
    #pragma unroll
    for (int w = 0; w < 8; w++) bs += reds[w];

    float inv = 1.0f / bs;
    #pragma unroll
    for (int i = 0; i < PER; i++)
        o[t + i * T] = __float2half(v[i] * inv);
}

// --------------------------- host side -------------------------------------
extern "C" void kernel_launch(void* const* d_in, const int* in_sizes, int n_in,
                              void* d_out, int out_size)
{
    const float* h1 = (const float*)d_in[0];
    const float* h2 = (const float*)d_in[1];
    const float* Wq = (const float*)d_in[2];
    const float* bq = (const float*)d_in[3];
    const float* Wk = (const float*)d_in[4];
    const float* bk = (const float*)d_in[5];
    const float* Wv = (const float*)d_in[6];
    const float* bv = (const float*)d_in[7];
    const float* Wo = (const float*)d_in[8];
    const float* bo = (const float*)d_in[9];
    float* out = (float*)d_out;

    void *h1s, *h2s, *Wqs, *Wks, *Wvs, *Wos, *Qs, *Ks, *Vts, *Es, *Os;
    float *E, *Fq, *Fk, *Fv;
    cudaGetSymbolAddress(&h1s, g_h1s);  cudaGetSymbolAddress(&h2s, g_h2s);
    cudaGetSymbolAddress(&Wqs, g_Wqs);  cudaGetSymbolAddress(&Wks, g_Wks);
    cudaGetSymbolAddress(&Wvs, g_Wvs);  cudaGetSymbolAddress(&Wos, g_Wos);
    cudaGetSymbolAddress(&Qs, g_Qs);    cudaGetSymbolAddress(&Ks, g_Ks);
    cudaGetSymbolAddress(&Vts, g_Vts);  cudaGetSymbolAddress(&Es, g_Es);
    cudaGetSymbolAddress(&Os, g_Os);
    cudaGetSymbolAddress((void**)&E, g_E);
    cudaGetSymbolAddress((void**)&Fq, g_Fq);
    cudaGetSymbolAddress((void**)&Fk, g_Fk);
    cudaGetSymbolAddress((void**)&Fv, g_Fv);

    cudaFuncSetAttribute(gemm_qkv,   cudaFuncAttributeMaxDynamicSharedMemorySize, SMEM_T2);
    cudaFuncSetAttribute(gemm_ec<2>, cudaFuncAttributeMaxDynamicSharedMemorySize, SMEM_T2);
    cudaFuncSetAttribute(gemm_ec<1>, cudaFuncAttributeMaxDynamicSharedMemorySize, SMEM_T1);

    const float scale = 0.044194173824159216f;  // 1/sqrt(512)

    long long nIn = (long long)MS * DIM;
    int blkIn = (int)((nIn + 255) / 256);
    long long nW = (long long)DIM * DIM;
    int blkW = (int)((nW + 255) / 256);

    // Launches 0-4: splits (A-side inputs need lo; weights are B-side, hi only)
    split_kernel<<<blkIn, 256>>>(h1, (__half*)h1s, DIM, nIn, 1);
    split_kernel<<<blkIn, 256>>>(h2, (__half*)h2s, DIM, nIn, 1);
    split_kernel<<<blkW, 256>>>(Wq, (__half*)Wqs, DIM, nW, 0);
    split_kernel<<<blkW, 256>>>(Wk, (__half*)Wks, DIM, nW, 0);
    split_kernel<<<blkW, 256>>>(Wv, (__half*)Wvs, DIM, nW, 0);

    // Launch 5 (ncu -s 5 -c 1 profiles this): fused Q/K/V projections, 2-term
    dim3 gqkv(DIM / BN, MS / BM, 3);
    gemm_qkv<<<gqkv, 256, SMEM_T2>>>((const __half*)h1s, (const __half*)h2s,
                                     (const __half*)Wqs, (const __half*)Wks,
                                     (const __half*)Wvs, Fq, Fk, Fv, bq, bk, bv);

    // RoPE hi-only (compact); transpose V hi-only (compact); split Wo
    {
        long long tot = (long long)MS * HALFD;
        int blk = (int)((tot + 255) / 256);
        rope_hi_kernel<<<blk, 256>>>(Fq, (__half*)Qs);
        rope_hi_kernel<<<blk, 256>>>(Fk, (__half*)Ks);
        dim3 gt(DIM / 32, SEQ / 32, BATCH);
        transpose_hi_kernel<<<gt, dim3(32, 8)>>>(Fv, (__half*)Vts);
        split_kernel<<<blkW, 256>>>(Wo, (__half*)Wos, DIM, nW, 0);
    }

    // scores: E[b] = scale * Qhi[b] Khi[b]^T   (1-term, compact)
    dim3 ge(SEQ / BN, SEQ / BM, BATCH);
    gemm_ec<1><<<ge, 256, SMEM_T1>>>((const __half*)Qs, (const __half*)Ks,
                                     E, nullptr, DIM, SEQ, SEQ, SEQ,
                                     (long long)SEQ * SEQ, scale);

    // softmax -> compact f16 P
    softmax_hi_kernel<<<BATCH * SEQ, 256>>>(E, (__half*)Es);

    // O[b] = P[b] V[b]  (NT vs transposed V, 1-term, compact)
    dim3 gpv(DIM / BN, SEQ / BM, BATCH);
    gemm_ec<1><<<gpv, 256, SMEM_T1>>>((const __half*)Es, (const __half*)Vts,
                                      Fq, nullptr, SEQ, DIM, SEQ, DIM,
                                      (long long)SEQ * DIM, 1.0f);

    // split O (A-side: hi+lo), output projection (2-term)
    split_kernel<<<blkIn, 256>>>(Fq, (__half*)Os, DIM, nIn, 1);
    dim3 gp(DIM / BN, MS / BM, 1);
    gemm_ec<2><<<gp, 256, SMEM_T2>>>((const __half*)Os, (const __half*)Wos,
                                     out, bo, DIM, DIM, 0, 0, 0, 1.0f);
}

// round 9
// speedup vs baseline: 4.7065x; 1.3675x over previous
#include <cuda_runtime.h>
#include <cuda_fp16.h>
#include <stdint.h>
#include <math.h>

// ===========================================================================
// CrossAttention B=8, S=2048, D=512 (single head, fp32 I/O).
// All five GEMMs on mma.sync (HMMA fp16, fp32 accum), 1-term (hi*hi only),
// compact f16 layouts, 2 CTAs/SM. Calibrated error model: ~2e-4 per dropped
// correction term (quadrature) -> predicted rel_err ~7e-4 < 1e-3.
// ===========================================================================

#define BATCH 8
#define SEQ   2048
#define DIM   512
#define MS    (BATCH * SEQ)     // 16384
#define HALFD (DIM / 2)

#define BM 128
#define BN 128
#define BKE 64                          // fp16 elems per k-chunk (128 bytes)
#define BKB 128                         // bytes per smem row
#define STAGES 3
#define TILE_BYTES (BM * BKB)           // 16384
#define SMEM_G (STAGES * 2 * TILE_BYTES)  // 98304 (A|B) -> 2 CTAs/SM

// --------------------------- device scratch -------------------------------
__device__ __align__(1024) __half g_h1s[(size_t)MS * DIM];
__device__ __align__(1024) __half g_h2s[(size_t)MS * DIM];
__device__ __align__(1024) __half g_Wqs[(size_t)DIM * DIM];
__device__ __align__(1024) __half g_Wks[(size_t)DIM * DIM];
__device__ __align__(1024) __half g_Wvs[(size_t)DIM * DIM];
__device__ __align__(1024) __half g_Wos[(size_t)DIM * DIM];
__device__ __align__(1024) __half g_Qs[(size_t)MS * DIM];
__device__ __align__(1024) __half g_Ks[(size_t)MS * DIM];
__device__ __align__(1024) __half g_Vts[(size_t)BATCH * DIM * SEQ];
__device__ __align__(1024) __half g_Es[(size_t)BATCH * SEQ * SEQ];
__device__ __align__(1024) __half g_Os[(size_t)MS * DIM];
__device__ __align__(1024) float g_E[(size_t)BATCH * SEQ * SEQ];
__device__ __align__(1024) float g_Fq[(size_t)MS * DIM];
__device__ __align__(1024) float g_Fk[(size_t)MS * DIM];
__device__ __align__(1024) float g_Fv[(size_t)MS * DIM];

// --------------------------- PTX helpers -----------------------------------
__device__ __forceinline__ uint32_t smem_u32(const void* p) {
    uint32_t a;
    asm("{ .reg .u64 t; cvta.to.shared.u64 t, %1; cvt.u32.u64 %0, t; }"
        : "=r"(a) : "l"(p));
    return a;
}
__device__ __forceinline__ void cp_async16(uint32_t dst, const void* src) {
    asm volatile("cp.async.cg.shared.global [%0], [%1], 16;" :: "r"(dst), "l"(src));
}
__device__ __forceinline__ void cp_commit() {
    asm volatile("cp.async.commit_group;" ::: "memory");
}
template <int N> __device__ __forceinline__ void cp_wait() {
    asm volatile("cp.async.wait_group %0;" :: "n"(N) : "memory");
}
__device__ __forceinline__ void ldsm4(uint32_t& r0, uint32_t& r1, uint32_t& r2,
                                      uint32_t& r3, uint32_t a) {
    asm volatile("ldmatrix.sync.aligned.m8n8.x4.shared.b16 {%0,%1,%2,%3}, [%4];"
                 : "=r"(r0), "=r"(r1), "=r"(r2), "=r"(r3) : "r"(a));
}
__device__ __forceinline__ void mma16816(float* d, const uint32_t* a,
                                         uint32_t b0, uint32_t b1) {
    asm volatile(
        "mma.sync.aligned.m16n8k16.row.col.f32.f16.f16.f32 "
        "{%0,%1,%2,%3}, {%4,%5,%6,%7}, {%8,%9}, {%0,%1,%2,%3};"
        : "+f"(d[0]), "+f"(d[1]), "+f"(d[2]), "+f"(d[3])
        : "r"(a[0]), "r"(a[1]), "r"(a[2]), "r"(a[3]), "r"(b0), "r"(b1));
}
__device__ __forceinline__ uint32_t sw128(uint32_t off) {
    return off ^ ((off >> 3) & 0x70);
}

// --------------------------- GEMM core (1-term) -----------------------------
// NT: C[m,n] = alpha * A[m,:].B[n,:] + bias[n]
// A: [rowsA, Kp] f16 compact; B: [rowsB, Kp] f16 compact.
// OutT = float or __half (PV writes f16 O directly).
template <typename OutT>
__device__ __forceinline__ void gemm_core1(
    const __half* __restrict__ A, const __half* __restrict__ B,
    OutT* __restrict__ C, const float* __restrict__ bias,
    int Kp, int ldC, float alpha, int m0, int n0, char* smem)
{
    const int tid  = threadIdx.x;
    const int wid  = tid >> 5;
    const int lane = tid & 31;
    const int wm   = wid & 3;     // 4 warps along M
    const int wn   = wid >> 2;    // 2 warps along N
    const uint32_t smb = smem_u32(smem);
    const int chunks = Kp / BKE;

    auto issue = [&](int it) {
        const long long k0 = (long long)it * BKE;
        const uint32_t sb = smb + (it % STAGES) * (2 * TILE_BYTES);
        #pragma unroll
        for (int i = 0; i < 4; i++) {
            const int id = tid * 4 + i;
            const int r = id >> 3, c = id & 7;
            const uint32_t off = sw128((uint32_t)(r * BKB + c * 16));
            const long long arow = (long long)r * Kp;
            cp_async16(sb + off, A + arow + k0 + c * 8);
            cp_async16(sb + TILE_BYTES + off, B + arow + k0 + c * 8);
        }
        cp_commit();
    };

    float acc[2][8][4] = {};
    const int aRowBase = wm * 32;
    const int bRowBase = wn * 64;
    const int lrow = lane & 15;
    const int lkc  = lane >> 4;

    const int prol = (chunks < STAGES - 1) ? chunks : (STAGES - 1);
    for (int it = 0; it < prol; it++) issue(it);

    for (int it = 0; it < chunks; it++) {
        cp_wait<STAGES - 2>();
        __syncthreads();
        if (it + STAGES - 1 < chunks) issue(it + STAGES - 1);

        const uint32_t sA = smb + (it % STAGES) * (2 * TILE_BYTES);
        const uint32_t sB = sA + TILE_BYTES;

        #pragma unroll
        for (int ks = 0; ks < 4; ks++) {
            uint32_t a[2][4], b[4][4];
            #pragma unroll
            for (int mi = 0; mi < 2; mi++) {
                const int row = aRowBase + mi * 16 + lrow;
                const uint32_t off = sw128((uint32_t)(row * BKB + ks * 32 + lkc * 16));
                ldsm4(a[mi][0], a[mi][1], a[mi][2], a[mi][3], sA + off);
            }
            #pragma unroll
            for (int nt = 0; nt < 4; nt++) {
                const int row = bRowBase + nt * 16 + lrow;
                const uint32_t off = sw128((uint32_t)(row * BKB + ks * 32 + lkc * 16));
                ldsm4(b[nt][0], b[nt][1], b[nt][2], b[nt][3], sB + off);
            }
            #pragma unroll
            for (int mi = 0; mi < 2; mi++)
                #pragma unroll
                for (int nt = 0; nt < 4; nt++) {
                    mma16816(acc[mi][nt * 2],     a[mi], b[nt][0], b[nt][2]);
                    mma16816(acc[mi][nt * 2 + 1], a[mi], b[nt][1], b[nt][3]);
                }
        }
    }

    // Epilogue
    #pragma unroll
    for (int mi = 0; mi < 2; mi++) {
        const int r = m0 + wm * 32 + mi * 16 + (lane >> 2);
        #pragma unroll
        for (int nj = 0; nj < 8; nj++) {
            const int cidx = n0 + wn * 64 + nj * 8 + (lane & 3) * 2;
            float b0 = 0.f, b1 = 0.f;
            if (bias) { b0 = bias[cidx]; b1 = bias[cidx + 1]; }
            float x0 = acc[mi][nj][0] * alpha + b0;
            float x1 = acc[mi][nj][1] * alpha + b1;
            float x2 = acc[mi][nj][2] * alpha + b0;
            float x3 = acc[mi][nj][3] * alpha + b1;
            if (sizeof(OutT) == 4) {
                float* Cf = (float*)C;
                *reinterpret_cast<float2*>(Cf + (long long)r * ldC + cidx)
                    = make_float2(x0, x1);
                *reinterpret_cast<float2*>(Cf + (long long)(r + 8) * ldC + cidx)
                    = make_float2(x2, x3);
            } else {
                __half* Ch = (__half*)C;
                *reinterpret_cast<__half2*>(Ch + (long long)r * ldC + cidx)
                    = __floats2half2_rn(x0, x1);
                *reinterpret_cast<__half2*>(Ch + (long long)(r + 8) * ldC + cidx)
                    = __floats2half2_rn(x2, x3);
            }
        }
    }
}

// Generic batched 1-term GEMM, 2 CTAs/SM.
template <typename OutT>
__global__ __launch_bounds__(256, 2) void gemm1(
    const __half* __restrict__ A, const __half* __restrict__ B,
    OutT* __restrict__ C, const float* __restrict__ bias,
    int Kp, int ldC, int aRowsPerB, int bRowsPerB, long long cPerB, float alpha)
{
    extern __shared__ __align__(1024) char smem[];
    const __half* Ab = A + ((long long)blockIdx.z * aRowsPerB + (long long)blockIdx.y * BM) * Kp;
    const __half* Bb = B + ((long long)blockIdx.z * bRowsPerB + (long long)blockIdx.x * BN) * Kp;
    OutT* Cb = C + (long long)blockIdx.z * cPerB;
    gemm_core1<OutT>(Ab, Bb, Cb, bias, Kp, ldC, alpha,
                     blockIdx.y * BM, blockIdx.x * BN, smem);
}

// Fused Q/K/V projections: one launch, z selects the GEMM.
__global__ __launch_bounds__(256, 2) void gemm_qkv(
    const __half* __restrict__ h1s, const __half* __restrict__ h2s,
    const __half* __restrict__ Wq, const __half* __restrict__ Wk,
    const __half* __restrict__ Wv,
    float* __restrict__ Fq, float* __restrict__ Fk, float* __restrict__ Fv,
    const float* __restrict__ bq, const float* __restrict__ bk,
    const float* __restrict__ bv)
{
    extern __shared__ __align__(1024) char smem[];
    const __half* A; const __half* B; float* C; const float* bias;
    if (blockIdx.z == 0)      { A = h1s; B = Wq; C = Fq; bias = bq; }
    else if (blockIdx.z == 1) { A = h2s; B = Wk; C = Fk; bias = bk; }
    else                      { A = h2s; B = Wv; C = Fv; bias = bv; }
    A += (long long)blockIdx.y * BM * DIM;
    B += (long long)blockIdx.x * BN * DIM;
    gemm_core1<float>(A, B, C, bias, DIM, DIM, 1.0f,
                      blockIdx.y * BM, blockIdx.x * BN, smem);
}

// --------------------------- elementwise kernels ---------------------------
// fp32 -> f16 compact convert; z picks (a->ya) or (b->yb). 4 elems/thread.
__global__ void convert2_kernel(const float* __restrict__ a, const float* __restrict__ b,
                                __half* __restrict__ ya, __half* __restrict__ yb,
                                long long n4)
{
    long long i = (long long)blockIdx.x * blockDim.x + threadIdx.x;
    if (i >= n4) return;
    const float* src = blockIdx.z ? b : a;
    __half* dst = blockIdx.z ? yb : ya;
    float4 v = reinterpret_cast<const float4*>(src)[i];
    __half2 h0 = __floats2half2_rn(v.x, v.y);
    __half2 h1 = __floats2half2_rn(v.z, v.w);
    reinterpret_cast<__half2*>(dst)[i * 2]     = h0;
    reinterpret_cast<__half2*>(dst)[i * 2 + 1] = h1;
}

// 4 weight tensors in one launch (z picks).
__global__ void convertW_kernel(const float* __restrict__ w0, const float* __restrict__ w1,
                                const float* __restrict__ w2, const float* __restrict__ w3,
                                __half* __restrict__ y0, __half* __restrict__ y1,
                                __half* __restrict__ y2, __half* __restrict__ y3,
                                long long n4)
{
    long long i = (long long)blockIdx.x * blockDim.x + threadIdx.x;
    if (i >= n4) return;
    const float* src; __half* dst;
    switch (blockIdx.z) {
        case 0: src = w0; dst = y0; break;
        case 1: src = w1; dst = y1; break;
        case 2: src = w2; dst = y2; break;
        default: src = w3; dst = y3; break;
    }
    float4 v = reinterpret_cast<const float4*>(src)[i];
    reinterpret_cast<__half2*>(dst)[i * 2]     = __floats2half2_rn(v.x, v.y);
    reinterpret_cast<__half2*>(dst)[i * 2 + 1] = __floats2half2_rn(v.z, v.w);
}

// RoPE hi-only; z picks (Fq->Qs) or (Fk->Ks). Compact [MS, DIM].
__global__ void rope2_kernel(const float* __restrict__ xq, const float* __restrict__ xk,
                             __half* __restrict__ yq, __half* __restrict__ yk)
{
    long long idx = (long long)blockIdx.x * blockDim.x + threadIdx.x;
    long long tot = (long long)MS * HALFD;
    if (idx >= tot) return;
    const float* x = blockIdx.z ? xk : xq;
    __half* y = blockIdx.z ? yk : yq;
    int j = (int)(idx % HALFD);
    long long bs = idx / HALFD;
    int s = (int)(bs % SEQ);

    float invf = powf(10000.0f, -(float)j / (float)HALFD);
    float ang = (float)s * invf;
    float c = cosf(ang), sn = sinf(ang);

    const float* p = x + bs * DIM;
    float x1 = p[j], x2 = p[j + HALFD];
    __half* q = y + bs * DIM;
    q[j]         = __float2half(x1 * c - x2 * sn);
    q[j + HALFD] = __float2half(x2 * c + x1 * sn);
}

// V [B, S(k), D(n)] fp32 -> Vt [B*D rows, SEQ cols] f16 (transposed)
__global__ void transpose_hi_kernel(const float* __restrict__ V, __half* __restrict__ Vt)
{
    __shared__ float tile[32][33];
    const int b  = blockIdx.z;
    const int n0 = blockIdx.x * 32;
    const int k0 = blockIdx.y * 32;
    const int tx = threadIdx.x, ty = threadIdx.y;   // block (32, 8)
    const float* src = V + (size_t)b * SEQ * DIM;
    #pragma unroll
    for (int i = 0; i < 4; i++)
        tile[ty + 8 * i][tx] = src[(size_t)(k0 + ty + 8 * i) * DIM + n0 + tx];
    __syncthreads();
    __half* dst = Vt + (size_t)b * DIM * SEQ;
    #pragma unroll
    for (int i = 0; i < 4; i++) {
        float f = tile[tx][ty + 8 * i];
        dst[(size_t)(n0 + ty + 8 * i) * SEQ + (k0 + tx)] = __float2half(f);
    }
}

// softmax rows of E fp32 (len 2048) -> compact f16 [row, SEQ]
__global__ __launch_bounds__(256) void softmax_hi_kernel(const float* __restrict__ E,
                                                         __half* __restrict__ Es)
{
    const int T = 256, PER = SEQ / T;    // 8
    const float* p = E + (size_t)blockIdx.x * SEQ;
    __half* o = Es + (size_t)blockIdx.x * SEQ;
    const int t = threadIdx.x;

    float v[PER];
    float m = -3.4e38f;
    #pragma unroll
    for (int i = 0; i < PER; i++) { v[i] = p[t + i * T]; m = fmaxf(m, v[i]); }
    #pragma unroll
    for (int off = 16; off; off >>= 1) m = fmaxf(m, __shfl_xor_sync(0xffffffffu, m, off));

    __shared__ float redm[8], reds[8];
    if ((t & 31) == 0) redm[t >> 5] = m;
    __syncthreads();
    float bm = redm[0];
    #pragma unroll
    for (int w = 1; w < 8; w++) bm = fmaxf(bm, redm[w]);

    float s = 0.0f;
    #pragma unroll
    for (int i = 0; i < PER; i++) { v[i] = expf(v[i] - bm); s += v[i]; }
    #pragma unroll
    for (int off = 16; off; off >>= 1) s += __shfl_xor_sync(0xffffffffu, s, off);
    if ((t & 31) == 0) reds[t >> 5] = s;
    __syncthreads();
    float bs = 0.0f;
    #pragma unroll
    for (int w = 0; w < 8; w++) bs += reds[w];

    float inv = 1.0f / bs;
    #pragma unroll
    for (int i = 0; i < PER; i++)
        o[t + i * T] = __float2half(v[i] * inv);
}

// --------------------------- host side -------------------------------------
extern "C" void kernel_launch(void* const* d_in, const int* in_sizes, int n_in,
                              void* d_out, int out_size)
{
    const float* h1 = (const float*)d_in[0];
    const float* h2 = (const float*)d_in[1];
    const float* Wq = (const float*)d_in[2];
    const float* bq = (const float*)d_in[3];
    const float* Wk = (const float*)d_in[4];
    const float* bk = (const float*)d_in[5];
    const float* Wv = (const float*)d_in[6];
    const float* bv = (const float*)d_in[7];
    const float* Wo = (const float*)d_in[8];
    const float* bo = (const float*)d_in[9];
    float* out = (float*)d_out;

    void *h1s, *h2s, *Wqs, *Wks, *Wvs, *Wos, *Qs, *Ks, *Vts, *Es, *Os;
    float *E, *Fq, *Fk, *Fv;
    cudaGetSymbolAddress(&h1s, g_h1s);  cudaGetSymbolAddress(&h2s, g_h2s);
    cudaGetSymbolAddress(&Wqs, g_Wqs);  cudaGetSymbolAddress(&Wks, g_Wks);
    cudaGetSymbolAddress(&Wvs, g_Wvs);  cudaGetSymbolAddress(&Wos, g_Wos);
    cudaGetSymbolAddress(&Qs, g_Qs);    cudaGetSymbolAddress(&Ks, g_Ks);
    cudaGetSymbolAddress(&Vts, g_Vts);  cudaGetSymbolAddress(&Es, g_Es);
    cudaGetSymbolAddress(&Os, g_Os);
    cudaGetSymbolAddress((void**)&E, g_E);
    cudaGetSymbolAddress((void**)&Fq, g_Fq);
    cudaGetSymbolAddress((void**)&Fk, g_Fk);
    cudaGetSymbolAddress((void**)&Fv, g_Fv);

    cudaFuncSetAttribute(gemm_qkv,      cudaFuncAttributeMaxDynamicSharedMemorySize, SMEM_G);
    cudaFuncSetAttribute(gemm1<float>,  cudaFuncAttributeMaxDynamicSharedMemorySize, SMEM_G);
    cudaFuncSetAttribute(gemm1<__half>, cudaFuncAttributeMaxDynamicSharedMemorySize, SMEM_G);

    const float scale = 0.044194173824159216f;  // 1/sqrt(512)

    // 0: convert h1, h2 -> f16 compact (z picks tensor)
    {
        long long n4 = (long long)MS * DIM / 4;
        dim3 g((unsigned)((n4 + 255) / 256), 1, 2);
        convert2_kernel<<<g, 256>>>(h1, h2, (__half*)h1s, (__half*)h2s, n4);
    }
    // 1: convert all 4 weights
    {
        long long n4 = (long long)DIM * DIM / 4;
        dim3 g((unsigned)((n4 + 255) / 256), 1, 4);
        convertW_kernel<<<g, 256>>>(Wq, Wk, Wv, Wo,
                                    (__half*)Wqs, (__half*)Wks, (__half*)Wvs, (__half*)Wos, n4);
    }
    // 2: fused Q/K/V projections (1-term)
    dim3 gqkv(DIM / BN, MS / BM, 3);
    gemm_qkv<<<gqkv, 256, SMEM_G>>>((const __half*)h1s, (const __half*)h2s,
                                    (const __half*)Wqs, (const __half*)Wks,
                                    (const __half*)Wvs, Fq, Fk, Fv, bq, bk, bv);
    // 3: RoPE Q and K (z picks)
    {
        long long tot = (long long)MS * HALFD;
        dim3 g((unsigned)((tot + 255) / 256), 1, 2);
        rope2_kernel<<<g, 256>>>(Fq, Fk, (__half*)Qs, (__half*)Ks);
    }
    // 4: transpose V
    {
        dim3 gt(DIM / 32, SEQ / 32, BATCH);
        transpose_hi_kernel<<<gt, dim3(32, 8)>>>(Fv, (__half*)Vts);
    }
    // 5 (ncu profiles this): scores E[b] = scale * Q[b] K[b]^T
    dim3 ge(SEQ / BN, SEQ / BM, BATCH);
    gemm1<float><<<ge, 256, SMEM_G>>>((const __half*)Qs, (const __half*)Ks,
                                      E, nullptr, DIM, SEQ, SEQ, SEQ,
                                      (long long)SEQ * SEQ, scale);
    // 6: softmax -> compact f16 P
    softmax_hi_kernel<<<BATCH * SEQ, 256>>>(E, (__half*)Es);
    // 7: O[b] = P[b] V[b], writes f16 O directly
    dim3 gpv(DIM / BN, SEQ / BM, BATCH);
    gemm1<__half><<<gpv, 256, SMEM_G>>>((const __half*)Es, (const __half*)Vts,
                                        (__half*)Os, nullptr, SEQ, DIM, SEQ, DIM,
                                        (long long)SEQ * DIM, 1.0f);
    // 8: output projection
    dim3 gp(DIM / BN, MS / BM, 1);
    gemm1<float><<<gp, 256, SMEM_G>>>((const __half*)Os, (const __half*)Wos,
                                      out, bo, DIM, DIM, 0, 0, 0, 1.0f);
}

// round 10
// speedup vs baseline: 4.9234x; 1.0461x over previous
#include <cuda_runtime.h>
#include <cuda_fp16.h>
#include <stdint.h>
#include <math.h>

// ===========================================================================
// CrossAttention B=8, S=2048, D=512 (single head, fp32 I/O).
// All five GEMMs on mma.sync (HMMA fp16, fp32 accum), 1-term, compact f16,
// 2 CTAs/SM. f16 intermediates end-to-end (E in f16: softmax perturbation
// averages out). rope uses exp2f+sincosf instead of powf.
// ===========================================================================

#define BATCH 8
#define SEQ   2048
#define DIM   512
#define MS    (BATCH * SEQ)     // 16384
#define HALFD (DIM / 2)

#define BM 128
#define BN 128
#define BKE 64                          // fp16 elems per k-chunk (128 bytes)
#define BKB 128                         // bytes per smem row
#define STAGES 3
#define TILE_BYTES (BM * BKB)           // 16384
#define SMEM_G (STAGES * 2 * TILE_BYTES)  // 98304 (A|B) -> 2 CTAs/SM

// --------------------------- device scratch -------------------------------
__device__ __align__(1024) __half g_h1s[(size_t)MS * DIM];
__device__ __align__(1024) __half g_h2s[(size_t)MS * DIM];
__device__ __align__(1024) __half g_Wqs[(size_t)DIM * DIM];
__device__ __align__(1024) __half g_Wks[(size_t)DIM * DIM];
__device__ __align__(1024) __half g_Wvs[(size_t)DIM * DIM];
__device__ __align__(1024) __half g_Wos[(size_t)DIM * DIM];
__device__ __align__(1024) __half g_Fq16[(size_t)MS * DIM];
__device__ __align__(1024) __half g_Fk16[(size_t)MS * DIM];
__device__ __align__(1024) __half g_Fv16[(size_t)MS * DIM];
__device__ __align__(1024) __half g_Qs[(size_t)MS * DIM];
__device__ __align__(1024) __half g_Ks[(size_t)MS * DIM];
__device__ __align__(1024) __half g_Vts[(size_t)BATCH * DIM * SEQ];
__device__ __align__(1024) __half g_E16[(size_t)BATCH * SEQ * SEQ];
__device__ __align__(1024) __half g_Es[(size_t)BATCH * SEQ * SEQ];
__device__ __align__(1024) __half g_Os[(size_t)MS * DIM];

// --------------------------- PTX helpers -----------------------------------
__device__ __forceinline__ uint32_t smem_u32(const void* p) {
    uint32_t a;
    asm("{ .reg .u64 t; cvta.to.shared.u64 t, %1; cvt.u32.u64 %0, t; }"
        : "=r"(a) : "l"(p));
    return a;
}
__device__ __forceinline__ void cp_async16(uint32_t dst, const void* src) {
    asm volatile("cp.async.cg.shared.global [%0], [%1], 16;" :: "r"(dst), "l"(src));
}
__device__ __forceinline__ void cp_commit() {
    asm volatile("cp.async.commit_group;" ::: "memory");
}
template <int N> __device__ __forceinline__ void cp_wait() {
    asm volatile("cp.async.wait_group %0;" :: "n"(N) : "memory");
}
__device__ __forceinline__ void ldsm4(uint32_t& r0, uint32_t& r1, uint32_t& r2,
                                      uint32_t& r3, uint32_t a) {
    asm volatile("ldmatrix.sync.aligned.m8n8.x4.shared.b16 {%0,%1,%2,%3}, [%4];"
                 : "=r"(r0), "=r"(r1), "=r"(r2), "=r"(r3) : "r"(a));
}
__device__ __forceinline__ void mma16816(float* d, const uint32_t* a,
                                         uint32_t b0, uint32_t b1) {
    asm volatile(
        "mma.sync.aligned.m16n8k16.row.col.f32.f16.f16.f32 "
        "{%0,%1,%2,%3}, {%4,%5,%6,%7}, {%8,%9}, {%0,%1,%2,%3};"
        : "+f"(d[0]), "+f"(d[1]), "+f"(d[2]), "+f"(d[3])
        : "r"(a[0]), "r"(a[1]), "r"(a[2]), "r"(a[3]), "r"(b0), "r"(b1));
}
__device__ __forceinline__ uint32_t sw128(uint32_t off) {
    return off ^ ((off >> 3) & 0x70);
}

// --------------------------- GEMM core (1-term) -----------------------------
// NT: C[m,n] = alpha * A[m,:].B[n,:] + bias[n]
// A: [rowsA, Kp] f16 compact; B: [rowsB, Kp] f16 compact.
template <typename OutT>
__device__ __forceinline__ void gemm_core1(
    const __half* __restrict__ A, const __half* __restrict__ B,
    OutT* __restrict__ C, const float* __restrict__ bias,
    int Kp, int ldC, float alpha, int m0, int n0, char* smem)
{
    const int tid  = threadIdx.x;
    const int wid  = tid >> 5;
    const int lane = tid & 31;
    const int wm   = wid & 3;     // 4 warps along M
    const int wn   = wid >> 2;    // 2 warps along N
    const uint32_t smb = smem_u32(smem);
    const int chunks = Kp / BKE;

    auto issue = [&](int it) {
        const long long k0 = (long long)it * BKE;
        const uint32_t sb = smb + (it % STAGES) * (2 * TILE_BYTES);
        #pragma unroll
        for (int i = 0; i < 4; i++) {
            const int id = tid * 4 + i;
            const int r = id >> 3, c = id & 7;
            const uint32_t off = sw128((uint32_t)(r * BKB + c * 16));
            const long long arow = (long long)r * Kp;
            cp_async16(sb + off, A + arow + k0 + c * 8);
            cp_async16(sb + TILE_BYTES + off, B + arow + k0 + c * 8);
        }
        cp_commit();
    };

    float acc[2][8][4] = {};
    const int aRowBase = wm * 32;
    const int bRowBase = wn * 64;
    const int lrow = lane & 15;
    const int lkc  = lane >> 4;

    const int prol = (chunks < STAGES - 1) ? chunks : (STAGES - 1);
    for (int it = 0; it < prol; it++) issue(it);

    for (int it = 0; it < chunks; it++) {
        cp_wait<STAGES - 2>();
        __syncthreads();
        if (it + STAGES - 1 < chunks) issue(it + STAGES - 1);

        const uint32_t sA = smb + (it % STAGES) * (2 * TILE_BYTES);
        const uint32_t sB = sA + TILE_BYTES;

        #pragma unroll
        for (int ks = 0; ks < 4; ks++) {
            uint32_t a[2][4], b[4][4];
            #pragma unroll
            for (int mi = 0; mi < 2; mi++) {
                const int row = aRowBase + mi * 16 + lrow;
                const uint32_t off = sw128((uint32_t)(row * BKB + ks * 32 + lkc * 16));
                ldsm4(a[mi][0], a[mi][1], a[mi][2], a[mi][3], sA + off);
            }
            #pragma unroll
            for (int nt = 0; nt < 4; nt++) {
                const int row = bRowBase + nt * 16 + lrow;
                const uint32_t off = sw128((uint32_t)(row * BKB + ks * 32 + lkc * 16));
                ldsm4(b[nt][0], b[nt][1], b[nt][2], b[nt][3], sB + off);
            }
            #pragma unroll
            for (int mi = 0; mi < 2; mi++)
                #pragma unroll
                for (int nt = 0; nt < 4; nt++) {
                    mma16816(acc[mi][nt * 2],     a[mi], b[nt][0], b[nt][2]);
                    mma16816(acc[mi][nt * 2 + 1], a[mi], b[nt][1], b[nt][3]);
                }
        }
    }

    // Epilogue
    #pragma unroll
    for (int mi = 0; mi < 2; mi++) {
        const int r = m0 + wm * 32 + mi * 16 + (lane >> 2);
        #pragma unroll
        for (int nj = 0; nj < 8; nj++) {
            const int cidx = n0 + wn * 64 + nj * 8 + (lane & 3) * 2;
            float b0 = 0.f, b1 = 0.f;
            if (bias) { b0 = bias[cidx]; b1 = bias[cidx + 1]; }
            float x0 = acc[mi][nj][0] * alpha + b0;
            float x1 = acc[mi][nj][1] * alpha + b1;
            float x2 = acc[mi][nj][2] * alpha + b0;
            float x3 = acc[mi][nj][3] * alpha + b1;
            if (sizeof(OutT) == 4) {
                float* Cf = (float*)C;
                *reinterpret_cast<float2*>(Cf + (long long)r * ldC + cidx)
                    = make_float2(x0, x1);
                *reinterpret_cast<float2*>(Cf + (long long)(r + 8) * ldC + cidx)
                    = make_float2(x2, x3);
            } else {
                __half* Ch = (__half*)C;
                *reinterpret_cast<__half2*>(Ch + (long long)r * ldC + cidx)
                    = __floats2half2_rn(x0, x1);
                *reinterpret_cast<__half2*>(Ch + (long long)(r + 8) * ldC + cidx)
                    = __floats2half2_rn(x2, x3);
            }
        }
    }
}

// Generic batched 1-term GEMM, 2 CTAs/SM.
template <typename OutT>
__global__ __launch_bounds__(256, 2) void gemm1(
    const __half* __restrict__ A, const __half* __restrict__ B,
    OutT* __restrict__ C, const float* __restrict__ bias,
    int Kp, int ldC, int aRowsPerB, int bRowsPerB, long long cPerB, float alpha)
{
    extern __shared__ __align__(1024) char smem[];
    const __half* Ab = A + ((long long)blockIdx.z * aRowsPerB + (long long)blockIdx.y * BM) * Kp;
    const __half* Bb = B + ((long long)blockIdx.z * bRowsPerB + (long long)blockIdx.x * BN) * Kp;
    OutT* Cb = C + (long long)blockIdx.z * cPerB;
    gemm_core1<OutT>(Ab, Bb, Cb, bias, Kp, ldC, alpha,
                     blockIdx.y * BM, blockIdx.x * BN, smem);
}

// Fused Q/K/V projections: one launch, z selects; writes f16 outputs.
__global__ __launch_bounds__(256, 2) void gemm_qkv(
    const __half* __restrict__ h1s, const __half* __restrict__ h2s,
    const __half* __restrict__ Wq, const __half* __restrict__ Wk,
    const __half* __restrict__ Wv,
    __half* __restrict__ Fq, __half* __restrict__ Fk, __half* __restrict__ Fv,
    const float* __restrict__ bq, const float* __restrict__ bk,
    const float* __restrict__ bv)
{
    extern __shared__ __align__(1024) char smem[];
    const __half* A; const __half* B; __half* C; const float* bias;
    if (blockIdx.z == 0)      { A = h1s; B = Wq; C = Fq; bias = bq; }
    else if (blockIdx.z == 1) { A = h2s; B = Wk; C = Fk; bias = bk; }
    else                      { A = h2s; B = Wv; C = Fv; bias = bv; }
    A += (long long)blockIdx.y * BM * DIM;
    B += (long long)blockIdx.x * BN * DIM;
    gemm_core1<__half>(A, B, C, bias, DIM, DIM, 1.0f,
                       blockIdx.y * BM, blockIdx.x * BN, smem);
}

// --------------------------- elementwise kernels ---------------------------
// fp32 -> f16 compact convert; z picks (a->ya) or (b->yb). 4 elems/thread.
__global__ void convert2_kernel(const float* __restrict__ a, const float* __restrict__ b,
                                __half* __restrict__ ya, __half* __restrict__ yb,
                                long long n4)
{
    long long i = (long long)blockIdx.x * blockDim.x + threadIdx.x;
    if (i >= n4) return;
    const float* src = blockIdx.z ? b : a;
    __half* dst = blockIdx.z ? yb : ya;
    float4 v = reinterpret_cast<const float4*>(src)[i];
    reinterpret_cast<__half2*>(dst)[i * 2]     = __floats2half2_rn(v.x, v.y);
    reinterpret_cast<__half2*>(dst)[i * 2 + 1] = __floats2half2_rn(v.z, v.w);
}

// 4 weight tensors in one launch (z picks).
__global__ void convertW_kernel(const float* __restrict__ w0, const float* __restrict__ w1,
                                const float* __restrict__ w2, const float* __restrict__ w3,
                                __half* __restrict__ y0, __half* __restrict__ y1,
                                __half* __restrict__ y2, __half* __restrict__ y3,
                                long long n4)
{
    long long i = (long long)blockIdx.x * blockDim.x + threadIdx.x;
    if (i >= n4) return;
    const float* src; __half* dst;
    switch (blockIdx.z) {
        case 0: src = w0; dst = y0; break;
        case 1: src = w1; dst = y1; break;
        case 2: src = w2; dst = y2; break;
        default: src = w3; dst = y3; break;
    }
    float4 v = reinterpret_cast<const float4*>(src)[i];
    reinterpret_cast<__half2*>(dst)[i * 2]     = __floats2half2_rn(v.x, v.y);
    reinterpret_cast<__half2*>(dst)[i * 2 + 1] = __floats2half2_rn(v.z, v.w);
}

// RoPE hi-only, f16 in/out; z picks (Fq->Qs) or (Fk->Ks).
// invf = 10000^(-j/256) computed as exp2f(j * -log2(10000)/256) (one MUFU).
__global__ void rope2_kernel(const __half* __restrict__ xq, const __half* __restrict__ xk,
                             __half* __restrict__ yq, __half* __restrict__ yk)
{
    long long idx = (long long)blockIdx.x * blockDim.x + threadIdx.x;
    long long tot = (long long)MS * HALFD;
    if (idx >= tot) return;
    const __half* x = blockIdx.z ? xk : xq;
    __half* y = blockIdx.z ? yk : yq;
    int j = (int)(idx % HALFD);
    long long bs = idx / HALFD;
    int s = (int)(bs % SEQ);

    const float kNegLog2Base = -13.287712379549449f / 256.0f;  // -log2(10000)/256
    float invf = exp2f((float)j * kNegLog2Base);
    float ang = (float)s * invf;
    float sn, c;
    sincosf(ang, &sn, &c);

    const __half* p = x + bs * DIM;
    float x1 = __half2float(p[j]);
    float x2 = __half2float(p[j + HALFD]);
    __half* q = y + bs * DIM;
    q[j]         = __float2half(x1 * c - x2 * sn);
    q[j + HALFD] = __float2half(x2 * c + x1 * sn);
}

// V f16 [B, S(k), D(n)] -> Vt f16 [B*D rows, SEQ cols] (transposed)
__global__ void transpose_hi_kernel(const __half* __restrict__ V, __half* __restrict__ Vt)
{
    __shared__ float tile[32][33];
    const int b  = blockIdx.z;
    const int n0 = blockIdx.x * 32;
    const int k0 = blockIdx.y * 32;
    const int tx = threadIdx.x, ty = threadIdx.y;   // block (32, 8)
    const __half* src = V + (size_t)b * SEQ * DIM;
    #pragma unroll
    for (int i = 0; i < 4; i++)
        tile[ty + 8 * i][tx] = __half2float(src[(size_t)(k0 + ty + 8 * i) * DIM + n0 + tx]);
    __syncthreads();
    __half* dst = Vt + (size_t)b * DIM * SEQ;
    #pragma unroll
    for (int i = 0; i < 4; i++)
        dst[(size_t)(n0 + ty + 8 * i) * SEQ + (k0 + tx)] = __float2half(tile[tx][ty + 8 * i]);
}

// softmax rows of E f16 (len 2048) -> f16 P, vectorized 8 halves/thread.
__global__ __launch_bounds__(256) void softmax_h_kernel(const __half* __restrict__ E,
                                                        __half* __restrict__ Es)
{
    const int t = threadIdx.x;
    const uint2* pin = reinterpret_cast<const uint2*>(E + (size_t)blockIdx.x * SEQ);
    uint2* pout = reinterpret_cast<uint2*>(Es + (size_t)blockIdx.x * SEQ);

    // load 8 halves (two uint2 at t and t+256; 512 uint2 per row)
    uint2 u0 = pin[t];
    uint2 u1 = pin[t + 256];
    float v[8];
    {
        float2 f;
        f = __half22float2(*reinterpret_cast<__half2*>(&u0.x)); v[0] = f.x; v[1] = f.y;
        f = __half22float2(*reinterpret_cast<__half2*>(&u0.y)); v[2] = f.x; v[3] = f.y;
        f = __half22float2(*reinterpret_cast<__half2*>(&u1.x)); v[4] = f.x; v[5] = f.y;
        f = __half22float2(*reinterpret_cast<__half2*>(&u1.y)); v[6] = f.x; v[7] = f.y;
    }

    float m = v[0];
    #pragma unroll
    for (int i = 1; i < 8; i++) m = fmaxf(m, v[i]);
    #pragma unroll
    for (int off = 16; off; off >>= 1) m = fmaxf(m, __shfl_xor_sync(0xffffffffu, m, off));

    __shared__ float redm[8], reds[8];
    if ((t & 31) == 0) redm[t >> 5] = m;
    __syncthreads();
    float bm = redm[0];
    #pragma unroll
    for (int w = 1; w < 8; w++) bm = fmaxf(bm, redm[w]);

    float s = 0.0f;
    #pragma unroll
    for (int i = 0; i < 8; i++) { v[i] = __expf(v[i] - bm); s += v[i]; }
    #pragma unroll
    for (int off = 16; off; off >>= 1) s += __shfl_xor_sync(0xffffffffu, s, off);
    if ((t & 31) == 0) reds[t >> 5] = s;
    __syncthreads();
    float bs = 0.0f;
    #pragma unroll
    for (int w = 0; w < 8; w++) bs += reds[w];

    float inv = 1.0f / bs;
    uint2 o0, o1;
    __half2 h;
    h = __floats2half2_rn(v[0] * inv, v[1] * inv); o0.x = *reinterpret_cast<uint32_t*>(&h);
    h = __floats2half2_rn(v[2] * inv, v[3] * inv); o0.y = *reinterpret_cast<uint32_t*>(&h);
    h = __floats2half2_rn(v[4] * inv, v[5] * inv); o1.x = *reinterpret_cast<uint32_t*>(&h);
    h = __floats2half2_rn(v[6] * inv, v[7] * inv); o1.y = *reinterpret_cast<uint32_t*>(&h);
    pout[t]       = o0;
    pout[t + 256] = o1;
}

// --------------------------- host side -------------------------------------
extern "C" void kernel_launch(void* const* d_in, const int* in_sizes, int n_in,
                              void* d_out, int out_size)
{
    const float* h1 = (const float*)d_in[0];
    const float* h2 = (const float*)d_in[1];
    const float* Wq = (const float*)d_in[2];
    const float* bq = (const float*)d_in[3];
    const float* Wk = (const float*)d_in[4];
    const float* bk = (const float*)d_in[5];
    const float* Wv = (const float*)d_in[6];
    const float* bv = (const float*)d_in[7];
    const float* Wo = (const float*)d_in[8];
    const float* bo = (const float*)d_in[9];
    float* out = (float*)d_out;

    void *h1s, *h2s, *Wqs, *Wks, *Wvs, *Wos, *Fq, *Fk, *Fv;
    void *Qs, *Ks, *Vts, *E16, *Es, *Os;
    cudaGetSymbolAddress(&h1s, g_h1s);  cudaGetSymbolAddress(&h2s, g_h2s);
    cudaGetSymbolAddress(&Wqs, g_Wqs);  cudaGetSymbolAddress(&Wks, g_Wks);
    cudaGetSymbolAddress(&Wvs, g_Wvs);  cudaGetSymbolAddress(&Wos, g_Wos);
    cudaGetSymbolAddress(&Fq, g_Fq16);  cudaGetSymbolAddress(&Fk, g_Fk16);
    cudaGetSymbolAddress(&Fv, g_Fv16);
    cudaGetSymbolAddress(&Qs, g_Qs);    cudaGetSymbolAddress(&Ks, g_Ks);
    cudaGetSymbolAddress(&Vts, g_Vts);  cudaGetSymbolAddress(&E16, g_E16);
    cudaGetSymbolAddress(&Es, g_Es);    cudaGetSymbolAddress(&Os, g_Os);

    cudaFuncSetAttribute(gemm_qkv,      cudaFuncAttributeMaxDynamicSharedMemorySize, SMEM_G);
    cudaFuncSetAttribute(gemm1<float>,  cudaFuncAttributeMaxDynamicSharedMemorySize, SMEM_G);
    cudaFuncSetAttribute(gemm1<__half>, cudaFuncAttributeMaxDynamicSharedMemorySize, SMEM_G);

    const float scale = 0.044194173824159216f;  // 1/sqrt(512)

    // 0: convert h1, h2 -> f16 compact
    {
        long long n4 = (long long)MS * DIM / 4;
        dim3 g((unsigned)((n4 + 255) / 256), 1, 2);
        convert2_kernel<<<g, 256>>>(h1, h2, (__half*)h1s, (__half*)h2s, n4);
    }
    // 1: convert all 4 weights
    {
        long long n4 = (long long)DIM * DIM / 4;
        dim3 g((unsigned)((n4 + 255) / 256), 1, 4);
        convertW_kernel<<<g, 256>>>(Wq, Wk, Wv, Wo,
                                    (__half*)Wqs, (__half*)Wks, (__half*)Wvs, (__half*)Wos, n4);
    }
    // 2: fused Q/K/V projections, f16 outputs
    dim3 gqkv(DIM / BN, MS / BM, 3);
    gemm_qkv<<<gqkv, 256, SMEM_G>>>((const __half*)h1s, (const __half*)h2s,
                                    (const __half*)Wqs, (const __half*)Wks,
                                    (const __half*)Wvs,
                                    (__half*)Fq, (__half*)Fk, (__half*)Fv, bq, bk, bv);
    // 3: RoPE Q and K (f16 in/out, z picks)
    {
        long long tot = (long long)MS * HALFD;
        dim3 g((unsigned)((tot + 255) / 256), 1, 2);
        rope2_kernel<<<g, 256>>>((const __half*)Fq, (const __half*)Fk,
                                 (__half*)Qs, (__half*)Ks);
    }
    // 4: transpose V (f16 in)
    {
        dim3 gt(DIM / 32, SEQ / 32, BATCH);
        transpose_hi_kernel<<<gt, dim3(32, 8)>>>((const __half*)Fv, (__half*)Vts);
    }
    // 5 (ncu profiles this): scores E16[b] = scale * Q[b] K[b]^T  (f16 out)
    dim3 ge(SEQ / BN, SEQ / BM, BATCH);
    gemm1<__half><<<ge, 256, SMEM_G>>>((const __half*)Qs, (const __half*)Ks,
                                       (__half*)E16, nullptr, DIM, SEQ, SEQ, SEQ,
                                       (long long)SEQ * SEQ, scale);
    // 6: softmax (f16 -> f16)
    softmax_h_kernel<<<BATCH * SEQ, 256>>>((const __half*)E16, (__half*)Es);
    // 7: O[b] = P[b] V[b], f16 out
    dim3 gpv(DIM / BN, SEQ / BM, BATCH);
    gemm1<__half><<<gpv, 256, SMEM_G>>>((const __half*)Es, (const __half*)Vts,
                                        (__half*)Os, nullptr, SEQ, DIM, SEQ, DIM,
                                        (long long)SEQ * DIM, 1.0f);
    // 8: output projection (fp32 out)
    dim3 gp(DIM / BN, MS / BM, 1);
    gemm1<float><<<gp, 256, SMEM_G>>>((const __half*)Os, (const __half*)Wos,
                                      out, bo, DIM, DIM, 0, 0, 0, 1.0f);
}

// round 11
// speedup vs baseline: 5.0190x; 1.0194x over previous
#include <cuda_runtime.h>
#include <cuda_fp16.h>
#include <stdint.h>
#include <math.h>

// ===========================================================================
// CrossAttention B=8, S=2048, D=512 (single head, fp32 I/O).
// All GEMMs on mma.sync (HMMA fp16, fp32 accum), 1-term, compact f16,
// 2 CTAs/SM. Algebraic fusion: W' = Wo@Wv (fp32, exact), V' = h2@W'^T + Wo@bv,
// out = P@V' + bo  -- the separate output projection GEMM is eliminated.
// ===========================================================================

#define BATCH 8
#define SEQ   2048
#define DIM   512
#define MS    (BATCH * SEQ)     // 16384
#define HALFD (DIM / 2)

#define BM 128
#define BN 128
#define BKE 64                          // fp16 elems per k-chunk (128 bytes)
#define BKB 128                         // bytes per smem row
#define STAGES 3
#define TILE_BYTES (BM * BKB)           // 16384
#define SMEM_G (STAGES * 2 * TILE_BYTES)  // 98304 (A|B) -> 2 CTAs/SM

// --------------------------- device scratch -------------------------------
__device__ __align__(1024) __half g_h1s[(size_t)MS * DIM];
__device__ __align__(1024) __half g_h2s[(size_t)MS * DIM];
__device__ __align__(1024) __half g_Wqs[(size_t)DIM * DIM];
__device__ __align__(1024) __half g_Wks[(size_t)DIM * DIM];
__device__ __align__(1024) __half g_Wps[(size_t)DIM * DIM];   // W' = Wo@Wv, f16
__device__ __align__(1024) float  g_cb[DIM];                  // Wo@bv
__device__ __align__(1024) __half g_Fq16[(size_t)MS * DIM];
__device__ __align__(1024) __half g_Fk16[(size_t)MS * DIM];
__device__ __align__(1024) __half g_Fv16[(size_t)MS * DIM];   // V'
__device__ __align__(1024) __half g_Qs[(size_t)MS * DIM];
__device__ __align__(1024) __half g_Ks[(size_t)MS * DIM];
__device__ __align__(1024) __half g_Vts[(size_t)BATCH * DIM * SEQ];
__device__ __align__(1024) __half g_E16[(size_t)BATCH * SEQ * SEQ];
__device__ __align__(1024) __half g_Es[(size_t)BATCH * SEQ * SEQ];

// --------------------------- PTX helpers -----------------------------------
__device__ __forceinline__ uint32_t smem_u32(const void* p) {
    uint32_t a;
    asm("{ .reg .u64 t; cvta.to.shared.u64 t, %1; cvt.u32.u64 %0, t; }"
        : "=r"(a) : "l"(p));
    return a;
}
__device__ __forceinline__ void cp_async16(uint32_t dst, const void* src) {
    asm volatile("cp.async.cg.shared.global [%0], [%1], 16;" :: "r"(dst), "l"(src));
}
__device__ __forceinline__ void cp_commit() {
    asm volatile("cp.async.commit_group;" ::: "memory");
}
template <int N> __device__ __forceinline__ void cp_wait() {
    asm volatile("cp.async.wait_group %0;" :: "n"(N) : "memory");
}
__device__ __forceinline__ void ldsm4(uint32_t& r0, uint32_t& r1, uint32_t& r2,
                                      uint32_t& r3, uint32_t a) {
    asm volatile("ldmatrix.sync.aligned.m8n8.x4.shared.b16 {%0,%1,%2,%3}, [%4];"
                 : "=r"(r0), "=r"(r1), "=r"(r2), "=r"(r3) : "r"(a));
}
__device__ __forceinline__ void mma16816(float* d, const uint32_t* a,
                                         uint32_t b0, uint32_t b1) {
    asm volatile(
        "mma.sync.aligned.m16n8k16.row.col.f32.f16.f16.f32 "
        "{%0,%1,%2,%3}, {%4,%5,%6,%7}, {%8,%9}, {%0,%1,%2,%3};"
        : "+f"(d[0]), "+f"(d[1]), "+f"(d[2]), "+f"(d[3])
        : "r"(a[0]), "r"(a[1]), "r"(a[2]), "r"(a[3]), "r"(b0), "r"(b1));
}
__device__ __forceinline__ uint32_t sw128(uint32_t off) {
    return off ^ ((off >> 3) & 0x70);
}

// --------------------------- GEMM core (1-term) -----------------------------
// NT: C[m,n] = alpha * A[m,:].B[n,:] + bias[n]
template <typename OutT>
__device__ __forceinline__ void gemm_core1(
    const __half* __restrict__ A, const __half* __restrict__ B,
    OutT* __restrict__ C, const float* __restrict__ bias,
    int Kp, int ldC, float alpha, int m0, int n0, char* smem)
{
    const int tid  = threadIdx.x;
    const int wid  = tid >> 5;
    const int lane = tid & 31;
    const int wm   = wid & 3;
    const int wn   = wid >> 2;
    const uint32_t smb = smem_u32(smem);
    const int chunks = Kp / BKE;

    auto issue = [&](int it) {
        const long long k0 = (long long)it * BKE;
        const uint32_t sb = smb + (it % STAGES) * (2 * TILE_BYTES);
        #pragma unroll
        for (int i = 0; i < 4; i++) {
            const int id = tid * 4 + i;
            const int r = id >> 3, c = id & 7;
            const uint32_t off = sw128((uint32_t)(r * BKB + c * 16));
            const long long arow = (long long)r * Kp;
            cp_async16(sb + off, A + arow + k0 + c * 8);
            cp_async16(sb + TILE_BYTES + off, B + arow + k0 + c * 8);
        }
        cp_commit();
    };

    float acc[2][8][4] = {};
    const int aRowBase = wm * 32;
    const int bRowBase = wn * 64;
    const int lrow = lane & 15;
    const int lkc  = lane >> 4;

    const int prol = (chunks < STAGES - 1) ? chunks : (STAGES - 1);
    for (int it = 0; it < prol; it++) issue(it);

    for (int it = 0; it < chunks; it++) {
        cp_wait<STAGES - 2>();
        __syncthreads();
        if (it + STAGES - 1 < chunks) issue(it + STAGES - 1);

        const uint32_t sA = smb + (it % STAGES) * (2 * TILE_BYTES);
        const uint32_t sB = sA + TILE_BYTES;

        #pragma unroll
        for (int ks = 0; ks < 4; ks++) {
            uint32_t a[2][4], b[4][4];
            #pragma unroll
            for (int mi = 0; mi < 2; mi++) {
                const int row = aRowBase + mi * 16 + lrow;
                const uint32_t off = sw128((uint32_t)(row * BKB + ks * 32 + lkc * 16));
                ldsm4(a[mi][0], a[mi][1], a[mi][2], a[mi][3], sA + off);
            }
            #pragma unroll
            for (int nt = 0; nt < 4; nt++) {
                const int row = bRowBase + nt * 16 + lrow;
                const uint32_t off = sw128((uint32_t)(row * BKB + ks * 32 + lkc * 16));
                ldsm4(b[nt][0], b[nt][1], b[nt][2], b[nt][3], sB + off);
            }
            #pragma unroll
            for (int mi = 0; mi < 2; mi++)
                #pragma unroll
                for (int nt = 0; nt < 4; nt++) {
                    mma16816(acc[mi][nt * 2],     a[mi], b[nt][0], b[nt][2]);
                    mma16816(acc[mi][nt * 2 + 1], a[mi], b[nt][1], b[nt][3]);
                }
        }
    }

    #pragma unroll
    for (int mi = 0; mi < 2; mi++) {
        const int r = m0 + wm * 32 + mi * 16 + (lane >> 2);
        #pragma unroll
        for (int nj = 0; nj < 8; nj++) {
            const int cidx = n0 + wn * 64 + nj * 8 + (lane & 3) * 2;
            float b0 = 0.f, b1 = 0.f;
            if (bias) { b0 = bias[cidx]; b1 = bias[cidx + 1]; }
            float x0 = acc[mi][nj][0] * alpha + b0;
            float x1 = acc[mi][nj][1] * alpha + b1;
            float x2 = acc[mi][nj][2] * alpha + b0;
            float x3 = acc[mi][nj][3] * alpha + b1;
            if (sizeof(OutT) == 4) {
                float* Cf = (float*)C;
                *reinterpret_cast<float2*>(Cf + (long long)r * ldC + cidx)
                    = make_float2(x0, x1);
                *reinterpret_cast<float2*>(Cf + (long long)(r + 8) * ldC + cidx)
                    = make_float2(x2, x3);
            } else {
                __half* Ch = (__half*)C;
                *reinterpret_cast<__half2*>(Ch + (long long)r * ldC + cidx)
                    = __floats2half2_rn(x0, x1);
                *reinterpret_cast<__half2*>(Ch + (long long)(r + 8) * ldC + cidx)
                    = __floats2half2_rn(x2, x3);
            }
        }
    }
}

template <typename OutT>
__global__ __launch_bounds__(256, 2) void gemm1(
    const __half* __restrict__ A, const __half* __restrict__ B,
    OutT* __restrict__ C, const float* __restrict__ bias,
    int Kp, int ldC, int aRowsPerB, int bRowsPerB, long long cPerB, float alpha)
{
    extern __shared__ __align__(1024) char smem[];
    const __half* Ab = A + ((long long)blockIdx.z * aRowsPerB + (long long)blockIdx.y * BM) * Kp;
    const __half* Bb = B + ((long long)blockIdx.z * bRowsPerB + (long long)blockIdx.x * BN) * Kp;
    OutT* Cb = C + (long long)blockIdx.z * cPerB;
    gemm_core1<OutT>(Ab, Bb, Cb, bias, Kp, ldC, alpha,
                     blockIdx.y * BM, blockIdx.x * BN, smem);
}

// Fused Q/K/V' projections: one launch, z selects; writes f16 outputs.
// z==2 computes V' = h2 @ W'^T + cb0 (Wo folded into Wv).
__global__ __launch_bounds__(256, 2) void gemm_qkv(
    const __half* __restrict__ h1s, const __half* __restrict__ h2s,
    const __half* __restrict__ Wq, const __half* __restrict__ Wk,
    const __half* __restrict__ Wp,
    __half* __restrict__ Fq, __half* __restrict__ Fk, __half* __restrict__ Fv,
    const float* __restrict__ bq, const float* __restrict__ bk,
    const float* __restrict__ cb0)
{
    extern __shared__ __align__(1024) char smem[];
    const __half* A; const __half* B; __half* C; const float* bias;
    if (blockIdx.z == 0)      { A = h1s; B = Wq; C = Fq; bias = bq; }
    else if (blockIdx.z == 1) { A = h2s; B = Wk; C = Fk; bias = bk; }
    else                      { A = h2s; B = Wp; C = Fv; bias = cb0; }
    A += (long long)blockIdx.y * BM * DIM;
    B += (long long)blockIdx.x * BN * DIM;
    gemm_core1<__half>(A, B, C, bias, DIM, DIM, 1.0f,
                       blockIdx.y * BM, blockIdx.x * BN, smem);
}

// --------------------------- weight folding (fp32, exact) ------------------
// W'[e,c] = sum_d Wo[e,d] * Wv[d,c]   -> f16 Wps[e*512 + c]
// 64x64 tiles, BK=16, 256 threads, 4x4 micro-tile.
__global__ __launch_bounds__(256) void wfold_kernel(
    const float* __restrict__ Wo, const float* __restrict__ Wv,
    __half* __restrict__ Wps)
{
    __shared__ float As[16][64];   // As[d][e]
    __shared__ float Bs[16][64];   // Bs[d][c]
    const int t = threadIdx.x;
    const int tx = t & 15, ty = t >> 4;
    const int e0 = blockIdx.y * 64;
    const int c0 = blockIdx.x * 64;

    float acc[4][4] = {};
    for (int d0 = 0; d0 < DIM; d0 += 16) {
        #pragma unroll
        for (int i = 0; i < 4; i++) {
            int id = t * 4 + i;
            int m = id >> 4, dd = id & 15;          // A: 64 e-rows x 16 d
            As[dd][m] = Wo[(e0 + m) * DIM + d0 + dd];
            int col = id & 63, row = id >> 6;       // B: 16 d-rows x 64 c
            Bs[row][col] = Wv[(d0 + row) * DIM + c0 + col];
        }
        __syncthreads();
        #pragma unroll
        for (int dd = 0; dd < 16; dd++) {
            float a[4], b[4];
            #pragma unroll
            for (int u = 0; u < 4; u++) { a[u] = As[dd][ty * 4 + u]; b[u] = Bs[dd][tx * 4 + u]; }
            #pragma unroll
            for (int x = 0; x < 4; x++)
                #pragma unroll
                for (int y = 0; y < 4; y++)
                    acc[x][y] = fmaf(a[x], b[y], acc[x][y]);
        }
        __syncthreads();
    }
    #pragma unroll
    for (int x = 0; x < 4; x++)
        #pragma unroll
        for (int y = 0; y < 4; y++)
            Wps[(size_t)(e0 + ty * 4 + x) * DIM + c0 + tx * 4 + y] = __float2half(acc[x][y]);
}

// cb0[e] = sum_d Wo[e,d] * bv[d]  (fp32 exact); one block per e.
__global__ __launch_bounds__(256) void cbias_kernel(
    const float* __restrict__ Wo, const float* __restrict__ bv,
    float* __restrict__ cb)
{
    const int e = blockIdx.x;
    const int t = threadIdx.x;
    float s = 0.f;
    for (int d = t; d < DIM; d += 256) s += Wo[e * DIM + d] * bv[d];
    #pragma unroll
    for (int off = 16; off; off >>= 1) s += __shfl_xor_sync(0xffffffffu, s, off);
    __shared__ float red[8];
    if ((t & 31) == 0) red[t >> 5] = s;
    __syncthreads();
    if (t == 0) {
        float tot = 0.f;
        #pragma unroll
        for (int w = 0; w < 8; w++) tot += red[w];
        cb[e] = tot;
    }
}

// --------------------------- elementwise kernels ---------------------------
// fp32 -> f16 compact convert; z picks (a->ya) or (b->yb). 4 elems/thread.
__global__ void convert2_kernel(const float* __restrict__ a, const float* __restrict__ b,
                                __half* __restrict__ ya, __half* __restrict__ yb,
                                long long n4)
{
    long long i = (long long)blockIdx.x * blockDim.x + threadIdx.x;
    if (i >= n4) return;
    const float* src = blockIdx.z ? b : a;
    __half* dst = blockIdx.z ? yb : ya;
    float4 v = reinterpret_cast<const float4*>(src)[i];
    reinterpret_cast<__half2*>(dst)[i * 2]     = __floats2half2_rn(v.x, v.y);
    reinterpret_cast<__half2*>(dst)[i * 2 + 1] = __floats2half2_rn(v.z, v.w);
}

// RoPE, f16 in/out, 2 adjacent j per thread (half2); z picks q or k.
__global__ void rope2_kernel(const __half* __restrict__ xq, const __half* __restrict__ xk,
                             __half* __restrict__ yq, __half* __restrict__ yk)
{
    long long idx = (long long)blockIdx.x * blockDim.x + threadIdx.x;
    const int HP = HALFD / 2;   // 128 j-pairs
    long long tot = (long long)MS * HP;
    if (idx >= tot) return;
    const __half* x = blockIdx.z ? xk : xq;
    __half* y = blockIdx.z ? yk : yq;
    int jp = (int)(idx % HP);
    int j = jp * 2;
    long long bs = idx / HP;
    int s = (int)(bs % SEQ);

    const float kNegLog2Base = -13.287712379549449f / 256.0f;  // -log2(10000)/256
    float i0 = exp2f((float)j * kNegLog2Base);
    float i1 = exp2f((float)(j + 1) * kNegLog2Base);
    float sn0, c0, sn1, c1;
    sincosf((float)s * i0, &sn0, &c0);
    sincosf((float)s * i1, &sn1, &c1);

    const __half* p = x + bs * DIM;
    float2 fa = __half22float2(*reinterpret_cast<const __half2*>(p + j));
    float2 fb = __half22float2(*reinterpret_cast<const __half2*>(p + j + HALFD));
    __half* q = y + bs * DIM;
    *reinterpret_cast<__half2*>(q + j) =
        __floats2half2_rn(fa.x * c0 - fb.x * sn0, fa.y * c1 - fb.y * sn1);
    *reinterpret_cast<__half2*>(q + j + HALFD) =
        __floats2half2_rn(fb.x * c0 + fa.x * sn0, fb.y * c1 + fa.y * sn1);
}

// V' f16 [B, S(k), D(n)] -> Vt f16 [B*D rows, SEQ cols] (transposed)
__global__ void transpose_hi_kernel(const __half* __restrict__ V, __half* __restrict__ Vt)
{
    __shared__ float tile[32][33];
    const int b  = blockIdx.z;
    const int n0 = blockIdx.x * 32;
    const int k0 = blockIdx.y * 32;
    const int tx = threadIdx.x, ty = threadIdx.y;   // block (32, 8)
    const __half* src = V + (size_t)b * SEQ * DIM;
    #pragma unroll
    for (int i = 0; i < 4; i++)
        tile[ty + 8 * i][tx] = __half2float(src[(size_t)(k0 + ty + 8 * i) * DIM + n0 + tx]);
    __syncthreads();
    __half* dst = Vt + (size_t)b * DIM * SEQ;
    #pragma unroll
    for (int i = 0; i < 4; i++)
        dst[(size_t)(n0 + ty + 8 * i) * SEQ + (k0 + tx)] = __float2half(tile[tx][ty + 8 * i]);
}

// softmax rows of E f16 (len 2048) -> f16 P, 8 halves/thread.
__global__ __launch_bounds__(256) void softmax_h_kernel(const __half* __restrict__ E,
                                                        __half* __restrict__ Es)
{
    const int t = threadIdx.x;
    const uint2* pin = reinterpret_cast<const uint2*>(E + (size_t)blockIdx.x * SEQ);
    uint2* pout = reinterpret_cast<uint2*>(Es + (size_t)blockIdx.x * SEQ);

    uint2 u0 = pin[t];
    uint2 u1 = pin[t + 256];
    float v[8];
    {
        float2 f;
        f = __half22float2(*reinterpret_cast<__half2*>(&u0.x)); v[0] = f.x; v[1] = f.y;
        f = __half22float2(*reinterpret_cast<__half2*>(&u0.y)); v[2] = f.x; v[3] = f.y;
        f = __half22float2(*reinterpret_cast<__half2*>(&u1.x)); v[4] = f.x; v[5] = f.y;
        f = __half22float2(*reinterpret_cast<__half2*>(&u1.y)); v[6] = f.x; v[7] = f.y;
    }

    float m = v[0];
    #pragma unroll
    for (int i = 1; i < 8; i++) m = fmaxf(m, v[i]);
    #pragma unroll
    for (int off = 16; off; off >>= 1) m = fmaxf(m, __shfl_xor_sync(0xffffffffu, m, off));

    __shared__ float redm[8], reds[8];
    if ((t & 31) == 0) redm[t >> 5] = m;
    __syncthreads();
    float bm = redm[0];
    #pragma unroll
    for (int w = 1; w < 8; w++) bm = fmaxf(bm, redm[w]);

    float s = 0.0f;
    #pragma unroll
    for (int i = 0; i < 8; i++) { v[i] = __expf(v[i] - bm); s += v[i]; }
    #pragma unroll
    for (int off = 16; off; off >>= 1) s += __shfl_xor_sync(0xffffffffu, s, off);
    if ((t & 31) == 0) reds[t >> 5] = s;
    __syncthreads();
    float bs = 0.0f;
    #pragma unroll
    for (int w = 0; w < 8; w++) bs += reds[w];

    float inv = 1.0f / bs;
    uint2 o0, o1;
    __half2 h;
    h = __floats2half2_rn(v[0] * inv, v[1] * inv); o0.x = *reinterpret_cast<uint32_t*>(&h);
    h = __floats2half2_rn(v[2] * inv, v[3] * inv); o0.y = *reinterpret_cast<uint32_t*>(&h);
    h = __floats2half2_rn(v[4] * inv, v[5] * inv); o1.x = *reinterpret_cast<uint32_t*>(&h);
    h = __floats2half2_rn(v[6] * inv, v[7] * inv); o1.y = *reinterpret_cast<uint32_t*>(&h);
    pout[t]       = o0;
    pout[t + 256] = o1;
}

// --------------------------- host side -------------------------------------
extern "C" void kernel_launch(void* const* d_in, const int* in_sizes, int n_in,
                              void* d_out, int out_size)
{
    const float* h1 = (const float*)d_in[0];
    const float* h2 = (const float*)d_in[1];
    const float* Wq = (const float*)d_in[2];
    const float* bq = (const float*)d_in[3];
    const float* Wk = (const float*)d_in[4];
    const float* bk = (const float*)d_in[5];
    const float* Wv = (const float*)d_in[6];
    const float* bv = (const float*)d_in[7];
    const float* Wo = (const float*)d_in[8];
    const float* bo = (const float*)d_in[9];
    float* out = (float*)d_out;

    void *h1s, *h2s, *Wqs, *Wks, *Wps, *cb;
    void *Fq, *Fk, *Fv, *Qs, *Ks, *Vts, *E16, *Es;
    cudaGetSymbolAddress(&h1s, g_h1s);  cudaGetSymbolAddress(&h2s, g_h2s);
    cudaGetSymbolAddress(&Wqs, g_Wqs);  cudaGetSymbolAddress(&Wks, g_Wks);
    cudaGetSymbolAddress(&Wps, g_Wps);  cudaGetSymbolAddress(&cb, g_cb);
    cudaGetSymbolAddress(&Fq, g_Fq16);  cudaGetSymbolAddress(&Fk, g_Fk16);
    cudaGetSymbolAddress(&Fv, g_Fv16);
    cudaGetSymbolAddress(&Qs, g_Qs);    cudaGetSymbolAddress(&Ks, g_Ks);
    cudaGetSymbolAddress(&Vts, g_Vts);  cudaGetSymbolAddress(&E16, g_E16);
    cudaGetSymbolAddress(&Es, g_Es);

    cudaFuncSetAttribute(gemm_qkv,      cudaFuncAttributeMaxDynamicSharedMemorySize, SMEM_G);
    cudaFuncSetAttribute(gemm1<float>,  cudaFuncAttributeMaxDynamicSharedMemorySize, SMEM_G);
    cudaFuncSetAttribute(gemm1<__half>, cudaFuncAttributeMaxDynamicSharedMemorySize, SMEM_G);

    const float scale = 0.044194173824159216f;  // 1/sqrt(512)

    // 0: convert h1, h2 -> f16
    {
        long long n4 = (long long)MS * DIM / 4;
        dim3 g((unsigned)((n4 + 255) / 256), 1, 2);
        convert2_kernel<<<g, 256>>>(h1, h2, (__half*)h1s, (__half*)h2s, n4);
    }
    // 1: convert Wq, Wk -> f16
    {
        long long n4 = (long long)DIM * DIM / 4;
        dim3 g((unsigned)((n4 + 255) / 256), 1, 2);
        convert2_kernel<<<g, 256>>>(Wq, Wk, (__half*)Wqs, (__half*)Wks, n4);
    }
    // 2: W' = Wo @ Wv (fp32 exact -> f16)
    {
        dim3 g(DIM / 64, DIM / 64, 1);
        wfold_kernel<<<g, 256>>>(Wo, Wv, (__half*)Wps);
    }
    // 3: cb0 = Wo @ bv
    cbias_kernel<<<DIM, 256>>>(Wo, bv, (float*)cb);
    // 4: fused Q/K/V' projections
    dim3 gqkv(DIM / BN, MS / BM, 3);
    gemm_qkv<<<gqkv, 256, SMEM_G>>>((const __half*)h1s, (const __half*)h2s,
                                    (const __half*)Wqs, (const __half*)Wks,
                                    (const __half*)Wps,
                                    (__half*)Fq, (__half*)Fk, (__half*)Fv,
                                    bq, bk, (const float*)cb);
    // 5: RoPE Q and K (2 j per thread, z picks)
    {
        long long tot = (long long)MS * (HALFD / 2);
        dim3 g((unsigned)((tot + 255) / 256), 1, 2);
        rope2_kernel<<<g, 256>>>((const __half*)Fq, (const __half*)Fk,
                                 (__half*)Qs, (__half*)Ks);
    }
    // 6: transpose V'
    {
        dim3 gt(DIM / 32, SEQ / 32, BATCH);
        transpose_hi_kernel<<<gt, dim3(32, 8)>>>((const __half*)Fv, (__half*)Vts);
    }
    // 7: scores E16[b] = scale * Q[b] K[b]^T  (f16 out)
    dim3 ge(SEQ / BN, SEQ / BM, BATCH);
    gemm1<__half><<<ge, 256, SMEM_G>>>((const __half*)Qs, (const __half*)Ks,
                                       (__half*)E16, nullptr, DIM, SEQ, SEQ, SEQ,
                                       (long long)SEQ * SEQ, scale);
    // 8: softmax (f16 -> f16)
    softmax_h_kernel<<<BATCH * SEQ, 256>>>((const __half*)E16, (__half*)Es);
    // 9: out[b] = P[b] V'[b] + bo  (fp32 out, final)
    dim3 gpv(DIM / BN, SEQ / BM, BATCH);
    gemm1<float><<<gpv, 256, SMEM_G>>>((const __half*)Es, (const __half*)Vts,
                                       out, bo, SEQ, DIM, SEQ, DIM,
                                       (long long)SEQ * DIM, 1.0f);
}

// round 12
// speedup vs baseline: 5.1145x; 1.0190x over previous
#include <cuda_runtime.h>
#include <cuda_fp16.h>
#include <stdint.h>
#include <math.h>

// ===========================================================================
// CrossAttention B=8, S=2048, D=512 (single head, fp32 I/O).
// All GEMMs on mma.sync (HMMA fp16, fp32 accum), 1-term, compact f16,
// 2 CTAs/SM. Algebraic fusions:
//   - W' = Wo@Wv (fp32 exact): output projection folded into V projection.
//   - RoPE folded into the Q/K projection epilogue via feature permutation
//     p -> orig(p) = (p&1) ? p/2+256 : p/2  (QK^T is permutation-invariant).
// ===========================================================================

#define BATCH 8
#define SEQ   2048
#define DIM   512
#define MS    (BATCH * SEQ)     // 16384
#define HALFD (DIM / 2)

#define BM 128
#define BN 128
#define BKE 64                          // fp16 elems per k-chunk (128 bytes)
#define BKB 128                         // bytes per smem row
#define STAGES 3
#define TILE_BYTES (BM * BKB)           // 16384
#define SMEM_G (STAGES * 2 * TILE_BYTES)  // 98304 (A|B) -> 2 CTAs/SM

// --------------------------- device scratch -------------------------------
__device__ __align__(1024) __half g_h1s[(size_t)MS * DIM];
__device__ __align__(1024) __half g_h2s[(size_t)MS * DIM];
__device__ __align__(1024) __half g_Wqs[(size_t)DIM * DIM];   // permuted rows
__device__ __align__(1024) __half g_Wks[(size_t)DIM * DIM];   // permuted rows
__device__ __align__(1024) __half g_Wps[(size_t)DIM * DIM];   // W' = Wo@Wv
__device__ __align__(1024) float  g_cb[DIM];                  // Wo@bv
__device__ __align__(1024) float2 g_tab[(size_t)SEQ * HALFD]; // (cos,sin)[s][c]
__device__ __align__(1024) __half g_Fv16[(size_t)MS * DIM];   // V'
__device__ __align__(1024) __half g_Qs[(size_t)MS * DIM];     // permuted features
__device__ __align__(1024) __half g_Ks[(size_t)MS * DIM];     // permuted features
__device__ __align__(1024) __half g_Vts[(size_t)BATCH * DIM * SEQ];
__device__ __align__(1024) __half g_E16[(size_t)BATCH * SEQ * SEQ];
__device__ __align__(1024) __half g_Es[(size_t)BATCH * SEQ * SEQ];

// --------------------------- PTX helpers -----------------------------------
__device__ __forceinline__ uint32_t smem_u32(const void* p) {
    uint32_t a;
    asm("{ .reg .u64 t; cvta.to.shared.u64 t, %1; cvt.u32.u64 %0, t; }"
        : "=r"(a) : "l"(p));
    return a;
}
__device__ __forceinline__ void cp_async16(uint32_t dst, const void* src) {
    asm volatile("cp.async.cg.shared.global [%0], [%1], 16;" :: "r"(dst), "l"(src));
}
__device__ __forceinline__ void cp_commit() {
    asm volatile("cp.async.commit_group;" ::: "memory");
}
template <int N> __device__ __forceinline__ void cp_wait() {
    asm volatile("cp.async.wait_group %0;" :: "n"(N) : "memory");
}
__device__ __forceinline__ void ldsm4(uint32_t& r0, uint32_t& r1, uint32_t& r2,
                                      uint32_t& r3, uint32_t a) {
    asm volatile("ldmatrix.sync.aligned.m8n8.x4.shared.b16 {%0,%1,%2,%3}, [%4];"
                 : "=r"(r0), "=r"(r1), "=r"(r2), "=r"(r3) : "r"(a));
}
__device__ __forceinline__ void mma16816(float* d, const uint32_t* a,
                                         uint32_t b0, uint32_t b1) {
    asm volatile(
        "mma.sync.aligned.m16n8k16.row.col.f32.f16.f16.f32 "
        "{%0,%1,%2,%3}, {%4,%5,%6,%7}, {%8,%9}, {%0,%1,%2,%3};"
        : "+f"(d[0]), "+f"(d[1]), "+f"(d[2]), "+f"(d[3])
        : "r"(a[0]), "r"(a[1]), "r"(a[2]), "r"(a[3]), "r"(b0), "r"(b1));
}
__device__ __forceinline__ uint32_t sw128(uint32_t off) {
    return off ^ ((off >> 3) & 0x70);
}

// --------------------------- GEMM core (1-term) -----------------------------
// NT: C[m,n] = alpha * A[m,:].B[n,:] + bias[n]     (ROPE==false)
// ROPE==true: output columns are permuted features; pairs (2c,2c+1) are
// rotated by tab[s][c] after bias (bias indexed by ORIGINAL feature).
template <typename OutT, bool ROPE>
__device__ __forceinline__ void gemm_core1(
    const __half* __restrict__ A, const __half* __restrict__ B,
    OutT* __restrict__ C, const float* __restrict__ bias,
    const float2* __restrict__ tab,
    int Kp, int ldC, float alpha, int m0, int n0, char* smem)
{
    const int tid  = threadIdx.x;
    const int wid  = tid >> 5;
    const int lane = tid & 31;
    const int wm   = wid & 3;
    const int wn   = wid >> 2;
    const uint32_t smb = smem_u32(smem);
    const int chunks = Kp / BKE;

    auto issue = [&](int it) {
        const long long k0 = (long long)it * BKE;
        const uint32_t sb = smb + (it % STAGES) * (2 * TILE_BYTES);
        #pragma unroll
        for (int i = 0; i < 4; i++) {
            const int id = tid * 4 + i;
            const int r = id >> 3, c = id & 7;
            const uint32_t off = sw128((uint32_t)(r * BKB + c * 16));
            const long long arow = (long long)r * Kp;
            cp_async16(sb + off, A + arow + k0 + c * 8);
            cp_async16(sb + TILE_BYTES + off, B + arow + k0 + c * 8);
        }
        cp_commit();
    };

    float acc[2][8][4] = {};
    const int aRowBase = wm * 32;
    const int bRowBase = wn * 64;
    const int lrow = lane & 15;
    const int lkc  = lane >> 4;

    const int prol = (chunks < STAGES - 1) ? chunks : (STAGES - 1);
    for (int it = 0; it < prol; it++) issue(it);

    for (int it = 0; it < chunks; it++) {
        cp_wait<STAGES - 2>();
        __syncthreads();
        if (it + STAGES - 1 < chunks) issue(it + STAGES - 1);

        const uint32_t sA = smb + (it % STAGES) * (2 * TILE_BYTES);
        const uint32_t sB = sA + TILE_BYTES;

        #pragma unroll
        for (int ks = 0; ks < 4; ks++) {
            uint32_t a[2][4], b[4][4];
            #pragma unroll
            for (int mi = 0; mi < 2; mi++) {
                const int row = aRowBase + mi * 16 + lrow;
                const uint32_t off = sw128((uint32_t)(row * BKB + ks * 32 + lkc * 16));
                ldsm4(a[mi][0], a[mi][1], a[mi][2], a[mi][3], sA + off);
            }
            #pragma unroll
            for (int nt = 0; nt < 4; nt++) {
                const int row = bRowBase + nt * 16 + lrow;
                const uint32_t off = sw128((uint32_t)(row * BKB + ks * 32 + lkc * 16));
                ldsm4(b[nt][0], b[nt][1], b[nt][2], b[nt][3], sB + off);
            }
            #pragma unroll
            for (int mi = 0; mi < 2; mi++)
                #pragma unroll
                for (int nt = 0; nt < 4; nt++) {
                    mma16816(acc[mi][nt * 2],     a[mi], b[nt][0], b[nt][2]);
                    mma16816(acc[mi][nt * 2 + 1], a[mi], b[nt][1], b[nt][3]);
                }
        }
    }

    #pragma unroll
    for (int mi = 0; mi < 2; mi++) {
        const int r = m0 + wm * 32 + mi * 16 + (lane >> 2);
        const int s0 = r & (SEQ - 1);
        const int s1 = (r + 8) & (SEQ - 1);
        #pragma unroll
        for (int nj = 0; nj < 8; nj++) {
            const int cidx = n0 + wn * 64 + nj * 8 + (lane & 3) * 2;  // even
            if (ROPE) {
                const int c = cidx >> 1;     // rope pair index (0..255)
                float b0 = bias ? bias[c] : 0.f;
                float b1 = bias ? bias[c + HALFD] : 0.f;
                float x0 = acc[mi][nj][0] + b0;
                float x1 = acc[mi][nj][1] + b1;
                float x2 = acc[mi][nj][2] + b0;
                float x3 = acc[mi][nj][3] + b1;
                float2 cs0 = tab[(size_t)s0 * HALFD + c];
                float2 cs1 = tab[(size_t)s1 * HALFD + c];
                float y0 = x0 * cs0.x - x1 * cs0.y;
                float y1 = x1 * cs0.x + x0 * cs0.y;
                float y2 = x2 * cs1.x - x3 * cs1.y;
                float y3 = x3 * cs1.x + x2 * cs1.y;
                __half* Ch = (__half*)C;
                *reinterpret_cast<__half2*>(Ch + (long long)r * ldC + cidx)
                    = __floats2half2_rn(y0, y1);
                *reinterpret_cast<__half2*>(Ch + (long long)(r + 8) * ldC + cidx)
                    = __floats2half2_rn(y2, y3);
            } else {
                float b0 = bias ? bias[cidx] : 0.f;
                float b1 = bias ? bias[cidx + 1] : 0.f;
                float x0 = acc[mi][nj][0] * alpha + b0;
                float x1 = acc[mi][nj][1] * alpha + b1;
                float x2 = acc[mi][nj][2] * alpha + b0;
                float x3 = acc[mi][nj][3] * alpha + b1;
                if (sizeof(OutT) == 4) {
                    float* Cf = (float*)C;
                    *reinterpret_cast<float2*>(Cf + (long long)r * ldC + cidx)
                        = make_float2(x0, x1);
                    *reinterpret_cast<float2*>(Cf + (long long)(r + 8) * ldC + cidx)
                        = make_float2(x2, x3);
                } else {
                    __half* Ch = (__half*)C;
                    *reinterpret_cast<__half2*>(Ch + (long long)r * ldC + cidx)
                        = __floats2half2_rn(x0, x1);
                    *reinterpret_cast<__half2*>(Ch + (long long)(r + 8) * ldC + cidx)
                        = __floats2half2_rn(x2, x3);
                }
            }
        }
    }
}

template <typename OutT>
__global__ __launch_bounds__(256, 2) void gemm1(
    const __half* __restrict__ A, const __half* __restrict__ B,
    OutT* __restrict__ C, const float* __restrict__ bias,
    int Kp, int ldC, int aRowsPerB, int bRowsPerB, long long cPerB, float alpha)
{
    extern __shared__ __align__(1024) char smem[];
    const __half* Ab = A + ((long long)blockIdx.z * aRowsPerB + (long long)blockIdx.y * BM) * Kp;
    const __half* Bb = B + ((long long)blockIdx.z * bRowsPerB + (long long)blockIdx.x * BN) * Kp;
    OutT* Cb = C + (long long)blockIdx.z * cPerB;
    gemm_core1<OutT, false>(Ab, Bb, Cb, bias, nullptr, Kp, ldC, alpha,
                            blockIdx.y * BM, blockIdx.x * BN, smem);
}

// Fused Q/K/V' projections. z=0: Q=rope(h1@Wq^T+bq) (permuted features);
// z=1: K likewise; z=2: V' = h2@W'^T + cb0 (Wo folded, no rope).
__global__ __launch_bounds__(256, 2) void gemm_qkv(
    const __half* __restrict__ h1s, const __half* __restrict__ h2s,
    const __half* __restrict__ Wq, const __half* __restrict__ Wk,
    const __half* __restrict__ Wp,
    __half* __restrict__ Qs, __half* __restrict__ Ks, __half* __restrict__ Fv,
    const float* __restrict__ bq, const float* __restrict__ bk,
    const float* __restrict__ cb0, const float2* __restrict__ tab)
{
    extern __shared__ __align__(1024) char smem[];
    if (blockIdx.z == 2) {
        const __half* A = h2s + (long long)blockIdx.y * BM * DIM;
        const __half* B = Wp + (long long)blockIdx.x * BN * DIM;
        gemm_core1<__half, false>(A, B, Fv, cb0, nullptr, DIM, DIM, 1.0f,
                                  blockIdx.y * BM, blockIdx.x * BN, smem);
    } else {
        const __half* A = (blockIdx.z == 0 ? h1s : h2s) + (long long)blockIdx.y * BM * DIM;
        const __half* B = (blockIdx.z == 0 ? Wq : Wk) + (long long)blockIdx.x * BN * DIM;
        __half* C = blockIdx.z == 0 ? Qs : Ks;
        const float* bias = blockIdx.z == 0 ? bq : bk;
        gemm_core1<__half, true>(A, B, C, bias, tab, DIM, DIM, 1.0f,
                                 blockIdx.y * BM, blockIdx.x * BN, smem);
    }
}

// --------------------------- weight folding (fp32, exact) ------------------
__global__ __launch_bounds__(256) void wfold_kernel(
    const float* __restrict__ Wo, const float* __restrict__ Wv,
    __half* __restrict__ Wps)
{
    __shared__ float As[16][64];
    __shared__ float Bs[16][64];
    const int t = threadIdx.x;
    const int tx = t & 15, ty = t >> 4;
    const int e0 = blockIdx.y * 64;
    const int c0 = blockIdx.x * 64;

    float acc[4][4] = {};
    for (int d0 = 0; d0 < DIM; d0 += 16) {
        #pragma unroll
        for (int i = 0; i < 4; i++) {
            int id = t * 4 + i;
            int m = id >> 4, dd = id & 15;
            As[dd][m] = Wo[(e0 + m) * DIM + d0 + dd];
            int col = id & 63, row = id >> 6;
            Bs[row][col] = Wv[(d0 + row) * DIM + c0 + col];
        }
        __syncthreads();
        #pragma unroll
        for (int dd = 0; dd < 16; dd++) {
            float a[4], b[4];
            #pragma unroll
            for (int u = 0; u < 4; u++) { a[u] = As[dd][ty * 4 + u]; b[u] = Bs[dd][tx * 4 + u]; }
            #pragma unroll
            for (int x = 0; x < 4; x++)
                #pragma unroll
                for (int y = 0; y < 4; y++)
                    acc[x][y] = fmaf(a[x], b[y], acc[x][y]);
        }
        __syncthreads();
    }
    #pragma unroll
    for (int x = 0; x < 4; x++)
        #pragma unroll
        for (int y = 0; y < 4; y++)
            Wps[(size_t)(e0 + ty * 4 + x) * DIM + c0 + tx * 4 + y] = __float2half(acc[x][y]);
}

__global__ __launch_bounds__(256) void cbias_kernel(
    const float* __restrict__ Wo, const float* __restrict__ bv,
    float* __restrict__ cb)
{
    const int e = blockIdx.x;
    const int t = threadIdx.x;
    float s = 0.f;
    for (int d = t; d < DIM; d += 256) s += Wo[e * DIM + d] * bv[d];
    #pragma unroll
    for (int off = 16; off; off >>= 1) s += __shfl_xor_sync(0xffffffffu, s, off);
    __shared__ float red[8];
    if ((t & 31) == 0) red[t >> 5] = s;
    __syncthreads();
    if (t == 0) {
        float tot = 0.f;
        #pragma unroll
        for (int w = 0; w < 8; w++) tot += red[w];
        cb[e] = tot;
    }
}

// --------------------------- elementwise kernels ---------------------------
__global__ void convert2_kernel(const float* __restrict__ a, const float* __restrict__ b,
                                __half* __restrict__ ya, __half* __restrict__ yb,
                                long long n4)
{
    long long i = (long long)blockIdx.x * blockDim.x + threadIdx.x;
    if (i >= n4) return;
    const float* src = blockIdx.z ? b : a;
    __half* dst = blockIdx.z ? yb : ya;
    float4 v = reinterpret_cast<const float4*>(src)[i];
    reinterpret_cast<__half2*>(dst)[i * 2]     = __floats2half2_rn(v.x, v.y);
    reinterpret_cast<__half2*>(dst)[i * 2 + 1] = __floats2half2_rn(v.z, v.w);
}

// Convert Wq/Wk to f16 with ROW PERMUTATION: out row p = in row orig(p),
// orig(p) = (p&1) ? p/2+256 : p/2.  z picks Wq or Wk.
__global__ void convertWperm_kernel(const float* __restrict__ wq, const float* __restrict__ wk,
                                    __half* __restrict__ yq, __half* __restrict__ yk)
{
    long long i = (long long)blockIdx.x * blockDim.x + threadIdx.x;  // over DIM*DIM/4
    long long n4 = (long long)DIM * DIM / 4;
    if (i >= n4) return;
    const float* src = blockIdx.z ? wk : wq;
    __half* dst = blockIdx.z ? yk : yq;
    int p = (int)(i / (DIM / 4));
    int d4 = (int)(i % (DIM / 4));
    int orig = (p & 1) ? (p >> 1) + HALFD : (p >> 1);
    float4 v = reinterpret_cast<const float4*>(src + (size_t)orig * DIM)[d4];
    __half2* o = reinterpret_cast<__half2*>(dst + (size_t)p * DIM) + d4 * 2;
    o[0] = __floats2half2_rn(v.x, v.y);
    o[1] = __floats2half2_rn(v.z, v.w);
}

// Precompute rope table: tab[s*256+c] = (cos(s*invf(c)), sin(s*invf(c))).
__global__ void rope_table_kernel(float2* __restrict__ tab)
{
    long long i = (long long)blockIdx.x * blockDim.x + threadIdx.x;
    long long tot = (long long)SEQ * HALFD;
    if (i >= tot) return;
    int c = (int)(i % HALFD);
    int s = (int)(i / HALFD);
    const float kNegLog2Base = -13.287712379549449f / 256.0f;  // -log2(10000)/256
    float invf = exp2f((float)c * kNegLog2Base);
    float sn, cs;
    sincosf((float)s * invf, &sn, &cs);
    tab[i] = make_float2(cs, sn);
}

// V' f16 [B, S(k), D(n)] -> Vt f16 [B*D rows, SEQ cols] (transposed)
__global__ void transpose_hi_kernel(const __half* __restrict__ V, __half* __restrict__ Vt)
{
    __shared__ float tile[32][33];
    const int b  = blockIdx.z;
    const int n0 = blockIdx.x * 32;
    const int k0 = blockIdx.y * 32;
    const int tx = threadIdx.x, ty = threadIdx.y;
    const __half* src = V + (size_t)b * SEQ * DIM;
    #pragma unroll
    for (int i = 0; i < 4; i++)
        tile[ty + 8 * i][tx] = __half2float(src[(size_t)(k0 + ty + 8 * i) * DIM + n0 + tx]);
    __syncthreads();
    __half* dst = Vt + (size_t)b * DIM * SEQ;
    #pragma unroll
    for (int i = 0; i < 4; i++)
        dst[(size_t)(n0 + ty + 8 * i) * SEQ + (k0 + tx)] = __float2half(tile[tx][ty + 8 * i]);
}

// softmax rows of E f16 (len 2048) -> f16 P, 8 halves/thread.
__global__ __launch_bounds__(256) void softmax_h_kernel(const __half* __restrict__ E,
                                                        __half* __restrict__ Es)
{
    const int t = threadIdx.x;
    const uint2* pin = reinterpret_cast<const uint2*>(E + (size_t)blockIdx.x * SEQ);
    uint2* pout = reinterpret_cast<uint2*>(Es + (size_t)blockIdx.x * SEQ);

    uint2 u0 = pin[t];
    uint2 u1 = pin[t + 256];
    float v[8];
    {
        float2 f;
        f = __half22float2(*reinterpret_cast<__half2*>(&u0.x)); v[0] = f.x; v[1] = f.y;
        f = __half22float2(*reinterpret_cast<__half2*>(&u0.y)); v[2] = f.x; v[3] = f.y;
        f = __half22float2(*reinterpret_cast<__half2*>(&u1.x)); v[4] = f.x; v[5] = f.y;
        f = __half22float2(*reinterpret_cast<__half2*>(&u1.y)); v[6] = f.x; v[7] = f.y;
    }

    float m = v[0];
    #pragma unroll
    for (int i = 1; i < 8; i++) m = fmaxf(m, v[i]);
    #pragma unroll
    for (int off = 16; off; off >>= 1) m = fmaxf(m, __shfl_xor_sync(0xffffffffu, m, off));

    __shared__ float redm[8], reds[8];
    if ((t & 31) == 0) redm[t >> 5] = m;
    __syncthreads();
    float bm = redm[0];
    #pragma unroll
    for (int w = 1; w < 8; w++) bm = fmaxf(bm, redm[w]);

    float s = 0.0f;
    #pragma unroll
    for (int i = 0; i < 8; i++) { v[i] = __expf(v[i] - bm); s += v[i]; }
    #pragma unroll
    for (int off = 16; off; off >>= 1) s += __shfl_xor_sync(0xffffffffu, s, off);
    if ((t & 31) == 0) reds[t >> 5] = s;
    __syncthreads();
    float bs = 0.0f;
    #pragma unroll
    for (int w = 0; w < 8; w++) bs += reds[w];

    float inv = 1.0f / bs;
    uint2 o0, o1;
    __half2 h;
    h = __floats2half2_rn(v[0] * inv, v[1] * inv); o0.x = *reinterpret_cast<uint32_t*>(&h);
    h = __floats2half2_rn(v[2] * inv, v[3] * inv); o0.y = *reinterpret_cast<uint32_t*>(&h);
    h = __floats2half2_rn(v[4] * inv, v[5] * inv); o1.x = *reinterpret_cast<uint32_t*>(&h);
    h = __floats2half2_rn(v[6] * inv, v[7] * inv); o1.y = *reinterpret_cast<uint32_t*>(&h);
    pout[t]       = o0;
    pout[t + 256] = o1;
}

// --------------------------- host side -------------------------------------
extern "C" void kernel_launch(void* const* d_in, const int* in_sizes, int n_in,
                              void* d_out, int out_size)
{
    const float* h1 = (const float*)d_in[0];
    const float* h2 = (const float*)d_in[1];
    const float* Wq = (const float*)d_in[2];
    const float* bq = (const float*)d_in[3];
    const float* Wk = (const float*)d_in[4];
    const float* bk = (const float*)d_in[5];
    const float* Wv = (const float*)d_in[6];
    const float* bv = (const float*)d_in[7];
    const float* Wo = (const float*)d_in[8];
    const float* bo = (const float*)d_in[9];
    float* out = (float*)d_out;

    void *h1s, *h2s, *Wqs, *Wks, *Wps, *cb, *tab;
    void *Fv, *Qs, *Ks, *Vts, *E16, *Es;
    cudaGetSymbolAddress(&h1s, g_h1s);  cudaGetSymbolAddress(&h2s, g_h2s);
    cudaGetSymbolAddress(&Wqs, g_Wqs);  cudaGetSymbolAddress(&Wks, g_Wks);
    cudaGetSymbolAddress(&Wps, g_Wps);  cudaGetSymbolAddress(&cb, g_cb);
    cudaGetSymbolAddress(&tab, g_tab);
    cudaGetSymbolAddress(&Fv, g_Fv16);
    cudaGetSymbolAddress(&Qs, g_Qs);    cudaGetSymbolAddress(&Ks, g_Ks);
    cudaGetSymbolAddress(&Vts, g_Vts);  cudaGetSymbolAddress(&E16, g_E16);
    cudaGetSymbolAddress(&Es, g_Es);

    cudaFuncSetAttribute(gemm_qkv,      cudaFuncAttributeMaxDynamicSharedMemorySize, SMEM_G);
    cudaFuncSetAttribute(gemm1<float>,  cudaFuncAttributeMaxDynamicSharedMemorySize, SMEM_G);
    cudaFuncSetAttribute(gemm1<__half>, cudaFuncAttributeMaxDynamicSharedMemorySize, SMEM_G);

    const float scale = 0.044194173824159216f;  // 1/sqrt(512)

    // 0: convert h1, h2 -> f16
    {
        long long n4 = (long long)MS * DIM / 4;
        dim3 g((unsigned)((n4 + 255) / 256), 1, 2);
        convert2_kernel<<<g, 256>>>(h1, h2, (__half*)h1s, (__half*)h2s, n4);
    }
    // 1: convert Wq, Wk -> f16 with rope-pair row permutation
    {
        long long n4 = (long long)DIM * DIM / 4;
        dim3 g((unsigned)((n4 + 255) / 256), 1, 2);
        convertWperm_kernel<<<g, 256>>>(Wq, Wk, (__half*)Wqs, (__half*)Wks);
    }
    // 2: W' = Wo @ Wv (fp32 exact -> f16)
    {
        dim3 g(DIM / 64, DIM / 64, 1);
        wfold_kernel<<<g, 256>>>(Wo, Wv, (__half*)Wps);
    }
    // 3: cb0 = Wo @ bv
    cbias_kernel<<<DIM, 256>>>(Wo, bv, (float*)cb);
    // 4: rope cos/sin table
    {
        long long tot = (long long)SEQ * HALFD;
        rope_table_kernel<<<(unsigned)((tot + 255) / 256), 256>>>((float2*)tab);
    }
    // 5 (ncu profiles this): fused Q/K/V' projections (rope in epilogue)
    dim3 gqkv(DIM / BN, MS / BM, 3);
    gemm_qkv<<<gqkv, 256, SMEM_G>>>((const __half*)h1s, (const __half*)h2s,
                                    (const __half*)Wqs, (const __half*)Wks,
                                    (const __half*)Wps,
                                    (__half*)Qs, (__half*)Ks, (__half*)Fv,
                                    bq, bk, (const float*)cb, (const float2*)tab);
    // 6: transpose V'
    {
        dim3 gt(DIM / 32, SEQ / 32, BATCH);
        transpose_hi_kernel<<<gt, dim3(32, 8)>>>((const __half*)Fv, (__half*)Vts);
    }
    // 7: scores E16[b] = scale * Q[b] K[b]^T  (f16 out; permutation cancels)
    dim3 ge(SEQ / BN, SEQ / BM, BATCH);
    gemm1<__half><<<ge, 256, SMEM_G>>>((const __half*)Qs, (const __half*)Ks,
                                       (__half*)E16, nullptr, DIM, SEQ, SEQ, SEQ,
                                       (long long)SEQ * SEQ, scale);
    // 8: softmax (f16 -> f16)
    softmax_h_kernel<<<BATCH * SEQ, 256>>>((const __half*)E16, (__half*)Es);
    // 9: out[b] = P[b] V'[b] + bo  (fp32 out, final)
    dim3 gpv(DIM / BN, SEQ / BM, BATCH);
    gemm1<float><<<gpv, 256, SMEM_G>>>((const __half*)Es, (const __half*)Vts,
                                       out, bo, SEQ, DIM, SEQ, DIM,
                                       (long long)SEQ * DIM, 1.0f);
}